// round 1
// baseline (speedup 1.0000x reference)
#include <cuda_runtime.h>
#include <math.h>

// ---------------------------------------------------------------------------
// MultiHeadAttention: 2 chained linear layers for each of Q,K,V, then 128
// independent (1024x1024, head_dim 16) attentions, weird permute, final linear.
// Round 0: fp32 SIMT baseline (correctness + profile), flash-style attention.
// ---------------------------------------------------------------------------

#define BM 128
#define BN 128
#define BK 16

static const int Mdim = 2048;  // B*S
static const int Ndim = 1024;  // F
static const int Kdim = 1024;  // F

// Scratch (device globals: runtime allocation is forbidden)
__device__ float g_q1[2048 * 1024];
__device__ float g_k1[2048 * 1024];
__device__ float g_v1[2048 * 1024];
__device__ float g_q2[2048 * 1024];
__device__ float g_k2[2048 * 1024];
__device__ float g_v2[2048 * 1024];
__device__ float g_op[2048 * 1024];

// ---------------------------------------------------------------------------
// NT GEMM with bias: C[m][n] = sum_k A[m][k] * W[n][k] + bias[n]
// Both operands K-contiguous. 128x128 CTA tile, BK=16, 256 threads, 8x8/thread
// (split 4+4 rows/cols for conflict-free LDS.128 frag loads), double-buffered.
// blockIdx.z in {0,1,2} selects one of three independent problems so the three
// Q/K/V projections of a layer run in one launch (better SM occupancy).
// ---------------------------------------------------------------------------
__global__ void __launch_bounds__(256, 2)
gemm_nt_bias3(const float* __restrict__ A0, const float* __restrict__ A1, const float* __restrict__ A2,
              const float* __restrict__ W0, const float* __restrict__ W1, const float* __restrict__ W2,
              const float* __restrict__ b0, const float* __restrict__ b1, const float* __restrict__ b2,
              float* __restrict__ C0, float* __restrict__ C1, float* __restrict__ C2)
{
    const int z = blockIdx.z;
    const float* __restrict__ A    = (z == 0) ? A0 : (z == 1) ? A1 : A2;
    const float* __restrict__ W    = (z == 0) ? W0 : (z == 1) ? W1 : W2;
    const float* __restrict__ bias = (z == 0) ? b0 : (z == 1) ? b1 : b2;
    float* __restrict__ C          = (z == 0) ? C0 : (z == 1) ? C1 : C2;

    __shared__ float As[2][BK][BM];
    __shared__ float Bs[2][BK][BN];

    const int tid = threadIdx.x;
    const int bm = blockIdx.y * BM;
    const int bn = blockIdx.x * BN;

    // Global-load assignment: 128 rows x 4 float4 per operand tile.
    const int lrow = tid >> 2;        // 0..63 (second row = +64)
    const int lk   = (tid & 3) * 4;   // 0,4,8,12

    const float* Ag = A + (size_t)(bm + lrow) * Kdim + lk;
    const float* Bg = W + (size_t)(bn + lrow) * Kdim + lk;

    // Compute-thread mapping: 16x16 thread grid, split 4+4 tiles.
    const int tx = tid & 15;
    const int ty = tid >> 4;
    const int cn0 = tx * 4, cn1 = 64 + tx * 4;
    const int cm0 = ty * 4, cm1 = 64 + ty * 4;

    float acc[8][8];
#pragma unroll
    for (int i = 0; i < 8; ++i)
#pragma unroll
        for (int j = 0; j < 8; ++j) acc[i][j] = 0.f;

    // Prologue: load k-tile 0 into buffer 0.
    {
        float4 pa0 = *(const float4*)(Ag);
        float4 pa1 = *(const float4*)(Ag + (size_t)64 * Kdim);
        float4 pb0 = *(const float4*)(Bg);
        float4 pb1 = *(const float4*)(Bg + (size_t)64 * Kdim);
        As[0][lk + 0][lrow] = pa0.x; As[0][lk + 1][lrow] = pa0.y;
        As[0][lk + 2][lrow] = pa0.z; As[0][lk + 3][lrow] = pa0.w;
        As[0][lk + 0][lrow + 64] = pa1.x; As[0][lk + 1][lrow + 64] = pa1.y;
        As[0][lk + 2][lrow + 64] = pa1.z; As[0][lk + 3][lrow + 64] = pa1.w;
        Bs[0][lk + 0][lrow] = pb0.x; Bs[0][lk + 1][lrow] = pb0.y;
        Bs[0][lk + 2][lrow] = pb0.z; Bs[0][lk + 3][lrow] = pb0.w;
        Bs[0][lk + 0][lrow + 64] = pb1.x; Bs[0][lk + 1][lrow + 64] = pb1.y;
        Bs[0][lk + 2][lrow + 64] = pb1.z; Bs[0][lk + 3][lrow + 64] = pb1.w;
    }
    __syncthreads();

    const int NT = Kdim / BK;  // 64
    int buf = 0;
#pragma unroll 1
    for (int kt = 0; kt < NT; ++kt) {
        float4 na0, na1, nb0, nb1;
        const bool has_next = (kt + 1 < NT);
        if (has_next) {
            const float* Ap = Ag + (kt + 1) * BK;
            const float* Bp = Bg + (kt + 1) * BK;
            na0 = *(const float4*)(Ap);
            na1 = *(const float4*)(Ap + (size_t)64 * Kdim);
            nb0 = *(const float4*)(Bp);
            nb1 = *(const float4*)(Bp + (size_t)64 * Kdim);
        }

#pragma unroll
        for (int kk = 0; kk < BK; ++kk) {
            float a[8], b[8];
            *(float4*)(&a[0]) = *(const float4*)(&As[buf][kk][cm0]);
            *(float4*)(&a[4]) = *(const float4*)(&As[buf][kk][cm1]);
            *(float4*)(&b[0]) = *(const float4*)(&Bs[buf][kk][cn0]);
            *(float4*)(&b[4]) = *(const float4*)(&Bs[buf][kk][cn1]);
#pragma unroll
            for (int i = 0; i < 8; ++i)
#pragma unroll
                for (int j = 0; j < 8; ++j) acc[i][j] += a[i] * b[j];
        }

        if (has_next) {
            const int nb = buf ^ 1;
            As[nb][lk + 0][lrow] = na0.x; As[nb][lk + 1][lrow] = na0.y;
            As[nb][lk + 2][lrow] = na0.z; As[nb][lk + 3][lrow] = na0.w;
            As[nb][lk + 0][lrow + 64] = na1.x; As[nb][lk + 1][lrow + 64] = na1.y;
            As[nb][lk + 2][lrow + 64] = na1.z; As[nb][lk + 3][lrow + 64] = na1.w;
            Bs[nb][lk + 0][lrow] = nb0.x; Bs[nb][lk + 1][lrow] = nb0.y;
            Bs[nb][lk + 2][lrow] = nb0.z; Bs[nb][lk + 3][lrow] = nb0.w;
            Bs[nb][lk + 0][lrow + 64] = nb1.x; Bs[nb][lk + 1][lrow + 64] = nb1.y;
            Bs[nb][lk + 2][lrow + 64] = nb1.z; Bs[nb][lk + 3][lrow + 64] = nb1.w;
            __syncthreads();
            buf = nb;
        }
    }

    // Epilogue: add bias, store.
    float4 bb0 = *(const float4*)(bias + bn + cn0);
    float4 bb1 = *(const float4*)(bias + bn + cn1);
    const float bsc[8] = {bb0.x, bb0.y, bb0.z, bb0.w, bb1.x, bb1.y, bb1.z, bb1.w};
#pragma unroll
    for (int i = 0; i < 8; ++i) {
        const int row = bm + ((i < 4) ? (cm0 + i) : (cm1 + i - 4));
        float* Cp = C + (size_t)row * Ndim + bn;
        float4 o0 = make_float4(acc[i][0] + bsc[0], acc[i][1] + bsc[1],
                                acc[i][2] + bsc[2], acc[i][3] + bsc[3]);
        float4 o1 = make_float4(acc[i][4] + bsc[4], acc[i][5] + bsc[5],
                                acc[i][6] + bsc[6], acc[i][7] + bsc[7]);
        *(float4*)(Cp + cn0) = o0;
        *(float4*)(Cp + cn1) = o1;
    }
}

// ---------------------------------------------------------------------------
// Flash attention. One CTA per (chunk c, batch b): K_cb and V_cb (1024x16 fp32,
// 64KB each) live entirely in dynamic smem. 256 threads, each owns 4 q rows;
// online softmax in exp2 domain (scale 1/4 folded into log2 scale).
// Output written directly in the reference's permuted layout.
// ---------------------------------------------------------------------------
__device__ __forceinline__ float fast_exp2(float x) {
    float r;
    asm("ex2.approx.f32 %0, %1;" : "=f"(r) : "f"(x));
    return r;
}

__global__ void __launch_bounds__(256, 1)
attention_kernel(const float* __restrict__ Q, const float* __restrict__ K,
                 const float* __restrict__ V, float* __restrict__ Operm)
{
    extern __shared__ float sh[];
    float* Ks = sh;            // [1024][16]
    float* Vs = sh + 1024 * 16;

    const int c = blockIdx.x;  // 0..63
    const int b = blockIdx.y;  // 0..1
    const int tid = threadIdx.x;

    const float* Kb = K + (size_t)b * 1024 * 1024 + c * 16;
    const float* Vb = V + (size_t)b * 1024 * 1024 + c * 16;

    // Stage K and V (4096 float4 tasks each, 16 per thread).
    for (int t = tid; t < 4096; t += 256) {
        const int s = t >> 2, h4 = (t & 3) * 4;
        *(float4*)(Ks + s * 16 + h4) = *(const float4*)(Kb + (size_t)s * 1024 + h4);
        *(float4*)(Vs + s * 16 + h4) = *(const float4*)(Vb + (size_t)s * 1024 + h4);
    }
    __syncthreads();

    const float SCL = 0.25f * 1.4426950408889634f;  // (1/sqrt(16)) * log2(e)

    float q[4][16], acc[4][16], mx[4], l[4];
#pragma unroll
    for (int t = 0; t < 4; ++t) {
        const int r = tid + t * 256;
        const float* qp = Q + ((size_t)b * 1024 + r) * 1024 + c * 16;
#pragma unroll
        for (int h4 = 0; h4 < 4; ++h4)
            *(float4*)(&q[t][h4 * 4]) = *(const float4*)(qp + h4 * 4);
#pragma unroll
        for (int h = 0; h < 16; ++h) acc[t][h] = 0.f;
        mx[t] = -3.0e38f;
        l[t] = 0.f;
    }

#pragma unroll 1
    for (int j = 0; j < 1024; ++j) {
        float kj[16], vj[16];
#pragma unroll
        for (int h4 = 0; h4 < 4; ++h4) {
            *(float4*)(&kj[h4 * 4]) = *(const float4*)(&Ks[j * 16 + h4 * 4]);
            *(float4*)(&vj[h4 * 4]) = *(const float4*)(&Vs[j * 16 + h4 * 4]);
        }
#pragma unroll
        for (int t = 0; t < 4; ++t) {
            float d0 = 0.f, d1 = 0.f, d2 = 0.f, d3 = 0.f;
#pragma unroll
            for (int h = 0; h < 4; ++h) {
                d0 += q[t][h]      * kj[h];
                d1 += q[t][h + 4]  * kj[h + 4];
                d2 += q[t][h + 8]  * kj[h + 8];
                d3 += q[t][h + 12] * kj[h + 12];
            }
            const float z = ((d0 + d1) + (d2 + d3)) * SCL;
            if (z > mx[t]) {  // rare after warmup
                const float corr = fast_exp2(mx[t] - z);
                mx[t] = z;
                l[t] *= corr;
#pragma unroll
                for (int h = 0; h < 16; ++h) acc[t][h] *= corr;
            }
            const float p = fast_exp2(z - mx[t]);
            l[t] += p;
#pragma unroll
            for (int h = 0; h < 16; ++h) acc[t][h] += p * vj[h];
        }
    }

    // Epilogue: normalize + permuted store.
    // flat(c,b,s,h) viewed as (16,2,1024,64) then transpose(1,2,0,3):
    //   a=c>>2, e=c&3, tt=2e+b, b2=tt>>2, r2=tt&3,
    //   s2=r2*256+(s>>2), f=(a<<6)+((s&3)<<4)+h   (h contiguous -> float4 ok)
    const int a = c >> 2, e = c & 3;
    const int tt = 2 * e + b;
    const int b2 = tt >> 2, r2 = tt & 3;
#pragma unroll
    for (int t = 0; t < 4; ++t) {
        const int s = tid + t * 256;
        const float inv = 1.0f / l[t];
        const int s2 = (r2 << 8) | (s >> 2);
        const int f0 = (a << 6) | ((s & 3) << 4);
        float* op = Operm + ((size_t)b2 * 1024 + s2) * 1024 + f0;
#pragma unroll
        for (int h4 = 0; h4 < 4; ++h4) {
            float4 o = make_float4(acc[t][h4 * 4 + 0] * inv, acc[t][h4 * 4 + 1] * inv,
                                   acc[t][h4 * 4 + 2] * inv, acc[t][h4 * 4 + 3] * inv);
            *(float4*)(op + h4 * 4) = o;
        }
    }
}

// ---------------------------------------------------------------------------
extern "C" void kernel_launch(void* const* d_in, const int* in_sizes, int n_in,
                              void* d_out, int out_size)
{
    const float* x    = (const float*)d_in[0];
    const float* wq_w = (const float*)d_in[1];
    const float* wq_b = (const float*)d_in[2];
    const float* wk_w = (const float*)d_in[3];
    const float* wk_b = (const float*)d_in[4];
    const float* wv_w = (const float*)d_in[5];
    const float* wv_b = (const float*)d_in[6];
    const float* vq_w = (const float*)d_in[7];
    const float* vq_b = (const float*)d_in[8];
    const float* vk_w = (const float*)d_in[9];
    const float* vk_b = (const float*)d_in[10];
    const float* vv_w = (const float*)d_in[11];
    const float* vv_b = (const float*)d_in[12];
    const float* wo_w = (const float*)d_in[13];
    const float* wo_b = (const float*)d_in[14];
    float* out = (float*)d_out;

    float *q1, *k1, *v1, *q2, *k2, *v2, *op;
    cudaGetSymbolAddress((void**)&q1, g_q1);
    cudaGetSymbolAddress((void**)&k1, g_k1);
    cudaGetSymbolAddress((void**)&v1, g_v1);
    cudaGetSymbolAddress((void**)&q2, g_q2);
    cudaGetSymbolAddress((void**)&k2, g_k2);
    cudaGetSymbolAddress((void**)&v2, g_v2);
    cudaGetSymbolAddress((void**)&op, g_op);

    const dim3 blk(256);
    const dim3 g3(Ndim / BN, Mdim / BM, 3);  // (8,16,3)
    const dim3 g1(Ndim / BN, Mdim / BM, 1);

    // Layer 1: q1/k1/v1 = x @ {wq,wk,wv}^T + b
    gemm_nt_bias3<<<g3, blk>>>(x, x, x, wq_w, wk_w, wv_w, wq_b, wk_b, wv_b, q1, k1, v1);
    // Layer 2: q2/k2/v2 = q1/k1/v1 @ {vq,vk,vv}^T + b
    gemm_nt_bias3<<<g3, blk>>>(q1, k1, v1, vq_w, vk_w, vv_w, vq_b, vk_b, vv_b, q2, k2, v2);

    // Attention (128 CTAs), writes permuted o.
    const int smem = 2 * 1024 * 16 * (int)sizeof(float);  // 128KB
    cudaFuncSetAttribute(attention_kernel, cudaFuncAttributeMaxDynamicSharedMemorySize, smem);
    attention_kernel<<<dim3(64, 2), blk, smem>>>(q2, k2, v2, op);

    // Final projection: out = o_perm @ wo^T + wo_b
    gemm_nt_bias3<<<g1, blk>>>(op, op, op, wo_w, wo_w, wo_w, wo_b, wo_b, wo_b, out, out, out);
}

// round 3
// speedup vs baseline: 1.6812x; 1.6812x over previous
#include <cuda_runtime.h>
#include <cuda_bf16.h>
#include <cstdint>
#include <math.h>

// ===========================================================================
// Round 3: mma.sync bf16 (HMMA fallback; tcgen05 is 'a'-gated and unavailable
// through this toolchain's compute_103 PTX) split-precision GEMMs
// (C = Ahi*Bhi + Ahi*Blo + Alo*Bhi, fp32 accum) + f32x2 SIMT flash attention.
// ===========================================================================

__device__ __forceinline__ uint32_t smem_u32(const void* p) {
    uint32_t a;
    asm("{ .reg .u64 t; cvta.to.shared.u64 t, %1; cvt.u32.u64 %0, t; }" : "=r"(a) : "l"(p));
    return a;
}
__device__ __forceinline__ void lm4(uint32_t* r, uint32_t a) {
    asm volatile("ldmatrix.sync.aligned.m8n8.x4.shared.b16 {%0,%1,%2,%3}, [%4];"
        : "=r"(r[0]), "=r"(r[1]), "=r"(r[2]), "=r"(r[3]) : "r"(a));
}
__device__ __forceinline__ void mma_bf16(float* d, const uint32_t* a, uint32_t b0, uint32_t b1) {
    asm volatile("mma.sync.aligned.m16n8k16.row.col.f32.bf16.bf16.f32 "
        "{%0,%1,%2,%3}, {%4,%5,%6,%7}, {%8,%9}, {%0,%1,%2,%3};"
        : "+f"(d[0]), "+f"(d[1]), "+f"(d[2]), "+f"(d[3])
        : "r"(a[0]), "r"(a[1]), "r"(a[2]), "r"(a[3]), "r"(b0), "r"(b1));
}
__device__ __forceinline__ void cpasync16(uint32_t dst, const void* src) {
    asm volatile("cp.async.cg.shared.global [%0], [%1], 16;" :: "r"(dst), "l"(src));
}

// ---------------- packed f32x2 helpers -------------------------------------
typedef unsigned long long u64t;
__device__ __forceinline__ u64t pk2(float a, float b) {
    u64t r; asm("mov.b64 %0, {%1, %2};" : "=l"(r) : "f"(a), "f"(b)); return r;
}
__device__ __forceinline__ void upk2(float& a, float& b, u64t v) {
    asm("mov.b64 {%0, %1}, %2;" : "=f"(a), "=f"(b) : "l"(v));
}
__device__ __forceinline__ u64t ffma2(u64t a, u64t b, u64t c) {
    u64t d; asm("fma.rn.f32x2 %0, %1, %2, %3;" : "=l"(d) : "l"(a), "l"(b), "l"(c)); return d;
}
__device__ __forceinline__ u64t fmul2(u64t a, u64t b) {
    u64t d; asm("mul.rn.f32x2 %0, %1, %2;" : "=l"(d) : "l"(a), "l"(b)); return d;
}
__device__ __forceinline__ float fast_exp2(float x) {
    float r; asm("ex2.approx.f32 %0, %1;" : "=f"(r) : "f"(x)); return r;
}

// ---------------- scratch (device globals) ---------------------------------
__device__ __nv_bfloat16 g_xhi[2097152], g_xlo[2097152];
__device__ __nv_bfloat16 g_whi[7340032], g_wlo[7340032];     // 7 x 1M weights
__device__ __nv_bfloat16 g_q1hi[2097152], g_q1lo[2097152];
__device__ __nv_bfloat16 g_k1hi[2097152], g_k1lo[2097152];
__device__ __nv_bfloat16 g_v1hi[2097152], g_v1lo[2097152];
__device__ float g_q2[2097152], g_k2[2097152], g_v2[2097152];
__device__ __nv_bfloat16 g_ophi[2097152], g_oplo[2097152];

// ---------------- split fp32 -> bf16 hi/lo ---------------------------------
struct SplitArgs {
    const float* src[8];
    __nv_bfloat16* hi[8];
    __nv_bfloat16* lo[8];
    int n[8];
};

__global__ void __launch_bounds__(256) split8(SplitArgs a) {
    const int z = blockIdx.z;
    const int i = (blockIdx.x * 256 + threadIdx.x) * 4;
    if (i >= a.n[z]) return;
    const float4 v = *(const float4*)(a.src[z] + i);
    __nv_bfloat16 h0 = __float2bfloat16(v.x), h1 = __float2bfloat16(v.y);
    __nv_bfloat16 h2 = __float2bfloat16(v.z), h3 = __float2bfloat16(v.w);
    __nv_bfloat16 l0 = __float2bfloat16(v.x - __bfloat162float(h0));
    __nv_bfloat16 l1 = __float2bfloat16(v.y - __bfloat162float(h1));
    __nv_bfloat16 l2 = __float2bfloat16(v.z - __bfloat162float(h2));
    __nv_bfloat16 l3 = __float2bfloat16(v.w - __bfloat162float(h3));
    __nv_bfloat162 H0; H0.x = h0; H0.y = h1;
    __nv_bfloat162 H1; H1.x = h2; H1.y = h3;
    __nv_bfloat162 L0; L0.x = l0; L0.y = l1;
    __nv_bfloat162 L1; L1.x = l2; L1.y = l3;
    *(__nv_bfloat162*)(a.hi[z] + i) = H0;
    *(__nv_bfloat162*)(a.hi[z] + i + 2) = H1;
    *(__nv_bfloat162*)(a.lo[z] + i) = L0;
    *(__nv_bfloat162*)(a.lo[z] + i + 2) = L1;
}

// ---------------- mma.sync GEMM --------------------------------------------
// C[m][n] = sum_k A[m][k]*B[n][k] + bias[n]. A: 2048x1024, B: 1024x1024, both
// bf16 hi/lo. CTA 128x128, BK=32, 8 warps (4M x 2N -> 32x64/warp), cp.async
// double buffer, XOR-swizzled 64B rows for conflict-free ldmatrix.
// mode 0: write Chi/Clo (bf16 split). mode 1: write Cf (fp32).
struct GemmArgs {
    const __nv_bfloat16 *Ahi, *Alo, *Bhi, *Blo;
    const float* bias;
    float* Cf;
    __nv_bfloat16 *Chi, *Clo;
};

// swizzled byte offset within a 128x32 bf16 tile (64B rows, 16B atoms)
__device__ __forceinline__ uint32_t swz(int r, int s) {
    return (uint32_t)(r * 64 + ((s ^ ((r >> 1) & 3)) << 4));
}

__global__ void __launch_bounds__(256, 1)
gemm_mma(GemmArgs g0, GemmArgs g1, GemmArgs g2, int mode)
{
    const GemmArgs ga = (blockIdx.z == 0) ? g0 : (blockIdx.z == 1) ? g1 : g2;
    extern __shared__ char smem_raw[];
    const uint32_t sb = (smem_u32(smem_raw) + 1023u) & ~1023u;

    const int tid = threadIdx.x;
    const int lane = tid & 31;
    const int wid = tid >> 5;
    const int wm = wid & 3;      // 4 M-warps
    const int wn = wid >> 2;     // 2 N-warps
    const int bm = blockIdx.y * 128;
    const int bn = blockIdx.x * 128;

    // Tiles: Ahi @0, Alo @8192, Bhi @16384, Blo @24576; stage stride 32768.
    // cp.async assignment: 2048 16B atoms/chunk, 8 per thread (fixed).
    const __nv_bfloat16* gp[8];
    uint32_t dst[8];
#pragma unroll
    for (int i = 0; i < 8; ++i) {
        const int u = tid + i * 256;
        const int t = u >> 9;            // 0=Ahi 1=Alo 2=Bhi 3=Blo
        const int r = (u >> 2) & 127;
        const int s = u & 3;
        const __nv_bfloat16* base = (t == 0) ? ga.Ahi : (t == 1) ? ga.Alo : (t == 2) ? ga.Bhi : ga.Blo;
        const int grow = ((t < 2) ? bm : bn) + r;
        gp[i] = base + (size_t)grow * 1024 + s * 8;
        dst[i] = sb + t * 8192 + swz(r, s);
    }

    // ldmatrix base addresses (stage 0, hi tiles, ks=0); ks=1 -> ^32, lo -> +8192.
    uint32_t lmA[2], lmB[4];
    {
        const int rA = wm * 32 + ((lane >> 3) & 1) * 8 + (lane & 7);
        const int sA = lane >> 4;
#pragma unroll
        for (int mt = 0; mt < 2; ++mt)
            lmA[mt] = sb + swz(rA + mt * 16, sA);
        const int rB = wn * 64 + (lane >> 4) * 8 + (lane & 7);
        const int sB = (lane >> 3) & 1;
#pragma unroll
        for (int ng = 0; ng < 4; ++ng)
            lmB[ng] = sb + 16384 + swz(rB + ng * 16, sB);
    }

    float acc[2][4][2][4];
#pragma unroll
    for (int mt = 0; mt < 2; ++mt)
#pragma unroll
        for (int ng = 0; ng < 4; ++ng)
#pragma unroll
            for (int h = 0; h < 2; ++h)
#pragma unroll
                for (int j = 0; j < 4; ++j) acc[mt][ng][h][j] = 0.f;

    // Prologue: chunk 0 -> stage 0.
#pragma unroll
    for (int i = 0; i < 8; ++i) cpasync16(dst[i], gp[i]);
    asm volatile("cp.async.commit_group;" ::: "memory");

#pragma unroll 1
    for (int ch = 0; ch < 32; ++ch) {
        const uint32_t so = (uint32_t)((ch & 1) * 32768);
        if (ch < 31) {
            const uint32_t sn = (uint32_t)(((ch + 1) & 1) * 32768);
#pragma unroll
            for (int i = 0; i < 8; ++i) cpasync16(dst[i] + sn, gp[i] + (ch + 1) * 32);
            asm volatile("cp.async.commit_group;" ::: "memory");
            asm volatile("cp.async.wait_group 1;" ::: "memory");
        } else {
            asm volatile("cp.async.wait_group 0;" ::: "memory");
        }
        __syncthreads();

#pragma unroll
        for (int ks = 0; ks < 2; ++ks) {
            const uint32_t kx = (uint32_t)(ks << 5);
            uint32_t ah[2][4], al[2][4], bh[4][4], bl[4][4];
#pragma unroll
            for (int mt = 0; mt < 2; ++mt) {
                lm4(ah[mt], (lmA[mt] + so) ^ kx);
                lm4(al[mt], (lmA[mt] + 8192 + so) ^ kx);
            }
#pragma unroll
            for (int ng = 0; ng < 4; ++ng) {
                lm4(bh[ng], (lmB[ng] + so) ^ kx);
                lm4(bl[ng], (lmB[ng] + 8192 + so) ^ kx);
            }
#pragma unroll
            for (int mt = 0; mt < 2; ++mt)
#pragma unroll
                for (int ng = 0; ng < 4; ++ng)
#pragma unroll
                    for (int h = 0; h < 2; ++h) {
                        float* d = acc[mt][ng][h];
                        mma_bf16(d, ah[mt], bh[ng][2 * h], bh[ng][2 * h + 1]);  // hi*hi
                        mma_bf16(d, ah[mt], bl[ng][2 * h], bl[ng][2 * h + 1]);  // hi*lo
                        mma_bf16(d, al[mt], bh[ng][2 * h], bh[ng][2 * h + 1]);  // lo*hi
                    }
        }
        __syncthreads();
    }

    // Epilogue. Thread l of mma tile: rows (l>>2), (l>>2)+8; cols 2(l&3)+{0,1}.
#pragma unroll
    for (int mt = 0; mt < 2; ++mt) {
        const int r0 = bm + wm * 32 + mt * 16 + (lane >> 2);
#pragma unroll
        for (int ng = 0; ng < 4; ++ng)
#pragma unroll
            for (int h = 0; h < 2; ++h) {
                const int col = bn + wn * 64 + ng * 16 + h * 8 + 2 * (lane & 3);
                const float2 b2 = *(const float2*)(ga.bias + col);
                const float* a4 = acc[mt][ng][h];
                const float v00 = a4[0] + b2.x, v01 = a4[1] + b2.y;
                const float v10 = a4[2] + b2.x, v11 = a4[3] + b2.y;
                if (mode == 1) {
                    float2 p0; p0.x = v00; p0.y = v01;
                    float2 p1; p1.x = v10; p1.y = v11;
                    *(float2*)(ga.Cf + (size_t)r0 * 1024 + col) = p0;
                    *(float2*)(ga.Cf + (size_t)(r0 + 8) * 1024 + col) = p1;
                } else {
                    __nv_bfloat162 H0, L0, H1, L1;
                    H0.x = __float2bfloat16(v00); H0.y = __float2bfloat16(v01);
                    L0.x = __float2bfloat16(v00 - __bfloat162float(H0.x));
                    L0.y = __float2bfloat16(v01 - __bfloat162float(H0.y));
                    H1.x = __float2bfloat16(v10); H1.y = __float2bfloat16(v11);
                    L1.x = __float2bfloat16(v10 - __bfloat162float(H1.x));
                    L1.y = __float2bfloat16(v11 - __bfloat162float(H1.y));
                    *(__nv_bfloat162*)(ga.Chi + (size_t)r0 * 1024 + col) = H0;
                    *(__nv_bfloat162*)(ga.Clo + (size_t)r0 * 1024 + col) = L0;
                    *(__nv_bfloat162*)(ga.Chi + (size_t)(r0 + 8) * 1024 + col) = H1;
                    *(__nv_bfloat162*)(ga.Clo + (size_t)(r0 + 8) * 1024 + col) = L1;
                }
            }
    }
}

// ---------------- flash attention (SIMT, packed f32x2) ----------------------
__global__ void __launch_bounds__(256, 1)
attention_kernel(const float* __restrict__ Q, const float* __restrict__ K,
                 const float* __restrict__ V,
                 __nv_bfloat16* __restrict__ Ohi, __nv_bfloat16* __restrict__ Olo)
{
    extern __shared__ float sh[];
    float* Ks = sh;
    float* Vs = sh + 1024 * 16;

    const int c = blockIdx.x;
    const int b = blockIdx.y;
    const int tid = threadIdx.x;

    const float* Kb = K + (size_t)b * 1048576 + c * 16;
    const float* Vb = V + (size_t)b * 1048576 + c * 16;
    for (int t = tid; t < 4096; t += 256) {
        const int s = t >> 2, h4 = (t & 3) * 4;
        *(float4*)(Ks + s * 16 + h4) = *(const float4*)(Kb + (size_t)s * 1024 + h4);
        *(float4*)(Vs + s * 16 + h4) = *(const float4*)(Vb + (size_t)s * 1024 + h4);
    }
    __syncthreads();

    const float SCL = 0.25f * 1.4426950408889634f;

    u64t q2[4][8], acc[4][8];
    float mx[4], l[4];
#pragma unroll
    for (int t = 0; t < 4; ++t) {
        const int r = tid + t * 256;
        const float* qp = Q + ((size_t)b * 1024 + r) * 1024 + c * 16;
#pragma unroll
        for (int h4 = 0; h4 < 4; ++h4) {
            const float4 v = *(const float4*)(qp + h4 * 4);
            q2[t][h4 * 2 + 0] = pk2(v.x, v.y);
            q2[t][h4 * 2 + 1] = pk2(v.z, v.w);
        }
#pragma unroll
        for (int i = 0; i < 8; ++i) acc[t][i] = 0ull;
        mx[t] = -3.0e38f;
        l[t] = 0.f;
    }

#pragma unroll 1
    for (int j = 0; j < 1024; ++j) {
        u64t kj[8], vj[8];
#pragma unroll
        for (int h4 = 0; h4 < 4; ++h4) {
            const float4 kv = *(const float4*)(&Ks[j * 16 + h4 * 4]);
            const float4 vv = *(const float4*)(&Vs[j * 16 + h4 * 4]);
            kj[h4 * 2 + 0] = pk2(kv.x, kv.y);
            kj[h4 * 2 + 1] = pk2(kv.z, kv.w);
            vj[h4 * 2 + 0] = pk2(vv.x, vv.y);
            vj[h4 * 2 + 1] = pk2(vv.z, vv.w);
        }
#pragma unroll
        for (int t = 0; t < 4; ++t) {
            u64t d2 = 0ull;
#pragma unroll
            for (int i = 0; i < 8; ++i) d2 = ffma2(q2[t][i], kj[i], d2);
            float dx, dy;
            upk2(dx, dy, d2);
            const float z = (dx + dy) * SCL;
            if (z > mx[t]) {  // rare after warmup
                const float corr = fast_exp2(mx[t] - z);
                mx[t] = z;
                l[t] *= corr;
                const u64t cc = pk2(corr, corr);
#pragma unroll
                for (int i = 0; i < 8; ++i) acc[t][i] = fmul2(acc[t][i], cc);
            }
            const float p = fast_exp2(z - mx[t]);
            l[t] += p;
            const u64t pp = pk2(p, p);
#pragma unroll
            for (int i = 0; i < 8; ++i) acc[t][i] = ffma2(pp, vj[i], acc[t][i]);
        }
    }

    // permuted epilogue -> bf16 hi/lo
    const int a = c >> 2, e = c & 3;
    const int tt = 2 * e + b;
    const int b2 = tt >> 2, r2 = tt & 3;
#pragma unroll
    for (int t = 0; t < 4; ++t) {
        const int s = tid + t * 256;
        const float inv = 1.0f / l[t];
        const int s2 = (r2 << 8) | (s >> 2);
        const int f0 = (a << 6) | ((s & 3) << 4);
        const size_t off = ((size_t)b2 * 1024 + s2) * 1024 + f0;
        __nv_bfloat16* hp = Ohi + off;
        __nv_bfloat16* lp = Olo + off;
#pragma unroll
        for (int i = 0; i < 8; ++i) {
            float a0, a1;
            upk2(a0, a1, acc[t][i]);
            a0 *= inv; a1 *= inv;
            __nv_bfloat162 H, L;
            H.x = __float2bfloat16(a0);
            H.y = __float2bfloat16(a1);
            L.x = __float2bfloat16(a0 - __bfloat162float(H.x));
            L.y = __float2bfloat16(a1 - __bfloat162float(H.y));
            *(__nv_bfloat162*)(hp + i * 2) = H;
            *(__nv_bfloat162*)(lp + i * 2) = L;
        }
    }
}

// ---------------------------------------------------------------------------
extern "C" void kernel_launch(void* const* d_in, const int* in_sizes, int n_in,
                              void* d_out, int out_size)
{
    const float* x    = (const float*)d_in[0];
    const float* wq_w = (const float*)d_in[1];
    const float* wq_b = (const float*)d_in[2];
    const float* wk_w = (const float*)d_in[3];
    const float* wk_b = (const float*)d_in[4];
    const float* wv_w = (const float*)d_in[5];
    const float* wv_b = (const float*)d_in[6];
    const float* vq_w = (const float*)d_in[7];
    const float* vq_b = (const float*)d_in[8];
    const float* vk_w = (const float*)d_in[9];
    const float* vk_b = (const float*)d_in[10];
    const float* vv_w = (const float*)d_in[11];
    const float* vv_b = (const float*)d_in[12];
    const float* wo_w = (const float*)d_in[13];
    const float* wo_b = (const float*)d_in[14];
    float* out = (float*)d_out;

    __nv_bfloat16 *xhi, *xlo, *whi, *wlo;
    __nv_bfloat16 *q1hi, *q1lo, *k1hi, *k1lo, *v1hi, *v1lo, *ophi, *oplo;
    float *q2, *k2, *v2;
    cudaGetSymbolAddress((void**)&xhi, g_xhi);   cudaGetSymbolAddress((void**)&xlo, g_xlo);
    cudaGetSymbolAddress((void**)&whi, g_whi);   cudaGetSymbolAddress((void**)&wlo, g_wlo);
    cudaGetSymbolAddress((void**)&q1hi, g_q1hi); cudaGetSymbolAddress((void**)&q1lo, g_q1lo);
    cudaGetSymbolAddress((void**)&k1hi, g_k1hi); cudaGetSymbolAddress((void**)&k1lo, g_k1lo);
    cudaGetSymbolAddress((void**)&v1hi, g_v1hi); cudaGetSymbolAddress((void**)&v1lo, g_v1lo);
    cudaGetSymbolAddress((void**)&q2, g_q2);     cudaGetSymbolAddress((void**)&k2, g_k2);
    cudaGetSymbolAddress((void**)&v2, g_v2);
    cudaGetSymbolAddress((void**)&ophi, g_ophi); cudaGetSymbolAddress((void**)&oplo, g_oplo);

    // ---- split x + 7 weights into bf16 hi/lo ----
    SplitArgs sa;
    const float* srcs[8] = {x, wq_w, wk_w, wv_w, vq_w, vk_w, vv_w, wo_w};
    for (int i = 0; i < 8; ++i) {
        sa.src[i] = srcs[i];
        if (i == 0) { sa.hi[i] = xhi; sa.lo[i] = xlo; sa.n[i] = 2097152; }
        else { sa.hi[i] = whi + (size_t)(i - 1) * 1048576; sa.lo[i] = wlo + (size_t)(i - 1) * 1048576; sa.n[i] = 1048576; }
    }
    split8<<<dim3(2048, 1, 8), 256>>>(sa);

    const int gemm_smem = 66560;  // 2 stages x 32KB + alignment pad
    cudaFuncSetAttribute(gemm_mma, cudaFuncAttributeMaxDynamicSharedMemorySize, gemm_smem);

    GemmArgs a0{}, a1{}, a2{};
    // Layer 1: {q1,k1,v1} = x @ {wq,wk,wv}^T + b   (split bf16 output)
    a0 = {xhi, xlo, whi + 0 * 1048576, wlo + 0 * 1048576, wq_b, nullptr, q1hi, q1lo};
    a1 = {xhi, xlo, whi + 1 * 1048576, wlo + 1 * 1048576, wk_b, nullptr, k1hi, k1lo};
    a2 = {xhi, xlo, whi + 2 * 1048576, wlo + 2 * 1048576, wv_b, nullptr, v1hi, v1lo};
    gemm_mma<<<dim3(8, 16, 3), 256, gemm_smem>>>(a0, a1, a2, 0);

    // Layer 2: {q2,k2,v2} = {q1,k1,v1} @ {vq,vk,vv}^T + b   (fp32 output)
    a0 = {q1hi, q1lo, whi + 3 * 1048576, wlo + 3 * 1048576, vq_b, q2, nullptr, nullptr};
    a1 = {k1hi, k1lo, whi + 4 * 1048576, wlo + 4 * 1048576, vk_b, k2, nullptr, nullptr};
    a2 = {v1hi, v1lo, whi + 5 * 1048576, wlo + 5 * 1048576, vv_b, v2, nullptr, nullptr};
    gemm_mma<<<dim3(8, 16, 3), 256, gemm_smem>>>(a0, a1, a2, 1);

    // Attention: writes permuted o, split bf16
    const int attn_smem = 2 * 1024 * 16 * (int)sizeof(float);
    cudaFuncSetAttribute(attention_kernel, cudaFuncAttributeMaxDynamicSharedMemorySize, attn_smem);
    attention_kernel<<<dim3(64, 2), 256, attn_smem>>>(q2, k2, v2, ophi, oplo);

    // Final: out = o @ wo^T + b
    a0 = {ophi, oplo, whi + 6 * 1048576, wlo + 6 * 1048576, wo_b, out, nullptr, nullptr};
    gemm_mma<<<dim3(8, 16, 1), 256, gemm_smem>>>(a0, a0, a0, 1);
}

// round 4
// speedup vs baseline: 2.5125x; 1.4945x over previous
#include <cuda_runtime.h>
#include <cuda_bf16.h>
#include <cstdint>
#include <math.h>

// ===========================================================================
// Round 4: mma.sync everywhere. Split-precision bf16 GEMMs (3-stage cp.async)
// + MMA flash attention (3-term QK^T, bf16 P, 2-term P*V), fused permute.
// ===========================================================================

__device__ __forceinline__ uint32_t smem_u32(const void* p) {
    uint32_t a;
    asm("{ .reg .u64 t; cvta.to.shared.u64 t, %1; cvt.u32.u64 %0, t; }" : "=r"(a) : "l"(p));
    return a;
}
__device__ __forceinline__ void lm4(uint32_t* r, uint32_t a) {
    asm volatile("ldmatrix.sync.aligned.m8n8.x4.shared.b16 {%0,%1,%2,%3}, [%4];"
        : "=r"(r[0]), "=r"(r[1]), "=r"(r[2]), "=r"(r[3]) : "r"(a));
}
__device__ __forceinline__ void lm4t(uint32_t* r, uint32_t a) {
    asm volatile("ldmatrix.sync.aligned.m8n8.x4.trans.shared.b16 {%0,%1,%2,%3}, [%4];"
        : "=r"(r[0]), "=r"(r[1]), "=r"(r[2]), "=r"(r[3]) : "r"(a));
}
__device__ __forceinline__ void mma_bf16(float* d, const uint32_t* a, uint32_t b0, uint32_t b1) {
    asm volatile("mma.sync.aligned.m16n8k16.row.col.f32.bf16.bf16.f32 "
        "{%0,%1,%2,%3}, {%4,%5,%6,%7}, {%8,%9}, {%0,%1,%2,%3};"
        : "+f"(d[0]), "+f"(d[1]), "+f"(d[2]), "+f"(d[3])
        : "r"(a[0]), "r"(a[1]), "r"(a[2]), "r"(a[3]), "r"(b0), "r"(b1));
}
__device__ __forceinline__ void cpasync16(uint32_t dst, const void* src) {
    asm volatile("cp.async.cg.shared.global [%0], [%1], 16;" :: "r"(dst), "l"(src));
}
__device__ __forceinline__ float fast_exp2(float x) {
    float r; asm("ex2.approx.f32 %0, %1;" : "=f"(r) : "f"(x)); return r;
}
// pack two f32 -> bf16x2 with lo = first arg
__device__ __forceinline__ uint32_t packbf(float lo, float hi) {
    uint32_t d;
    asm("cvt.rn.bf16x2.f32 %0, %1, %2;" : "=r"(d) : "f"(hi), "f"(lo));
    return d;
}

// ---------------- scratch (device globals) ---------------------------------
__device__ __nv_bfloat16 g_xhi[2097152], g_xlo[2097152];
__device__ __nv_bfloat16 g_whi[7340032], g_wlo[7340032];     // 7 x 1M weights
__device__ __nv_bfloat16 g_q1hi[2097152], g_q1lo[2097152];
__device__ __nv_bfloat16 g_k1hi[2097152], g_k1lo[2097152];
__device__ __nv_bfloat16 g_v1hi[2097152], g_v1lo[2097152];
__device__ __nv_bfloat16 g_q2hi[2097152], g_q2lo[2097152];
__device__ __nv_bfloat16 g_k2hi[2097152], g_k2lo[2097152];
__device__ __nv_bfloat16 g_v2hi[2097152], g_v2lo[2097152];
__device__ __nv_bfloat16 g_ophi[2097152], g_oplo[2097152];

// ---------------- split fp32 -> bf16 hi/lo ---------------------------------
struct SplitArgs {
    const float* src[8];
    __nv_bfloat16* hi[8];
    __nv_bfloat16* lo[8];
    int n[8];
};

__global__ void __launch_bounds__(256) split8(SplitArgs a) {
    const int z = blockIdx.z;
    const int i = (blockIdx.x * 256 + threadIdx.x) * 4;
    if (i >= a.n[z]) return;
    const float4 v = *(const float4*)(a.src[z] + i);
    __nv_bfloat16 h0 = __float2bfloat16(v.x), h1 = __float2bfloat16(v.y);
    __nv_bfloat16 h2 = __float2bfloat16(v.z), h3 = __float2bfloat16(v.w);
    __nv_bfloat16 l0 = __float2bfloat16(v.x - __bfloat162float(h0));
    __nv_bfloat16 l1 = __float2bfloat16(v.y - __bfloat162float(h1));
    __nv_bfloat16 l2 = __float2bfloat16(v.z - __bfloat162float(h2));
    __nv_bfloat16 l3 = __float2bfloat16(v.w - __bfloat162float(h3));
    __nv_bfloat162 H0; H0.x = h0; H0.y = h1;
    __nv_bfloat162 H1; H1.x = h2; H1.y = h3;
    __nv_bfloat162 L0; L0.x = l0; L0.y = l1;
    __nv_bfloat162 L1; L1.x = l2; L1.y = l3;
    *(__nv_bfloat162*)(a.hi[z] + i) = H0;
    *(__nv_bfloat162*)(a.hi[z] + i + 2) = H1;
    *(__nv_bfloat162*)(a.lo[z] + i) = L0;
    *(__nv_bfloat162*)(a.lo[z] + i + 2) = L1;
}

// ---------------- mma.sync GEMM (3-stage pipeline) --------------------------
struct GemmArgs {
    const __nv_bfloat16 *Ahi, *Alo, *Bhi, *Blo;
    const float* bias;
    float* Cf;
    __nv_bfloat16 *Chi, *Clo;
};

// swizzled byte offset within a 128x32 bf16 tile (64B rows, 16B atoms)
__device__ __forceinline__ uint32_t swz(int r, int s) {
    return (uint32_t)(r * 64 + ((s ^ ((r >> 1) & 3)) << 4));
}

__global__ void __launch_bounds__(256, 1)
gemm_mma(GemmArgs g0, GemmArgs g1, GemmArgs g2, int mode)
{
    const GemmArgs ga = (blockIdx.z == 0) ? g0 : (blockIdx.z == 1) ? g1 : g2;
    extern __shared__ char smem_raw[];
    const uint32_t sb = (smem_u32(smem_raw) + 1023u) & ~1023u;

    const int tid = threadIdx.x;
    const int lane = tid & 31;
    const int wid = tid >> 5;
    const int wm = wid & 3;
    const int wn = wid >> 2;
    const int bm = blockIdx.y * 128;
    const int bn = blockIdx.x * 128;

    // Tiles within a stage: Ahi @0, Alo @8192, Bhi @16384, Blo @24576; stage stride 32768.
    const __nv_bfloat16* gp[8];
    uint32_t dst[8];
#pragma unroll
    for (int i = 0; i < 8; ++i) {
        const int u = tid + i * 256;
        const int t = u >> 9;
        const int r = (u >> 2) & 127;
        const int s = u & 3;
        const __nv_bfloat16* base = (t == 0) ? ga.Ahi : (t == 1) ? ga.Alo : (t == 2) ? ga.Bhi : ga.Blo;
        const int grow = ((t < 2) ? bm : bn) + r;
        gp[i] = base + (size_t)grow * 1024 + s * 8;
        dst[i] = sb + t * 8192 + swz(r, s);
    }

    uint32_t lmA[2], lmB[4];
    {
        const int rA = wm * 32 + ((lane >> 3) & 1) * 8 + (lane & 7);
        const int sA = lane >> 4;
#pragma unroll
        for (int mt = 0; mt < 2; ++mt) lmA[mt] = sb + swz(rA + mt * 16, sA);
        const int rB = wn * 64 + (lane >> 4) * 8 + (lane & 7);
        const int sB = (lane >> 3) & 1;
#pragma unroll
        for (int ng = 0; ng < 4; ++ng) lmB[ng] = sb + 16384 + swz(rB + ng * 16, sB);
    }

    float acc[2][4][2][4];
#pragma unroll
    for (int mt = 0; mt < 2; ++mt)
#pragma unroll
        for (int ng = 0; ng < 4; ++ng)
#pragma unroll
            for (int h = 0; h < 2; ++h)
#pragma unroll
                for (int j = 0; j < 4; ++j) acc[mt][ng][h][j] = 0.f;

    // Prologue: chunks 0,1 -> stages 0,1.
#pragma unroll
    for (int i = 0; i < 8; ++i) cpasync16(dst[i], gp[i]);
    asm volatile("cp.async.commit_group;" ::: "memory");
#pragma unroll
    for (int i = 0; i < 8; ++i) cpasync16(dst[i] + 32768, gp[i] + 32);
    asm volatile("cp.async.commit_group;" ::: "memory");

#pragma unroll 1
    for (int ch = 0; ch < 32; ++ch) {
        if (ch < 31) { asm volatile("cp.async.wait_group 1;" ::: "memory"); }
        else         { asm volatile("cp.async.wait_group 0;" ::: "memory"); }
        __syncthreads();   // chunk ch visible; all warps done computing ch-1

        if (ch + 2 < 32) {
            const uint32_t sn = (uint32_t)(((ch + 2) % 3) * 32768);
#pragma unroll
            for (int i = 0; i < 8; ++i) cpasync16(dst[i] + sn, gp[i] + (ch + 2) * 32);
            asm volatile("cp.async.commit_group;" ::: "memory");
        }

        const uint32_t so = (uint32_t)((ch % 3) * 32768);
#pragma unroll
        for (int ks = 0; ks < 2; ++ks) {
            const uint32_t kx = (uint32_t)(ks << 5);
            uint32_t ah[2][4], al[2][4], bh[4][4], bl[4][4];
#pragma unroll
            for (int mt = 0; mt < 2; ++mt) {
                lm4(ah[mt], (lmA[mt] + so) ^ kx);
                lm4(al[mt], (lmA[mt] + 8192 + so) ^ kx);
            }
#pragma unroll
            for (int ng = 0; ng < 4; ++ng) {
                lm4(bh[ng], (lmB[ng] + so) ^ kx);
                lm4(bl[ng], (lmB[ng] + 8192 + so) ^ kx);
            }
#pragma unroll
            for (int mt = 0; mt < 2; ++mt)
#pragma unroll
                for (int ng = 0; ng < 4; ++ng)
#pragma unroll
                    for (int h = 0; h < 2; ++h) {
                        float* d = acc[mt][ng][h];
                        mma_bf16(d, ah[mt], bh[ng][2 * h], bh[ng][2 * h + 1]);
                        mma_bf16(d, al[mt], bh[ng][2 * h], bh[ng][2 * h + 1]);
                        mma_bf16(d, ah[mt], bl[ng][2 * h], bl[ng][2 * h + 1]);
                    }
        }
    }

    // Epilogue
#pragma unroll
    for (int mt = 0; mt < 2; ++mt) {
        const int r0 = bm + wm * 32 + mt * 16 + (lane >> 2);
#pragma unroll
        for (int ng = 0; ng < 4; ++ng)
#pragma unroll
            for (int h = 0; h < 2; ++h) {
                const int col = bn + wn * 64 + ng * 16 + h * 8 + 2 * (lane & 3);
                const float2 b2 = *(const float2*)(ga.bias + col);
                const float* a4 = acc[mt][ng][h];
                const float v00 = a4[0] + b2.x, v01 = a4[1] + b2.y;
                const float v10 = a4[2] + b2.x, v11 = a4[3] + b2.y;
                if (mode == 1) {
                    float2 p0; p0.x = v00; p0.y = v01;
                    float2 p1; p1.x = v10; p1.y = v11;
                    *(float2*)(ga.Cf + (size_t)r0 * 1024 + col) = p0;
                    *(float2*)(ga.Cf + (size_t)(r0 + 8) * 1024 + col) = p1;
                } else {
                    __nv_bfloat162 H0, L0, H1, L1;
                    H0.x = __float2bfloat16(v00); H0.y = __float2bfloat16(v01);
                    L0.x = __float2bfloat16(v00 - __bfloat162float(H0.x));
                    L0.y = __float2bfloat16(v01 - __bfloat162float(H0.y));
                    H1.x = __float2bfloat16(v10); H1.y = __float2bfloat16(v11);
                    L1.x = __float2bfloat16(v10 - __bfloat162float(H1.x));
                    L1.y = __float2bfloat16(v11 - __bfloat162float(H1.y));
                    *(__nv_bfloat162*)(ga.Chi + (size_t)r0 * 1024 + col) = H0;
                    *(__nv_bfloat162*)(ga.Clo + (size_t)r0 * 1024 + col) = L0;
                    *(__nv_bfloat162*)(ga.Chi + (size_t)(r0 + 8) * 1024 + col) = H1;
                    *(__nv_bfloat162*)(ga.Clo + (size_t)(r0 + 8) * 1024 + col) = L1;
                }
            }
    }
}

// ---------------- MMA flash attention ---------------------------------------
// Grid (qt=4, c=64, b=2). 8 warps x 32 q-rows (2 m16 tiles). K/V/Q bf16 hi/lo
// in smem, 32B rows with 16B-half swizzle (bit2 of row) -> conflict-free
// ldmatrix. Online softmax in C-frag layout; P bf16; V 2-term split.
// Output written bf16 hi/lo at the reference's permuted location.
#define AKH 0u
#define AKL 32768u
#define AVH 65536u
#define AVL 98304u
#define AQH 131072u
#define AQL 139264u

__global__ void __launch_bounds__(256, 1)
attention_mma(const __nv_bfloat16* __restrict__ qhi, const __nv_bfloat16* __restrict__ qlo,
              const __nv_bfloat16* __restrict__ khi, const __nv_bfloat16* __restrict__ klo,
              const __nv_bfloat16* __restrict__ vhi, const __nv_bfloat16* __restrict__ vlo,
              __nv_bfloat16* __restrict__ Ohi, __nv_bfloat16* __restrict__ Olo)
{
    extern __shared__ char smraw[];
    const uint32_t sb = smem_u32(smraw);

    const int qt = blockIdx.x;
    const int c  = blockIdx.y;
    const int b  = blockIdx.z;
    const int tid = threadIdx.x;
    const int lane = tid & 31;
    const int w = tid >> 5;

    // ---- stage K/V (1024x16) and Q (256x16) hi/lo via cp.async ----
#pragma unroll
    for (int i = 0; i < 32; ++i) {
        const int u = tid + i * 256;
        const int arr = u >> 11;
        const int rem = u & 2047;
        const int r = rem >> 1;
        const int half = rem & 1;
        const __nv_bfloat16* base = (arr == 0) ? khi : (arr == 1) ? klo : (arr == 2) ? vhi : vlo;
        const __nv_bfloat16* src = base + ((size_t)((b << 10) + r) << 10) + (c << 4) + (half << 3);
        const uint32_t dstp = sb + (uint32_t)(arr << 15) + (uint32_t)(r * 32 + ((half ^ ((r >> 2) & 1)) << 4));
        cpasync16(dstp, src);
    }
#pragma unroll
    for (int i = 0; i < 4; ++i) {
        const int u = tid + i * 256;
        const int arr = u >> 9;
        const int rem = u & 511;
        const int r = rem >> 1;
        const int half = rem & 1;
        const __nv_bfloat16* base = arr ? qlo : qhi;
        const __nv_bfloat16* src = base + ((size_t)((b << 10) + (qt << 8) + r) << 10) + (c << 4) + (half << 3);
        const uint32_t dstp = sb + AQH + (uint32_t)(arr << 13) + (uint32_t)(r * 32 + ((half ^ ((r >> 2) & 1)) << 4));
        cpasync16(dstp, src);
    }
    asm volatile("cp.async.commit_group;" ::: "memory");
    asm volatile("cp.async.wait_group 0;" ::: "memory");
    __syncthreads();

    // ---- Q fragments (2 m16 tiles per warp) ----
    const uint32_t qoff = (uint32_t)((lane & 15) * 32 + ((((lane >> 4) & 1) ^ ((lane >> 2) & 1)) << 4));
    uint32_t qh[2][4], ql[2][4];
#pragma unroll
    for (int mt = 0; mt < 2; ++mt) {
        const uint32_t rowb = (uint32_t)((w * 32 + mt * 16) * 32);
        lm4(qh[mt], sb + AQH + rowb + qoff);
        lm4(ql[mt], sb + AQL + rowb + qoff);
    }

    // per-lane ldmatrix offsets for K (B-frag) and V (trans B-frag)
    const uint32_t kloff = (uint32_t)(((lane & 7) + ((lane >> 4) << 3)) * 32 +
                                      ((((lane >> 3) & 1) ^ ((lane >> 2) & 1)) << 4));
    const uint32_t vloff = (uint32_t)(((lane & 7) + (((lane >> 3) & 1) << 3)) * 32 +
                                      ((((lane >> 4) & 1) ^ ((lane >> 2) & 1)) << 4));

    const float SCL = 0.25f * 1.4426950408889634f;

    float oac[2][2][4];
    float mx[2][2], lsum[2][2];
#pragma unroll
    for (int mt = 0; mt < 2; ++mt)
#pragma unroll
        for (int ht = 0; ht < 2; ++ht)
#pragma unroll
            for (int j = 0; j < 4; ++j) oac[mt][ht][j] = 0.f;
#pragma unroll
    for (int mt = 0; mt < 2; ++mt) { mx[mt][0] = mx[mt][1] = -1e30f; lsum[mt][0] = lsum[mt][1] = 0.f; }

#pragma unroll 1
    for (int kb = 0; kb < 16; ++kb) {
#pragma unroll
        for (int mt = 0; mt < 2; ++mt) {
            float sc[8][4];
#pragma unroll
            for (int j = 0; j < 8; ++j)
#pragma unroll
                for (int i = 0; i < 4; ++i) sc[j][i] = 0.f;

            // --- QK^T: 3-term split ---
#pragma unroll
            for (int nt = 0; nt < 4; ++nt) {
                const uint32_t s0 = (uint32_t)((kb * 64 + nt * 16) * 32);
                uint32_t kh4[4], kl4[4];
                lm4(kh4, sb + AKH + s0 + kloff);
                lm4(kl4, sb + AKL + s0 + kloff);
                mma_bf16(sc[2 * nt], qh[mt], kh4[0], kh4[1]);
                mma_bf16(sc[2 * nt], ql[mt], kh4[0], kh4[1]);
                mma_bf16(sc[2 * nt], qh[mt], kl4[0], kl4[1]);
                mma_bf16(sc[2 * nt + 1], qh[mt], kh4[2], kh4[3]);
                mma_bf16(sc[2 * nt + 1], ql[mt], kh4[2], kh4[3]);
                mma_bf16(sc[2 * nt + 1], qh[mt], kl4[2], kl4[3]);
            }

            // --- online softmax (rows: lo = lane>>2, hi = +8) ---
            float rlo = sc[0][0], rhi = sc[0][2];
#pragma unroll
            for (int j = 0; j < 8; ++j) {
                rlo = fmaxf(rlo, fmaxf(sc[j][0], sc[j][1]));
                rhi = fmaxf(rhi, fmaxf(sc[j][2], sc[j][3]));
            }
            rlo = fmaxf(rlo, __shfl_xor_sync(0xffffffffu, rlo, 1));
            rlo = fmaxf(rlo, __shfl_xor_sync(0xffffffffu, rlo, 2));
            rhi = fmaxf(rhi, __shfl_xor_sync(0xffffffffu, rhi, 1));
            rhi = fmaxf(rhi, __shfl_xor_sync(0xffffffffu, rhi, 2));

            const float mlo = fmaxf(mx[mt][0], rlo);
            const float mhi = fmaxf(mx[mt][1], rhi);
            const float corrlo = fast_exp2((mx[mt][0] - mlo) * SCL);
            const float corrhi = fast_exp2((mx[mt][1] - mhi) * SCL);
            mx[mt][0] = mlo; mx[mt][1] = mhi;
            const float mslo = mlo * SCL, mshi = mhi * SCL;

            float slo = 0.f, shi = 0.f;
#pragma unroll
            for (int j = 0; j < 8; ++j) {
                sc[j][0] = fast_exp2(fmaf(sc[j][0], SCL, -mslo));
                sc[j][1] = fast_exp2(fmaf(sc[j][1], SCL, -mslo));
                sc[j][2] = fast_exp2(fmaf(sc[j][2], SCL, -mshi));
                sc[j][3] = fast_exp2(fmaf(sc[j][3], SCL, -mshi));
                slo += sc[j][0] + sc[j][1];
                shi += sc[j][2] + sc[j][3];
            }
            slo += __shfl_xor_sync(0xffffffffu, slo, 1);
            slo += __shfl_xor_sync(0xffffffffu, slo, 2);
            shi += __shfl_xor_sync(0xffffffffu, shi, 1);
            shi += __shfl_xor_sync(0xffffffffu, shi, 2);
            lsum[mt][0] = lsum[mt][0] * corrlo + slo;
            lsum[mt][1] = lsum[mt][1] * corrhi + shi;
#pragma unroll
            for (int ht = 0; ht < 2; ++ht) {
                oac[mt][ht][0] *= corrlo; oac[mt][ht][1] *= corrlo;
                oac[mt][ht][2] *= corrhi; oac[mt][ht][3] *= corrhi;
            }

            // --- pack P to bf16 a-frags, then P*V (2-term) ---
#pragma unroll
            for (int ks = 0; ks < 4; ++ks) {
                uint32_t pa[4];
                pa[0] = packbf(sc[2 * ks][0], sc[2 * ks][1]);
                pa[1] = packbf(sc[2 * ks][2], sc[2 * ks][3]);
                pa[2] = packbf(sc[2 * ks + 1][0], sc[2 * ks + 1][1]);
                pa[3] = packbf(sc[2 * ks + 1][2], sc[2 * ks + 1][3]);
                const uint32_t s0 = (uint32_t)((kb * 64 + ks * 16) * 32);
                uint32_t vh4[4], vl4[4];
                lm4t(vh4, sb + AVH + s0 + vloff);
                lm4t(vl4, sb + AVL + s0 + vloff);
                mma_bf16(oac[mt][0], pa, vh4[0], vh4[1]);
                mma_bf16(oac[mt][1], pa, vh4[2], vh4[3]);
                mma_bf16(oac[mt][0], pa, vl4[0], vl4[1]);
                mma_bf16(oac[mt][1], pa, vl4[2], vl4[3]);
            }
        }
    }

    // ---- epilogue: normalize + permuted split-bf16 store ----
    const int ca = c >> 2, e = c & 3;
    const int tt = 2 * e + b;
    const int b2 = tt >> 2, r2 = tt & 3;
#pragma unroll
    for (int mt = 0; mt < 2; ++mt) {
        const int s_lo = qt * 256 + w * 32 + mt * 16 + (lane >> 2);
        const int s_hi = s_lo + 8;
        const float inv_lo = 1.0f / lsum[mt][0];
        const float inv_hi = 1.0f / lsum[mt][1];
#pragma unroll
        for (int ht = 0; ht < 2; ++ht) {
            const int h0 = ht * 8 + 2 * (lane & 3);
#pragma unroll
            for (int rr = 0; rr < 2; ++rr) {
                const int s = rr ? s_hi : s_lo;
                const float inv = rr ? inv_hi : inv_lo;
                const float v0 = oac[mt][ht][rr * 2 + 0] * inv;
                const float v1 = oac[mt][ht][rr * 2 + 1] * inv;
                const int s2 = (r2 << 8) | (s >> 2);
                const int f = (ca << 6) | ((s & 3) << 4) | h0;
                const size_t off = (((size_t)b2 << 10) + s2) * 1024 + f;
                __nv_bfloat162 H, L;
                H.x = __float2bfloat16(v0); H.y = __float2bfloat16(v1);
                L.x = __float2bfloat16(v0 - __bfloat162float(H.x));
                L.y = __float2bfloat16(v1 - __bfloat162float(H.y));
                *(__nv_bfloat162*)(Ohi + off) = H;
                *(__nv_bfloat162*)(Olo + off) = L;
            }
        }
    }
}

// ---------------------------------------------------------------------------
extern "C" void kernel_launch(void* const* d_in, const int* in_sizes, int n_in,
                              void* d_out, int out_size)
{
    const float* x    = (const float*)d_in[0];
    const float* wq_b = (const float*)d_in[2];
    const float* wk_b = (const float*)d_in[4];
    const float* wv_b = (const float*)d_in[6];
    const float* vq_b = (const float*)d_in[8];
    const float* vk_b = (const float*)d_in[10];
    const float* vv_b = (const float*)d_in[12];
    const float* wo_b = (const float*)d_in[14];
    float* out = (float*)d_out;

    __nv_bfloat16 *xhi, *xlo, *whi, *wlo;
    __nv_bfloat16 *q1hi, *q1lo, *k1hi, *k1lo, *v1hi, *v1lo;
    __nv_bfloat16 *q2hi, *q2lo, *k2hi, *k2lo, *v2hi, *v2lo, *ophi, *oplo;
    cudaGetSymbolAddress((void**)&xhi, g_xhi);   cudaGetSymbolAddress((void**)&xlo, g_xlo);
    cudaGetSymbolAddress((void**)&whi, g_whi);   cudaGetSymbolAddress((void**)&wlo, g_wlo);
    cudaGetSymbolAddress((void**)&q1hi, g_q1hi); cudaGetSymbolAddress((void**)&q1lo, g_q1lo);
    cudaGetSymbolAddress((void**)&k1hi, g_k1hi); cudaGetSymbolAddress((void**)&k1lo, g_k1lo);
    cudaGetSymbolAddress((void**)&v1hi, g_v1hi); cudaGetSymbolAddress((void**)&v1lo, g_v1lo);
    cudaGetSymbolAddress((void**)&q2hi, g_q2hi); cudaGetSymbolAddress((void**)&q2lo, g_q2lo);
    cudaGetSymbolAddress((void**)&k2hi, g_k2hi); cudaGetSymbolAddress((void**)&k2lo, g_k2lo);
    cudaGetSymbolAddress((void**)&v2hi, g_v2hi); cudaGetSymbolAddress((void**)&v2lo, g_v2lo);
    cudaGetSymbolAddress((void**)&ophi, g_ophi); cudaGetSymbolAddress((void**)&oplo, g_oplo);

    // ---- split x + 7 weights into bf16 hi/lo ----
    SplitArgs sa;
    const float* srcs[8] = {x, (const float*)d_in[1], (const float*)d_in[3], (const float*)d_in[5],
                            (const float*)d_in[7], (const float*)d_in[9], (const float*)d_in[11],
                            (const float*)d_in[13]};
    for (int i = 0; i < 8; ++i) {
        sa.src[i] = srcs[i];
        if (i == 0) { sa.hi[i] = xhi; sa.lo[i] = xlo; sa.n[i] = 2097152; }
        else { sa.hi[i] = whi + (size_t)(i - 1) * 1048576; sa.lo[i] = wlo + (size_t)(i - 1) * 1048576; sa.n[i] = 1048576; }
    }
    split8<<<dim3(2048, 1, 8), 256>>>(sa);

    const int gemm_smem = 3 * 32768 + 1024;
    cudaFuncSetAttribute(gemm_mma, cudaFuncAttributeMaxDynamicSharedMemorySize, gemm_smem);

    GemmArgs a0{}, a1{}, a2{};
    // Layer 1: {q1,k1,v1} = x @ {wq,wk,wv}^T + b   (split bf16 output)
    a0 = {xhi, xlo, whi + 0 * 1048576, wlo + 0 * 1048576, wq_b, nullptr, q1hi, q1lo};
    a1 = {xhi, xlo, whi + 1 * 1048576, wlo + 1 * 1048576, wk_b, nullptr, k1hi, k1lo};
    a2 = {xhi, xlo, whi + 2 * 1048576, wlo + 2 * 1048576, wv_b, nullptr, v1hi, v1lo};
    gemm_mma<<<dim3(8, 16, 3), 256, gemm_smem>>>(a0, a1, a2, 0);

    // Layer 2: {q2,k2,v2} = {q1,k1,v1} @ {vq,vk,vv}^T + b  (split bf16 output)
    a0 = {q1hi, q1lo, whi + 3 * 1048576, wlo + 3 * 1048576, vq_b, nullptr, q2hi, q2lo};
    a1 = {k1hi, k1lo, whi + 4 * 1048576, wlo + 4 * 1048576, vk_b, nullptr, k2hi, k2lo};
    a2 = {v1hi, v1lo, whi + 5 * 1048576, wlo + 5 * 1048576, vv_b, nullptr, v2hi, v2lo};
    gemm_mma<<<dim3(8, 16, 3), 256, gemm_smem>>>(a0, a1, a2, 0);

    // Attention: MMA flash, writes permuted o (split bf16)
    const int attn_smem = 147456;
    cudaFuncSetAttribute(attention_mma, cudaFuncAttributeMaxDynamicSharedMemorySize, attn_smem);
    attention_mma<<<dim3(4, 64, 2), 256, attn_smem>>>(q2hi, q2lo, k2hi, k2lo, v2hi, v2lo, ophi, oplo);

    // Final: out = o @ wo^T + b (fp32 out)
    a0 = {ophi, oplo, whi + 6 * 1048576, wlo + 6 * 1048576, wo_b, out, nullptr, nullptr};
    gemm_mma<<<dim3(8, 16, 1), 256, gemm_smem>>>(a0, a0, a0, 1);
}

// round 5
// speedup vs baseline: 2.9463x; 1.1727x over previous
#include <cuda_runtime.h>
#include <cuda_bf16.h>
#include <cuda_fp16.h>
#include <cstdint>
#include <math.h>

// ===========================================================================
// Round 5: weight pre-multiply fusion (q = x @ (Vq Wq)^T + combined bias),
// split-bf16 3-term mma.sync GEMMs, flash attention with static-max softmax
// and fp16 P*V (accuracy margin), persistent K/V staging.
// ===========================================================================

__device__ __forceinline__ uint32_t smem_u32(const void* p) {
    uint32_t a;
    asm("{ .reg .u64 t; cvta.to.shared.u64 t, %1; cvt.u32.u64 %0, t; }" : "=r"(a) : "l"(p));
    return a;
}
__device__ __forceinline__ void lm4(uint32_t* r, uint32_t a) {
    asm volatile("ldmatrix.sync.aligned.m8n8.x4.shared.b16 {%0,%1,%2,%3}, [%4];"
        : "=r"(r[0]), "=r"(r[1]), "=r"(r[2]), "=r"(r[3]) : "r"(a));
}
__device__ __forceinline__ void lm4t(uint32_t* r, uint32_t a) {
    asm volatile("ldmatrix.sync.aligned.m8n8.x4.trans.shared.b16 {%0,%1,%2,%3}, [%4];"
        : "=r"(r[0]), "=r"(r[1]), "=r"(r[2]), "=r"(r[3]) : "r"(a));
}
__device__ __forceinline__ void mma_bf16(float* d, const uint32_t* a, uint32_t b0, uint32_t b1) {
    asm volatile("mma.sync.aligned.m16n8k16.row.col.f32.bf16.bf16.f32 "
        "{%0,%1,%2,%3}, {%4,%5,%6,%7}, {%8,%9}, {%0,%1,%2,%3};"
        : "+f"(d[0]), "+f"(d[1]), "+f"(d[2]), "+f"(d[3])
        : "r"(a[0]), "r"(a[1]), "r"(a[2]), "r"(a[3]), "r"(b0), "r"(b1));
}
__device__ __forceinline__ void mma_f16(float* d, const uint32_t* a, uint32_t b0, uint32_t b1) {
    asm volatile("mma.sync.aligned.m16n8k16.row.col.f32.f16.f16.f32 "
        "{%0,%1,%2,%3}, {%4,%5,%6,%7}, {%8,%9}, {%0,%1,%2,%3};"
        : "+f"(d[0]), "+f"(d[1]), "+f"(d[2]), "+f"(d[3])
        : "r"(a[0]), "r"(a[1]), "r"(a[2]), "r"(a[3]), "r"(b0), "r"(b1));
}
__device__ __forceinline__ void cpasync16(uint32_t dst, const void* src) {
    asm volatile("cp.async.cg.shared.global [%0], [%1], 16;" :: "r"(dst), "l"(src));
}
__device__ __forceinline__ float fast_exp2(float x) {
    float r; asm("ex2.approx.f32 %0, %1;" : "=f"(r) : "f"(x)); return r;
}
// pack two f32 -> f16x2 with lo = first arg
__device__ __forceinline__ uint32_t packh(float lo, float hi) {
    uint32_t d;
    asm("cvt.rn.f16x2.f32 %0, %1, %2;" : "=r"(d) : "f"(hi), "f"(lo));
    return d;
}

// ---------------- scratch (device globals; zero-initialized) ----------------
__device__ __nv_bfloat16 g_xhi[2097152], g_xlo[2097152];
__device__ __nv_bfloat16 g_whi[4194304], g_wlo[4194304];   // vq,vk,vv,wo splits
__device__ __nv_bfloat16 g_wThi[3145728], g_wTlo[3145728]; // wq,wk,wv transposed splits
__device__ __nv_bfloat16 g_wchi[3145728], g_wclo[3145728]; // combined weights
__device__ float g_bc[3072];                               // combined biases
__device__ float g_zb[1024];                               // zero bias (.bss)
__device__ __nv_bfloat16 g_q2hi[2097152], g_q2lo[2097152];
__device__ __nv_bfloat16 g_k2hi[2097152], g_k2lo[2097152];
__device__ __half       g_v2h[2097152],  g_v2l[2097152];
__device__ __nv_bfloat16 g_ophi[2097152], g_oplo[2097152];

// ---------------- split fp32 -> bf16 hi/lo (x, vq, vk, vv, wo) -------------
struct SplitArgs {
    const float* src[5];
    __nv_bfloat16* hi[5];
    __nv_bfloat16* lo[5];
    int n[5];
};

__global__ void __launch_bounds__(256) split5(SplitArgs a) {
    const int z = blockIdx.z;
    const int i = (blockIdx.x * 256 + threadIdx.x) * 4;
    if (i >= a.n[z]) return;
    const float4 v = *(const float4*)(a.src[z] + i);
    __nv_bfloat16 h0 = __float2bfloat16(v.x), h1 = __float2bfloat16(v.y);
    __nv_bfloat16 h2 = __float2bfloat16(v.z), h3 = __float2bfloat16(v.w);
    __nv_bfloat162 H0; H0.x = h0; H0.y = h1;
    __nv_bfloat162 H1; H1.x = h2; H1.y = h3;
    __nv_bfloat162 L0; L0.x = __float2bfloat16(v.x - __bfloat162float(h0));
    L0.y = __float2bfloat16(v.y - __bfloat162float(h1));
    __nv_bfloat162 L1; L1.x = __float2bfloat16(v.z - __bfloat162float(h2));
    L1.y = __float2bfloat16(v.w - __bfloat162float(h3));
    *(__nv_bfloat162*)(a.hi[z] + i) = H0;
    *(__nv_bfloat162*)(a.hi[z] + i + 2) = H1;
    *(__nv_bfloat162*)(a.lo[z] + i) = L0;
    *(__nv_bfloat162*)(a.lo[z] + i + 2) = L1;
}

// ---------------- transpose + split (wq, wk, wv) ----------------------------
// out[k][m] = in[m][k], bf16 hi/lo. 32x32 tiles.
__global__ void __launch_bounds__(256)
wsplitT(const float* W0, const float* W1, const float* W2,
        __nv_bfloat16* hiT, __nv_bfloat16* loT)
{
    const int z = blockIdx.z;
    const float* W = (z == 0) ? W0 : (z == 1) ? W1 : W2;
    __nv_bfloat16* ho = hiT + (size_t)z * 1048576;
    __nv_bfloat16* lo = loT + (size_t)z * 1048576;

    __shared__ float s[32][33];
    const int tx = threadIdx.x & 31;
    const int ty = threadIdx.x >> 5;       // 0..7
    const int k0 = blockIdx.x * 32;
    const int m0 = blockIdx.y * 32;
#pragma unroll
    for (int j = 0; j < 4; ++j)
        s[ty + j * 8][tx] = W[(size_t)(m0 + ty + j * 8) * 1024 + k0 + tx];
    __syncthreads();
#pragma unroll
    for (int j = 0; j < 4; ++j) {
        const float v = s[tx][ty + j * 8];
        const __nv_bfloat16 h = __float2bfloat16(v);
        const size_t off = (size_t)(k0 + ty + j * 8) * 1024 + m0 + tx;
        ho[off] = h;
        lo[off] = __float2bfloat16(v - __bfloat162float(h));
    }
}

// ---------------- combined bias: bc[n] = V[n,:].b + vb[n] -------------------
__global__ void __launch_bounds__(256)
bias_combine(const float* V0, const float* b0, const float* c0,
             const float* V1, const float* b1, const float* c1,
             const float* V2, const float* b2, const float* c2,
             float* bc)
{
    const int z = blockIdx.z;
    const float* V = (z == 0) ? V0 : (z == 1) ? V1 : V2;
    const float* b = (z == 0) ? b0 : (z == 1) ? b1 : b2;
    const float* c = (z == 0) ? c0 : (z == 1) ? c1 : c2;
    const int lane = threadIdx.x & 31;
    const int w = threadIdx.x >> 5;
    const int n = blockIdx.x * 8 + w;
    float s = 0.f;
#pragma unroll
    for (int it = 0; it < 8; ++it) {
        const int k = (it * 32 + lane) * 4;
        const float4 vv = *(const float4*)(V + (size_t)n * 1024 + k);
        const float4 bb = *(const float4*)(b + k);
        s += vv.x * bb.x + vv.y * bb.y + vv.z * bb.z + vv.w * bb.w;
    }
#pragma unroll
    for (int o = 16; o > 0; o >>= 1) s += __shfl_xor_sync(0xffffffffu, s, o);
    if (lane == 0) bc[z * 1024 + n] = s + c[n];
}

// ---------------- mma.sync GEMM (3-stage pipeline) --------------------------
// mode 0: bf16 hi/lo out; mode 1: fp32 out; mode 2: fp16 hi/lo out.
struct GemmArgs {
    const __nv_bfloat16 *Ahi, *Alo, *Bhi, *Blo;
    const float* bias;
    void *C0, *C1;
    int mode;
};

__device__ __forceinline__ uint32_t swz(int r, int s) {
    return (uint32_t)(r * 64 + ((s ^ ((r >> 1) & 3)) << 4));
}

__global__ void __launch_bounds__(256, 1)
gemm_mma(GemmArgs g0, GemmArgs g1, GemmArgs g2)
{
    const GemmArgs ga = (blockIdx.z == 0) ? g0 : (blockIdx.z == 1) ? g1 : g2;
    extern __shared__ char smem_raw[];
    const uint32_t sb = (smem_u32(smem_raw) + 1023u) & ~1023u;

    const int tid = threadIdx.x;
    const int lane = tid & 31;
    const int wid = tid >> 5;
    const int wm = wid & 3;
    const int wn = wid >> 2;
    const int bm = blockIdx.y * 128;
    const int bn = blockIdx.x * 128;

    const __nv_bfloat16* gp[8];
    uint32_t dst[8];
#pragma unroll
    for (int i = 0; i < 8; ++i) {
        const int u = tid + i * 256;
        const int t = u >> 9;
        const int r = (u >> 2) & 127;
        const int s = u & 3;
        const __nv_bfloat16* base = (t == 0) ? ga.Ahi : (t == 1) ? ga.Alo : (t == 2) ? ga.Bhi : ga.Blo;
        const int grow = ((t < 2) ? bm : bn) + r;
        gp[i] = base + (size_t)grow * 1024 + s * 8;
        dst[i] = sb + t * 8192 + swz(r, s);
    }

    uint32_t lmA[2], lmB[4];
    {
        const int rA = wm * 32 + ((lane >> 3) & 1) * 8 + (lane & 7);
        const int sA = lane >> 4;
#pragma unroll
        for (int mt = 0; mt < 2; ++mt) lmA[mt] = sb + swz(rA + mt * 16, sA);
        const int rB = wn * 64 + (lane >> 4) * 8 + (lane & 7);
        const int sB = (lane >> 3) & 1;
#pragma unroll
        for (int ng = 0; ng < 4; ++ng) lmB[ng] = sb + 16384 + swz(rB + ng * 16, sB);
    }

    float acc[2][4][2][4];
#pragma unroll
    for (int mt = 0; mt < 2; ++mt)
#pragma unroll
        for (int ng = 0; ng < 4; ++ng)
#pragma unroll
            for (int h = 0; h < 2; ++h)
#pragma unroll
                for (int j = 0; j < 4; ++j) acc[mt][ng][h][j] = 0.f;

#pragma unroll
    for (int i = 0; i < 8; ++i) cpasync16(dst[i], gp[i]);
    asm volatile("cp.async.commit_group;" ::: "memory");
#pragma unroll
    for (int i = 0; i < 8; ++i) cpasync16(dst[i] + 32768, gp[i] + 32);
    asm volatile("cp.async.commit_group;" ::: "memory");

#pragma unroll 1
    for (int ch = 0; ch < 32; ++ch) {
        if (ch < 31) { asm volatile("cp.async.wait_group 1;" ::: "memory"); }
        else         { asm volatile("cp.async.wait_group 0;" ::: "memory"); }
        __syncthreads();

        if (ch + 2 < 32) {
            const uint32_t sn = (uint32_t)(((ch + 2) % 3) * 32768);
#pragma unroll
            for (int i = 0; i < 8; ++i) cpasync16(dst[i] + sn, gp[i] + (ch + 2) * 32);
            asm volatile("cp.async.commit_group;" ::: "memory");
        }

        const uint32_t so = (uint32_t)((ch % 3) * 32768);
#pragma unroll
        for (int ks = 0; ks < 2; ++ks) {
            const uint32_t kx = (uint32_t)(ks << 5);
            uint32_t ah[2][4], al[2][4], bh[4][4], bl[4][4];
#pragma unroll
            for (int mt = 0; mt < 2; ++mt) {
                lm4(ah[mt], (lmA[mt] + so) ^ kx);
                lm4(al[mt], (lmA[mt] + 8192 + so) ^ kx);
            }
#pragma unroll
            for (int ng = 0; ng < 4; ++ng) {
                lm4(bh[ng], (lmB[ng] + so) ^ kx);
                lm4(bl[ng], (lmB[ng] + 8192 + so) ^ kx);
            }
#pragma unroll
            for (int mt = 0; mt < 2; ++mt)
#pragma unroll
                for (int ng = 0; ng < 4; ++ng)
#pragma unroll
                    for (int h = 0; h < 2; ++h) {
                        float* d = acc[mt][ng][h];
                        mma_bf16(d, ah[mt], bh[ng][2 * h], bh[ng][2 * h + 1]);
                        mma_bf16(d, al[mt], bh[ng][2 * h], bh[ng][2 * h + 1]);
                        mma_bf16(d, ah[mt], bl[ng][2 * h], bl[ng][2 * h + 1]);
                    }
        }
    }

#pragma unroll
    for (int mt = 0; mt < 2; ++mt) {
        const int r0 = bm + wm * 32 + mt * 16 + (lane >> 2);
#pragma unroll
        for (int ng = 0; ng < 4; ++ng)
#pragma unroll
            for (int h = 0; h < 2; ++h) {
                const int col = bn + wn * 64 + ng * 16 + h * 8 + 2 * (lane & 3);
                const float2 b2 = *(const float2*)(ga.bias + col);
                const float* a4 = acc[mt][ng][h];
                const float v00 = a4[0] + b2.x, v01 = a4[1] + b2.y;
                const float v10 = a4[2] + b2.x, v11 = a4[3] + b2.y;
                if (ga.mode == 1) {
                    float2 p0; p0.x = v00; p0.y = v01;
                    float2 p1; p1.x = v10; p1.y = v11;
                    *(float2*)((float*)ga.C0 + (size_t)r0 * 1024 + col) = p0;
                    *(float2*)((float*)ga.C0 + (size_t)(r0 + 8) * 1024 + col) = p1;
                } else if (ga.mode == 0) {
                    __nv_bfloat16* hp = (__nv_bfloat16*)ga.C0;
                    __nv_bfloat16* lp = (__nv_bfloat16*)ga.C1;
                    __nv_bfloat162 H0, L0, H1, L1;
                    H0.x = __float2bfloat16(v00); H0.y = __float2bfloat16(v01);
                    L0.x = __float2bfloat16(v00 - __bfloat162float(H0.x));
                    L0.y = __float2bfloat16(v01 - __bfloat162float(H0.y));
                    H1.x = __float2bfloat16(v10); H1.y = __float2bfloat16(v11);
                    L1.x = __float2bfloat16(v10 - __bfloat162float(H1.x));
                    L1.y = __float2bfloat16(v11 - __bfloat162float(H1.y));
                    *(__nv_bfloat162*)(hp + (size_t)r0 * 1024 + col) = H0;
                    *(__nv_bfloat162*)(lp + (size_t)r0 * 1024 + col) = L0;
                    *(__nv_bfloat162*)(hp + (size_t)(r0 + 8) * 1024 + col) = H1;
                    *(__nv_bfloat162*)(lp + (size_t)(r0 + 8) * 1024 + col) = L1;
                } else {
                    __half* hp = (__half*)ga.C0;
                    __half* lp = (__half*)ga.C1;
                    __half2 H0, L0, H1, L1;
                    H0.x = __float2half_rn(v00); H0.y = __float2half_rn(v01);
                    L0.x = __float2half_rn(v00 - __half2float(H0.x));
                    L0.y = __float2half_rn(v01 - __half2float(H0.y));
                    H1.x = __float2half_rn(v10); H1.y = __float2half_rn(v11);
                    L1.x = __float2half_rn(v10 - __half2float(H1.x));
                    L1.y = __float2half_rn(v11 - __half2float(H1.y));
                    *(__half2*)(hp + (size_t)r0 * 1024 + col) = H0;
                    *(__half2*)(lp + (size_t)r0 * 1024 + col) = L0;
                    *(__half2*)(hp + (size_t)(r0 + 8) * 1024 + col) = H1;
                    *(__half2*)(lp + (size_t)(r0 + 8) * 1024 + col) = L1;
                }
            }
    }
}

// ---------------- MMA flash attention (persistent per (c,b)) ---------------
// K bf16 hi/lo, V fp16 hi/lo staged once; 4 q-tiles looped. Static max (scores
// are O(1)), so no rescale chain; P in fp16; lsum reduced once at the end.
#define AKH 0u
#define AKL 32768u
#define AVH 65536u
#define AVL 98304u
#define AQH 131072u
#define AQL 139264u

__global__ void __launch_bounds__(256, 1)
attention_mma(const __nv_bfloat16* __restrict__ qhi, const __nv_bfloat16* __restrict__ qlo,
              const __nv_bfloat16* __restrict__ khi, const __nv_bfloat16* __restrict__ klo,
              const __half* __restrict__ vh, const __half* __restrict__ vl,
              __nv_bfloat16* __restrict__ Ohi, __nv_bfloat16* __restrict__ Olo)
{
    extern __shared__ char smraw[];
    const uint32_t sb = smem_u32(smraw);

    const int c = blockIdx.x;
    const int b = blockIdx.y;
    const int tid = threadIdx.x;
    const int lane = tid & 31;
    const int w = tid >> 5;

    // ---- stage K (bf16 hi/lo) + V (fp16 hi/lo), 1024x16 each ----
#pragma unroll
    for (int i = 0; i < 32; ++i) {
        const int u = tid + i * 256;
        const int arr = u >> 11;
        const int rem = u & 2047;
        const int r = rem >> 1;
        const int half = rem & 1;
        const void* base = (arr == 0) ? (const void*)khi : (arr == 1) ? (const void*)klo
                         : (arr == 2) ? (const void*)vh : (const void*)vl;
        const char* src = (const char*)base + ((((size_t)((b << 10) + r) << 10) + (c << 4) + (half << 3)) << 1);
        const uint32_t dstp = sb + (uint32_t)(arr << 15) + (uint32_t)(r * 32 + ((half ^ ((r >> 2) & 1)) << 4));
        cpasync16(dstp, src);
    }
    asm volatile("cp.async.commit_group;" ::: "memory");

    // lane offsets
    const uint32_t qoff = (uint32_t)((lane & 15) * 32 + ((((lane >> 4) & 1) ^ ((lane >> 2) & 1)) << 4));
    const uint32_t kloff = (uint32_t)(((lane & 7) + ((lane >> 4) << 3)) * 32 +
                                      ((((lane >> 3) & 1) ^ ((lane >> 2) & 1)) << 4));
    const uint32_t vloff = (uint32_t)(((lane & 7) + (((lane >> 3) & 1) << 3)) * 32 +
                                      ((((lane >> 4) & 1) ^ ((lane >> 2) & 1)) << 4));
    const float SCL = 0.25f * 1.4426950408889634f;

    // permute constants
    const int ca = c >> 2, e = c & 3;
    const int tt = 2 * e + b;
    const int b2 = tt >> 2, r2 = tt & 3;

#pragma unroll 1
    for (int qt = 0; qt < 4; ++qt) {
        // stage Q tile (256x16 hi/lo)
#pragma unroll
        for (int i = 0; i < 4; ++i) {
            const int u = tid + i * 256;
            const int arr = u >> 9;
            const int rem = u & 511;
            const int r = rem >> 1;
            const int half = rem & 1;
            const __nv_bfloat16* base = arr ? qlo : qhi;
            const __nv_bfloat16* src = base + ((size_t)((b << 10) + (qt << 8) + r) << 10) + (c << 4) + (half << 3);
            const uint32_t dstp = sb + AQH + (uint32_t)(arr << 13) + (uint32_t)(r * 32 + ((half ^ ((r >> 2) & 1)) << 4));
            cpasync16(dstp, src);
        }
        asm volatile("cp.async.commit_group;" ::: "memory");
        asm volatile("cp.async.wait_group 0;" ::: "memory");
        __syncthreads();

        uint32_t qh[2][4], ql[2][4];
#pragma unroll
        for (int mt = 0; mt < 2; ++mt) {
            const uint32_t rowb = (uint32_t)((w * 32 + mt * 16) * 32);
            lm4(qh[mt], sb + AQH + rowb + qoff);
            lm4(ql[mt], sb + AQL + rowb + qoff);
        }

        float oac[2][2][4];
        float lsum[2][2];
#pragma unroll
        for (int mt = 0; mt < 2; ++mt) {
            lsum[mt][0] = lsum[mt][1] = 0.f;
#pragma unroll
            for (int ht = 0; ht < 2; ++ht)
#pragma unroll
                for (int j = 0; j < 4; ++j) oac[mt][ht][j] = 0.f;
        }

#pragma unroll 1
        for (int kb = 0; kb < 16; ++kb) {
#pragma unroll
            for (int mt = 0; mt < 2; ++mt) {
                float sc[8][4];
#pragma unroll
                for (int j = 0; j < 8; ++j)
#pragma unroll
                    for (int i = 0; i < 4; ++i) sc[j][i] = 0.f;

                // QK^T: 3-term split
#pragma unroll
                for (int nt = 0; nt < 4; ++nt) {
                    const uint32_t s0 = (uint32_t)((kb * 64 + nt * 16) * 32);
                    uint32_t kh4[4], kl4[4];
                    lm4(kh4, sb + AKH + s0 + kloff);
                    lm4(kl4, sb + AKL + s0 + kloff);
                    mma_bf16(sc[2 * nt], qh[mt], kh4[0], kh4[1]);
                    mma_bf16(sc[2 * nt], ql[mt], kh4[0], kh4[1]);
                    mma_bf16(sc[2 * nt], qh[mt], kl4[0], kl4[1]);
                    mma_bf16(sc[2 * nt + 1], qh[mt], kh4[2], kh4[3]);
                    mma_bf16(sc[2 * nt + 1], ql[mt], kh4[2], kh4[3]);
                    mma_bf16(sc[2 * nt + 1], qh[mt], kl4[2], kl4[3]);
                }

                // exp2 (static max 0) + per-lane partial row sums
                float slo = 0.f, shi = 0.f;
#pragma unroll
                for (int j = 0; j < 8; ++j) {
                    sc[j][0] = fast_exp2(sc[j][0] * SCL);
                    sc[j][1] = fast_exp2(sc[j][1] * SCL);
                    sc[j][2] = fast_exp2(sc[j][2] * SCL);
                    sc[j][3] = fast_exp2(sc[j][3] * SCL);
                    slo += sc[j][0] + sc[j][1];
                    shi += sc[j][2] + sc[j][3];
                }
                lsum[mt][0] += slo;
                lsum[mt][1] += shi;

                // P (fp16) * V (fp16 hi/lo)
#pragma unroll
                for (int ks = 0; ks < 4; ++ks) {
                    uint32_t pa[4];
                    pa[0] = packh(sc[2 * ks][0], sc[2 * ks][1]);
                    pa[1] = packh(sc[2 * ks][2], sc[2 * ks][3]);
                    pa[2] = packh(sc[2 * ks + 1][0], sc[2 * ks + 1][1]);
                    pa[3] = packh(sc[2 * ks + 1][2], sc[2 * ks + 1][3]);
                    const uint32_t s0 = (uint32_t)((kb * 64 + ks * 16) * 32);
                    uint32_t vh4[4], vl4[4];
                    lm4t(vh4, sb + AVH + s0 + vloff);
                    lm4t(vl4, sb + AVL + s0 + vloff);
                    mma_f16(oac[mt][0], pa, vh4[0], vh4[1]);
                    mma_f16(oac[mt][1], pa, vh4[2], vh4[3]);
                    mma_f16(oac[mt][0], pa, vl4[0], vl4[1]);
                    mma_f16(oac[mt][1], pa, vl4[2], vl4[3]);
                }
            }
        }

        // reduce row sums once
#pragma unroll
        for (int mt = 0; mt < 2; ++mt)
#pragma unroll
            for (int rr = 0; rr < 2; ++rr) {
                float s = lsum[mt][rr];
                s += __shfl_xor_sync(0xffffffffu, s, 1);
                s += __shfl_xor_sync(0xffffffffu, s, 2);
                lsum[mt][rr] = s;
            }

        // epilogue: normalize + permuted split-bf16 store
#pragma unroll
        for (int mt = 0; mt < 2; ++mt) {
            const int s_lo = qt * 256 + w * 32 + mt * 16 + (lane >> 2);
            const float inv_lo = 1.0f / lsum[mt][0];
            const float inv_hi = 1.0f / lsum[mt][1];
#pragma unroll
            for (int ht = 0; ht < 2; ++ht) {
                const int h0 = ht * 8 + 2 * (lane & 3);
#pragma unroll
                for (int rr = 0; rr < 2; ++rr) {
                    const int s = s_lo + rr * 8;
                    const float inv = rr ? inv_hi : inv_lo;
                    const float v0 = oac[mt][ht][rr * 2 + 0] * inv;
                    const float v1 = oac[mt][ht][rr * 2 + 1] * inv;
                    const int s2 = (r2 << 8) | (s >> 2);
                    const int f = (ca << 6) | ((s & 3) << 4) | h0;
                    const size_t off = (((size_t)b2 << 10) + s2) * 1024 + f;
                    __nv_bfloat162 H, L;
                    H.x = __float2bfloat16(v0); H.y = __float2bfloat16(v1);
                    L.x = __float2bfloat16(v0 - __bfloat162float(H.x));
                    L.y = __float2bfloat16(v1 - __bfloat162float(H.y));
                    *(__nv_bfloat162*)(Ohi + off) = H;
                    *(__nv_bfloat162*)(Olo + off) = L;
                }
            }
        }
        __syncthreads();  // before next qt restages Q
    }
}

// ---------------------------------------------------------------------------
extern "C" void kernel_launch(void* const* d_in, const int* in_sizes, int n_in,
                              void* d_out, int out_size)
{
    const float* x    = (const float*)d_in[0];
    const float* wq_w = (const float*)d_in[1];
    const float* wq_b = (const float*)d_in[2];
    const float* wk_w = (const float*)d_in[3];
    const float* wk_b = (const float*)d_in[4];
    const float* wv_w = (const float*)d_in[5];
    const float* wv_b = (const float*)d_in[6];
    const float* vq_w = (const float*)d_in[7];
    const float* vq_b = (const float*)d_in[8];
    const float* vk_w = (const float*)d_in[9];
    const float* vk_b = (const float*)d_in[10];
    const float* vv_w = (const float*)d_in[11];
    const float* vv_b = (const float*)d_in[12];
    const float* wo_b = (const float*)d_in[14];
    float* out = (float*)d_out;

    __nv_bfloat16 *xhi, *xlo, *whi, *wlo, *wThi, *wTlo, *wchi, *wclo;
    __nv_bfloat16 *q2hi, *q2lo, *k2hi, *k2lo, *ophi, *oplo;
    __half *v2h, *v2l;
    float *bc, *zb;
    cudaGetSymbolAddress((void**)&xhi, g_xhi);   cudaGetSymbolAddress((void**)&xlo, g_xlo);
    cudaGetSymbolAddress((void**)&whi, g_whi);   cudaGetSymbolAddress((void**)&wlo, g_wlo);
    cudaGetSymbolAddress((void**)&wThi, g_wThi); cudaGetSymbolAddress((void**)&wTlo, g_wTlo);
    cudaGetSymbolAddress((void**)&wchi, g_wchi); cudaGetSymbolAddress((void**)&wclo, g_wclo);
    cudaGetSymbolAddress((void**)&bc, g_bc);     cudaGetSymbolAddress((void**)&zb, g_zb);
    cudaGetSymbolAddress((void**)&q2hi, g_q2hi); cudaGetSymbolAddress((void**)&q2lo, g_q2lo);
    cudaGetSymbolAddress((void**)&k2hi, g_k2hi); cudaGetSymbolAddress((void**)&k2lo, g_k2lo);
    cudaGetSymbolAddress((void**)&v2h, g_v2h);   cudaGetSymbolAddress((void**)&v2l, g_v2l);
    cudaGetSymbolAddress((void**)&ophi, g_ophi); cudaGetSymbolAddress((void**)&oplo, g_oplo);

    // 1) splits: x, vq, vk, vv, wo
    SplitArgs sa;
    const float* srcs[5] = {x, vq_w, vk_w, vv_w, (const float*)d_in[13]};
    for (int i = 0; i < 5; ++i) {
        sa.src[i] = srcs[i];
        if (i == 0) { sa.hi[i] = xhi; sa.lo[i] = xlo; sa.n[i] = 2097152; }
        else { sa.hi[i] = whi + (size_t)(i - 1) * 1048576; sa.lo[i] = wlo + (size_t)(i - 1) * 1048576; sa.n[i] = 1048576; }
    }
    split5<<<dim3(2048, 1, 5), 256>>>(sa);

    // 2) transpose-splits: wq, wk, wv
    wsplitT<<<dim3(32, 32, 3), 256>>>(wq_w, wk_w, wv_w, wThi, wTlo);

    // 3) combined biases
    bias_combine<<<dim3(128, 1, 3), 256>>>(vq_w, wq_b, vq_b, vk_w, wk_b, vk_b, vv_w, wv_b, vv_b, bc);

    const int gemm_smem = 3 * 32768 + 1024;
    cudaFuncSetAttribute(gemm_mma, cudaFuncAttributeMaxDynamicSharedMemorySize, gemm_smem);

    // 4) weight combine: Wc = Vq @ Wq (M=1024), split bf16 out
    GemmArgs a0{}, a1{}, a2{};
    a0 = {whi + 0, wlo + 0, wThi + 0, wTlo + 0, zb, wchi + 0, wclo + 0, 0};
    a1 = {whi + 1048576, wlo + 1048576, wThi + 1048576, wTlo + 1048576, zb, wchi + 1048576, wclo + 1048576, 0};
    a2 = {whi + 2097152, wlo + 2097152, wThi + 2097152, wTlo + 2097152, zb, wchi + 2097152, wclo + 2097152, 0};
    gemm_mma<<<dim3(8, 8, 3), 256, gemm_smem>>>(a0, a1, a2);

    // 5) data GEMMs: q2/k2 split bf16, v2 split fp16
    a0 = {xhi, xlo, wchi + 0, wclo + 0, bc + 0, q2hi, q2lo, 0};
    a1 = {xhi, xlo, wchi + 1048576, wclo + 1048576, bc + 1024, k2hi, k2lo, 0};
    a2 = {xhi, xlo, wchi + 2097152, wclo + 2097152, bc + 2048, v2h, v2l, 2};
    gemm_mma<<<dim3(8, 16, 3), 256, gemm_smem>>>(a0, a1, a2);

    // 6) attention (persistent per (c,b))
    const int attn_smem = 147456;
    cudaFuncSetAttribute(attention_mma, cudaFuncAttributeMaxDynamicSharedMemorySize, attn_smem);
    attention_mma<<<dim3(64, 2), 256, attn_smem>>>(q2hi, q2lo, k2hi, k2lo, v2h, v2l, ophi, oplo);

    // 7) final projection
    a0 = {ophi, oplo, whi + 3145728, wlo + 3145728, wo_b, out, nullptr, 1};
    gemm_mma<<<dim3(8, 16, 1), 256, gemm_smem>>>(a0, a0, a0);
}

// round 6
// speedup vs baseline: 3.1714x; 1.0764x over previous
#include <cuda_runtime.h>
#include <cuda_bf16.h>
#include <cuda_fp16.h>
#include <cstdint>
#include <math.h>

// ===========================================================================
// Round 6: occupancy-2 GEMMs (launch_bounds(256,2), paired B-frag loads),
// attention with f16x2 exp2 (half the MUFU work), shared K/V frags across
// m-tiles, and ones-MMA row sums. Weight pre-multiply fusion retained.
// ===========================================================================

__device__ __forceinline__ uint32_t smem_u32(const void* p) {
    uint32_t a;
    asm("{ .reg .u64 t; cvta.to.shared.u64 t, %1; cvt.u32.u64 %0, t; }" : "=r"(a) : "l"(p));
    return a;
}
__device__ __forceinline__ void lm4(uint32_t* r, uint32_t a) {
    asm volatile("ldmatrix.sync.aligned.m8n8.x4.shared.b16 {%0,%1,%2,%3}, [%4];"
        : "=r"(r[0]), "=r"(r[1]), "=r"(r[2]), "=r"(r[3]) : "r"(a));
}
__device__ __forceinline__ void lm4t(uint32_t* r, uint32_t a) {
    asm volatile("ldmatrix.sync.aligned.m8n8.x4.trans.shared.b16 {%0,%1,%2,%3}, [%4];"
        : "=r"(r[0]), "=r"(r[1]), "=r"(r[2]), "=r"(r[3]) : "r"(a));
}
__device__ __forceinline__ void mma_bf16(float* d, const uint32_t* a, uint32_t b0, uint32_t b1) {
    asm volatile("mma.sync.aligned.m16n8k16.row.col.f32.bf16.bf16.f32 "
        "{%0,%1,%2,%3}, {%4,%5,%6,%7}, {%8,%9}, {%0,%1,%2,%3};"
        : "+f"(d[0]), "+f"(d[1]), "+f"(d[2]), "+f"(d[3])
        : "r"(a[0]), "r"(a[1]), "r"(a[2]), "r"(a[3]), "r"(b0), "r"(b1));
}
__device__ __forceinline__ void mma_f16(float* d, const uint32_t* a, uint32_t b0, uint32_t b1) {
    asm volatile("mma.sync.aligned.m16n8k16.row.col.f32.f16.f16.f32 "
        "{%0,%1,%2,%3}, {%4,%5,%6,%7}, {%8,%9}, {%0,%1,%2,%3};"
        : "+f"(d[0]), "+f"(d[1]), "+f"(d[2]), "+f"(d[3])
        : "r"(a[0]), "r"(a[1]), "r"(a[2]), "r"(a[3]), "r"(b0), "r"(b1));
}
__device__ __forceinline__ void cpasync16(uint32_t dst, const void* src) {
    asm volatile("cp.async.cg.shared.global [%0], [%1], 16;" :: "r"(dst), "l"(src));
}
// pack two f32 -> f16x2 (low half = first arg)
__device__ __forceinline__ uint32_t packh(float lo, float hi) {
    uint32_t d;
    asm("cvt.rn.f16x2.f32 %0, %1, %2;" : "=r"(d) : "f"(hi), "f"(lo));
    return d;
}
__device__ __forceinline__ uint32_t hmul2(uint32_t a, uint32_t b) {
    uint32_t d; asm("mul.rn.f16x2 %0, %1, %2;" : "=r"(d) : "r"(a), "r"(b)); return d;
}
__device__ __forceinline__ uint32_t hex2(uint32_t a) {
    uint32_t d; asm("ex2.approx.f16x2 %0, %1;" : "=r"(d) : "r"(a)); return d;
}

// ---------------- scratch (device globals; zero-initialized) ----------------
__device__ __nv_bfloat16 g_xhi[2097152], g_xlo[2097152];
__device__ __nv_bfloat16 g_whi[4194304], g_wlo[4194304];   // vq,vk,vv,wo splits
__device__ __nv_bfloat16 g_wThi[3145728], g_wTlo[3145728]; // wq,wk,wv transposed splits
__device__ __nv_bfloat16 g_wchi[3145728], g_wclo[3145728]; // combined weights
__device__ float g_bc[3072];                               // combined biases
__device__ float g_zb[1024];                               // zero bias (.bss)
__device__ __nv_bfloat16 g_q2hi[2097152], g_q2lo[2097152];
__device__ __nv_bfloat16 g_k2hi[2097152], g_k2lo[2097152];
__device__ __half       g_v2h[2097152],  g_v2l[2097152];
__device__ __nv_bfloat16 g_ophi[2097152], g_oplo[2097152];

// ---------------- split fp32 -> bf16 hi/lo (x, vq, vk, vv, wo) -------------
struct SplitArgs {
    const float* src[5];
    __nv_bfloat16* hi[5];
    __nv_bfloat16* lo[5];
    int n[5];
};

__global__ void __launch_bounds__(256) split5(SplitArgs a) {
    const int z = blockIdx.z;
    const int i = (blockIdx.x * 256 + threadIdx.x) * 4;
    if (i >= a.n[z]) return;
    const float4 v = *(const float4*)(a.src[z] + i);
    __nv_bfloat16 h0 = __float2bfloat16(v.x), h1 = __float2bfloat16(v.y);
    __nv_bfloat16 h2 = __float2bfloat16(v.z), h3 = __float2bfloat16(v.w);
    __nv_bfloat162 H0; H0.x = h0; H0.y = h1;
    __nv_bfloat162 H1; H1.x = h2; H1.y = h3;
    __nv_bfloat162 L0; L0.x = __float2bfloat16(v.x - __bfloat162float(h0));
    L0.y = __float2bfloat16(v.y - __bfloat162float(h1));
    __nv_bfloat162 L1; L1.x = __float2bfloat16(v.z - __bfloat162float(h2));
    L1.y = __float2bfloat16(v.w - __bfloat162float(h3));
    *(__nv_bfloat162*)(a.hi[z] + i) = H0;
    *(__nv_bfloat162*)(a.hi[z] + i + 2) = H1;
    *(__nv_bfloat162*)(a.lo[z] + i) = L0;
    *(__nv_bfloat162*)(a.lo[z] + i + 2) = L1;
}

// ---------------- transpose + split (wq, wk, wv) ----------------------------
__global__ void __launch_bounds__(256)
wsplitT(const float* W0, const float* W1, const float* W2,
        __nv_bfloat16* hiT, __nv_bfloat16* loT)
{
    const int z = blockIdx.z;
    const float* W = (z == 0) ? W0 : (z == 1) ? W1 : W2;
    __nv_bfloat16* ho = hiT + (size_t)z * 1048576;
    __nv_bfloat16* lo = loT + (size_t)z * 1048576;

    __shared__ float s[32][33];
    const int tx = threadIdx.x & 31;
    const int ty = threadIdx.x >> 5;
    const int k0 = blockIdx.x * 32;
    const int m0 = blockIdx.y * 32;
#pragma unroll
    for (int j = 0; j < 4; ++j)
        s[ty + j * 8][tx] = W[(size_t)(m0 + ty + j * 8) * 1024 + k0 + tx];
    __syncthreads();
#pragma unroll
    for (int j = 0; j < 4; ++j) {
        const float v = s[tx][ty + j * 8];
        const __nv_bfloat16 h = __float2bfloat16(v);
        const size_t off = (size_t)(k0 + ty + j * 8) * 1024 + m0 + tx;
        ho[off] = h;
        lo[off] = __float2bfloat16(v - __bfloat162float(h));
    }
}

// ---------------- combined bias: bc[n] = V[n,:].b + vb[n] -------------------
__global__ void __launch_bounds__(256)
bias_combine(const float* V0, const float* b0, const float* c0,
             const float* V1, const float* b1, const float* c1,
             const float* V2, const float* b2, const float* c2,
             float* bc)
{
    const int z = blockIdx.z;
    const float* V = (z == 0) ? V0 : (z == 1) ? V1 : V2;
    const float* b = (z == 0) ? b0 : (z == 1) ? b1 : b2;
    const float* c = (z == 0) ? c0 : (z == 1) ? c1 : c2;
    const int lane = threadIdx.x & 31;
    const int w = threadIdx.x >> 5;
    const int n = blockIdx.x * 8 + w;
    float s = 0.f;
#pragma unroll
    for (int it = 0; it < 8; ++it) {
        const int k = (it * 32 + lane) * 4;
        const float4 vv = *(const float4*)(V + (size_t)n * 1024 + k);
        const float4 bb = *(const float4*)(b + k);
        s += vv.x * bb.x + vv.y * bb.y + vv.z * bb.z + vv.w * bb.w;
    }
#pragma unroll
    for (int o = 16; o > 0; o >>= 1) s += __shfl_xor_sync(0xffffffffu, s, o);
    if (lane == 0) bc[z * 1024 + n] = s + c[n];
}

// ---------------- mma.sync GEMM (3-stage pipeline, 2 CTAs/SM) ---------------
// mode 0: bf16 hi/lo out; mode 1: fp32 out; mode 2: fp16 hi/lo out.
struct GemmArgs {
    const __nv_bfloat16 *Ahi, *Alo, *Bhi, *Blo;
    const float* bias;
    void *C0, *C1;
    int mode;
};

__device__ __forceinline__ uint32_t swz(int r, int s) {
    return (uint32_t)(r * 64 + ((s ^ ((r >> 1) & 3)) << 4));
}

__global__ void __launch_bounds__(256, 2)
gemm_mma(GemmArgs g0, GemmArgs g1, GemmArgs g2)
{
    const GemmArgs ga = (blockIdx.z == 0) ? g0 : (blockIdx.z == 1) ? g1 : g2;
    extern __shared__ char smem_raw[];
    const uint32_t sb = (smem_u32(smem_raw) + 1023u) & ~1023u;

    const int tid = threadIdx.x;
    const int lane = tid & 31;
    const int wid = tid >> 5;
    const int wm = wid & 3;
    const int wn = wid >> 2;
    const int bm = blockIdx.y * 128;
    const int bn = blockIdx.x * 128;

    const __nv_bfloat16* gp[8];
    uint32_t dst[8];
#pragma unroll
    for (int i = 0; i < 8; ++i) {
        const int u = tid + i * 256;
        const int t = u >> 9;
        const int r = (u >> 2) & 127;
        const int s = u & 3;
        const __nv_bfloat16* base = (t == 0) ? ga.Ahi : (t == 1) ? ga.Alo : (t == 2) ? ga.Bhi : ga.Blo;
        const int grow = ((t < 2) ? bm : bn) + r;
        gp[i] = base + (size_t)grow * 1024 + s * 8;
        dst[i] = sb + t * 8192 + swz(r, s);
    }

    uint32_t lmA[2], lmB[4];
    {
        const int rA = wm * 32 + ((lane >> 3) & 1) * 8 + (lane & 7);
        const int sA = lane >> 4;
#pragma unroll
        for (int mt = 0; mt < 2; ++mt) lmA[mt] = sb + swz(rA + mt * 16, sA);
        const int rB = wn * 64 + (lane >> 4) * 8 + (lane & 7);
        const int sB = (lane >> 3) & 1;
#pragma unroll
        for (int ng = 0; ng < 4; ++ng) lmB[ng] = sb + 16384 + swz(rB + ng * 16, sB);
    }

    float acc[2][4][2][4];
#pragma unroll
    for (int mt = 0; mt < 2; ++mt)
#pragma unroll
        for (int ng = 0; ng < 4; ++ng)
#pragma unroll
            for (int h = 0; h < 2; ++h)
#pragma unroll
                for (int j = 0; j < 4; ++j) acc[mt][ng][h][j] = 0.f;

#pragma unroll
    for (int i = 0; i < 8; ++i) cpasync16(dst[i], gp[i]);
    asm volatile("cp.async.commit_group;" ::: "memory");
#pragma unroll
    for (int i = 0; i < 8; ++i) cpasync16(dst[i] + 32768, gp[i] + 32);
    asm volatile("cp.async.commit_group;" ::: "memory");

#pragma unroll 1
    for (int ch = 0; ch < 32; ++ch) {
        if (ch < 31) { asm volatile("cp.async.wait_group 1;" ::: "memory"); }
        else         { asm volatile("cp.async.wait_group 0;" ::: "memory"); }
        __syncthreads();

        if (ch + 2 < 32) {
            const uint32_t sn = (uint32_t)(((ch + 2) % 3) * 32768);
#pragma unroll
            for (int i = 0; i < 8; ++i) cpasync16(dst[i] + sn, gp[i] + (ch + 2) * 32);
            asm volatile("cp.async.commit_group;" ::: "memory");
        }

        const uint32_t so = (uint32_t)((ch % 3) * 32768);
#pragma unroll
        for (int ks = 0; ks < 2; ++ks) {
            const uint32_t kx = (uint32_t)(ks << 5);
            uint32_t ah[2][4], al[2][4];
#pragma unroll
            for (int mt = 0; mt < 2; ++mt) {
                lm4(ah[mt], (lmA[mt] + so) ^ kx);
                lm4(al[mt], (lmA[mt] + 8192 + so) ^ kx);
            }
            // B-frags in pairs of n-groups to bound live registers (occ 2)
#pragma unroll
            for (int ngp = 0; ngp < 2; ++ngp) {
                uint32_t bh[2][4], bl[2][4];
#pragma unroll
                for (int g = 0; g < 2; ++g) {
                    const int ng = ngp * 2 + g;
                    lm4(bh[g], (lmB[ng] + so) ^ kx);
                    lm4(bl[g], (lmB[ng] + 8192 + so) ^ kx);
                }
#pragma unroll
                for (int g = 0; g < 2; ++g)
#pragma unroll
                    for (int mt = 0; mt < 2; ++mt)
#pragma unroll
                        for (int h = 0; h < 2; ++h) {
                            float* d = acc[mt][ngp * 2 + g][h];
                            mma_bf16(d, ah[mt], bh[g][2 * h], bh[g][2 * h + 1]);
                            mma_bf16(d, al[mt], bh[g][2 * h], bh[g][2 * h + 1]);
                            mma_bf16(d, ah[mt], bl[g][2 * h], bl[g][2 * h + 1]);
                        }
            }
        }
    }

#pragma unroll
    for (int mt = 0; mt < 2; ++mt) {
        const int r0 = bm + wm * 32 + mt * 16 + (lane >> 2);
#pragma unroll
        for (int ng = 0; ng < 4; ++ng)
#pragma unroll
            for (int h = 0; h < 2; ++h) {
                const int col = bn + wn * 64 + ng * 16 + h * 8 + 2 * (lane & 3);
                const float2 b2 = *(const float2*)(ga.bias + col);
                const float* a4 = acc[mt][ng][h];
                const float v00 = a4[0] + b2.x, v01 = a4[1] + b2.y;
                const float v10 = a4[2] + b2.x, v11 = a4[3] + b2.y;
                if (ga.mode == 1) {
                    float2 p0; p0.x = v00; p0.y = v01;
                    float2 p1; p1.x = v10; p1.y = v11;
                    *(float2*)((float*)ga.C0 + (size_t)r0 * 1024 + col) = p0;
                    *(float2*)((float*)ga.C0 + (size_t)(r0 + 8) * 1024 + col) = p1;
                } else if (ga.mode == 0) {
                    __nv_bfloat16* hp = (__nv_bfloat16*)ga.C0;
                    __nv_bfloat16* lp = (__nv_bfloat16*)ga.C1;
                    __nv_bfloat162 H0, L0, H1, L1;
                    H0.x = __float2bfloat16(v00); H0.y = __float2bfloat16(v01);
                    L0.x = __float2bfloat16(v00 - __bfloat162float(H0.x));
                    L0.y = __float2bfloat16(v01 - __bfloat162float(H0.y));
                    H1.x = __float2bfloat16(v10); H1.y = __float2bfloat16(v11);
                    L1.x = __float2bfloat16(v10 - __bfloat162float(H1.x));
                    L1.y = __float2bfloat16(v11 - __bfloat162float(H1.y));
                    *(__nv_bfloat162*)(hp + (size_t)r0 * 1024 + col) = H0;
                    *(__nv_bfloat162*)(lp + (size_t)r0 * 1024 + col) = L0;
                    *(__nv_bfloat162*)(hp + (size_t)(r0 + 8) * 1024 + col) = H1;
                    *(__nv_bfloat162*)(lp + (size_t)(r0 + 8) * 1024 + col) = L1;
                } else {
                    __half* hp = (__half*)ga.C0;
                    __half* lp = (__half*)ga.C1;
                    __half2 H0, L0, H1, L1;
                    H0.x = __float2half_rn(v00); H0.y = __float2half_rn(v01);
                    L0.x = __float2half_rn(v00 - __half2float(H0.x));
                    L0.y = __float2half_rn(v01 - __half2float(H0.y));
                    H1.x = __float2half_rn(v10); H1.y = __float2half_rn(v11);
                    L1.x = __float2half_rn(v10 - __half2float(H1.x));
                    L1.y = __float2half_rn(v11 - __half2float(H1.y));
                    *(__half2*)(hp + (size_t)r0 * 1024 + col) = H0;
                    *(__half2*)(lp + (size_t)r0 * 1024 + col) = L0;
                    *(__half2*)(hp + (size_t)(r0 + 8) * 1024 + col) = H1;
                    *(__half2*)(lp + (size_t)(r0 + 8) * 1024 + col) = L1;
                }
            }
    }
}

// ---------------- MMA flash attention (persistent per (c,b)) ---------------
#define AKH 0u
#define AKL 32768u
#define AVH 65536u
#define AVL 98304u
#define AQH 131072u
#define AQL 139264u

__global__ void __launch_bounds__(256, 1)
attention_mma(const __nv_bfloat16* __restrict__ qhi, const __nv_bfloat16* __restrict__ qlo,
              const __nv_bfloat16* __restrict__ khi, const __nv_bfloat16* __restrict__ klo,
              const __half* __restrict__ vh, const __half* __restrict__ vl,
              __nv_bfloat16* __restrict__ Ohi, __nv_bfloat16* __restrict__ Olo)
{
    extern __shared__ char smraw[];
    const uint32_t sb = smem_u32(smraw);

    const int c = blockIdx.x;
    const int b = blockIdx.y;
    const int tid = threadIdx.x;
    const int lane = tid & 31;
    const int w = tid >> 5;

    // ---- stage K (bf16 hi/lo) + V (fp16 hi/lo), 1024x16 each ----
#pragma unroll
    for (int i = 0; i < 32; ++i) {
        const int u = tid + i * 256;
        const int arr = u >> 11;
        const int rem = u & 2047;
        const int r = rem >> 1;
        const int half = rem & 1;
        const void* base = (arr == 0) ? (const void*)khi : (arr == 1) ? (const void*)klo
                         : (arr == 2) ? (const void*)vh : (const void*)vl;
        const char* src = (const char*)base + ((((size_t)((b << 10) + r) << 10) + (c << 4) + (half << 3)) << 1);
        const uint32_t dstp = sb + (uint32_t)(arr << 15) + (uint32_t)(r * 32 + ((half ^ ((r >> 2) & 1)) << 4));
        cpasync16(dstp, src);
    }
    asm volatile("cp.async.commit_group;" ::: "memory");

    const uint32_t qoff = (uint32_t)((lane & 15) * 32 + ((((lane >> 4) & 1) ^ ((lane >> 2) & 1)) << 4));
    const uint32_t kloff = (uint32_t)(((lane & 7) + ((lane >> 4) << 3)) * 32 +
                                      ((((lane >> 3) & 1) ^ ((lane >> 2) & 1)) << 4));
    const uint32_t vloff = (uint32_t)(((lane & 7) + (((lane >> 3) & 1) << 3)) * 32 +
                                      ((((lane >> 4) & 1) ^ ((lane >> 2) & 1)) << 4));
    const float SCL = 0.25f * 1.4426950408889634f;
    const uint32_t scl2 = packh(SCL, SCL);
    const uint32_t ONES = 0x3C003C00u;  // half2(1.0, 1.0)

    const int ca = c >> 2, e = c & 3;
    const int tt = 2 * e + b;
    const int b2 = tt >> 2, r2 = tt & 3;

#pragma unroll 1
    for (int qt = 0; qt < 4; ++qt) {
        // stage Q tile (256x16 hi/lo)
#pragma unroll
        for (int i = 0; i < 4; ++i) {
            const int u = tid + i * 256;
            const int arr = u >> 9;
            const int rem = u & 511;
            const int r = rem >> 1;
            const int half = rem & 1;
            const __nv_bfloat16* base = arr ? qlo : qhi;
            const __nv_bfloat16* src = base + ((size_t)((b << 10) + (qt << 8) + r) << 10) + (c << 4) + (half << 3);
            const uint32_t dstp = sb + AQH + (uint32_t)(arr << 13) + (uint32_t)(r * 32 + ((half ^ ((r >> 2) & 1)) << 4));
            cpasync16(dstp, src);
        }
        asm volatile("cp.async.commit_group;" ::: "memory");
        asm volatile("cp.async.wait_group 0;" ::: "memory");
        __syncthreads();

        uint32_t qh[2][4], ql[2][4];
#pragma unroll
        for (int mt = 0; mt < 2; ++mt) {
            const uint32_t rowb = (uint32_t)((w * 32 + mt * 16) * 32);
            lm4(qh[mt], sb + AQH + rowb + qoff);
            lm4(ql[mt], sb + AQL + rowb + qoff);
        }

        float oac[2][2][4];
        float ls[2][4];
#pragma unroll
        for (int mt = 0; mt < 2; ++mt) {
#pragma unroll
            for (int j = 0; j < 4; ++j) ls[mt][j] = 0.f;
#pragma unroll
            for (int ht = 0; ht < 2; ++ht)
#pragma unroll
                for (int j = 0; j < 4; ++j) oac[mt][ht][j] = 0.f;
        }

#pragma unroll 1
        for (int kb = 0; kb < 16; ++kb) {
            float sc[2][8][4];
#pragma unroll
            for (int mt = 0; mt < 2; ++mt)
#pragma unroll
                for (int j = 0; j < 8; ++j)
#pragma unroll
                    for (int i = 0; i < 4; ++i) sc[mt][j][i] = 0.f;

            // QK^T: K frags shared across both m-tiles
#pragma unroll
            for (int nt = 0; nt < 4; ++nt) {
                const uint32_t s0 = (uint32_t)((kb * 64 + nt * 16) * 32);
                uint32_t kh4[4], kl4[4];
                lm4(kh4, sb + AKH + s0 + kloff);
                lm4(kl4, sb + AKL + s0 + kloff);
#pragma unroll
                for (int mt = 0; mt < 2; ++mt) {
                    mma_bf16(sc[mt][2 * nt], qh[mt], kh4[0], kh4[1]);
                    mma_bf16(sc[mt][2 * nt], ql[mt], kh4[0], kh4[1]);
                    mma_bf16(sc[mt][2 * nt], qh[mt], kl4[0], kl4[1]);
                    mma_bf16(sc[mt][2 * nt + 1], qh[mt], kh4[2], kh4[3]);
                    mma_bf16(sc[mt][2 * nt + 1], ql[mt], kh4[2], kh4[3]);
                    mma_bf16(sc[mt][2 * nt + 1], qh[mt], kl4[2], kl4[3]);
                }
            }

            // P = exp2(sc*SCL) in f16x2; V frags shared across m-tiles;
            // row sums via ones-column MMA (replicated across each quad).
#pragma unroll
            for (int ks = 0; ks < 4; ++ks) {
                const uint32_t s0 = (uint32_t)((kb * 64 + ks * 16) * 32);
                uint32_t vh4[4], vl4[4];
                lm4t(vh4, sb + AVH + s0 + vloff);
                lm4t(vl4, sb + AVL + s0 + vloff);
#pragma unroll
                for (int mt = 0; mt < 2; ++mt) {
                    uint32_t pa[4];
                    pa[0] = hex2(hmul2(packh(sc[mt][2 * ks][0], sc[mt][2 * ks][1]), scl2));
                    pa[1] = hex2(hmul2(packh(sc[mt][2 * ks][2], sc[mt][2 * ks][3]), scl2));
                    pa[2] = hex2(hmul2(packh(sc[mt][2 * ks + 1][0], sc[mt][2 * ks + 1][1]), scl2));
                    pa[3] = hex2(hmul2(packh(sc[mt][2 * ks + 1][2], sc[mt][2 * ks + 1][3]), scl2));
                    mma_f16(oac[mt][0], pa, vh4[0], vh4[1]);
                    mma_f16(oac[mt][1], pa, vh4[2], vh4[3]);
                    mma_f16(oac[mt][0], pa, vl4[0], vl4[1]);
                    mma_f16(oac[mt][1], pa, vl4[2], vl4[3]);
                    mma_f16(ls[mt], pa, ONES, ONES);
                }
            }
        }

        // epilogue: normalize + permuted split-bf16 store
#pragma unroll
        for (int mt = 0; mt < 2; ++mt) {
            const int s_lo = qt * 256 + w * 32 + mt * 16 + (lane >> 2);
            const float inv_lo = 1.0f / ls[mt][0];
            const float inv_hi = 1.0f / ls[mt][2];
#pragma unroll
            for (int ht = 0; ht < 2; ++ht) {
                const int h0 = ht * 8 + 2 * (lane & 3);
#pragma unroll
                for (int rr = 0; rr < 2; ++rr) {
                    const int s = s_lo + rr * 8;
                    const float inv = rr ? inv_hi : inv_lo;
                    const float v0 = oac[mt][ht][rr * 2 + 0] * inv;
                    const float v1 = oac[mt][ht][rr * 2 + 1] * inv;
                    const int s2 = (r2 << 8) | (s >> 2);
                    const int f = (ca << 6) | ((s & 3) << 4) | h0;
                    const size_t off = (((size_t)b2 << 10) + s2) * 1024 + f;
                    __nv_bfloat162 H, L;
                    H.x = __float2bfloat16(v0); H.y = __float2bfloat16(v1);
                    L.x = __float2bfloat16(v0 - __bfloat162float(H.x));
                    L.y = __float2bfloat16(v1 - __bfloat162float(H.y));
                    *(__nv_bfloat162*)(Ohi + off) = H;
                    *(__nv_bfloat162*)(Olo + off) = L;
                }
            }
        }
        __syncthreads();
    }
}

// ---------------------------------------------------------------------------
extern "C" void kernel_launch(void* const* d_in, const int* in_sizes, int n_in,
                              void* d_out, int out_size)
{
    const float* x    = (const float*)d_in[0];
    const float* wq_w = (const float*)d_in[1];
    const float* wq_b = (const float*)d_in[2];
    const float* wk_w = (const float*)d_in[3];
    const float* wk_b = (const float*)d_in[4];
    const float* wv_w = (const float*)d_in[5];
    const float* wv_b = (const float*)d_in[6];
    const float* vq_w = (const float*)d_in[7];
    const float* vq_b = (const float*)d_in[8];
    const float* vk_w = (const float*)d_in[9];
    const float* vk_b = (const float*)d_in[10];
    const float* vv_w = (const float*)d_in[11];
    const float* vv_b = (const float*)d_in[12];
    const float* wo_b = (const float*)d_in[14];
    float* out = (float*)d_out;

    __nv_bfloat16 *xhi, *xlo, *whi, *wlo, *wThi, *wTlo, *wchi, *wclo;
    __nv_bfloat16 *q2hi, *q2lo, *k2hi, *k2lo, *ophi, *oplo;
    __half *v2h, *v2l;
    float *bc, *zb;
    cudaGetSymbolAddress((void**)&xhi, g_xhi);   cudaGetSymbolAddress((void**)&xlo, g_xlo);
    cudaGetSymbolAddress((void**)&whi, g_whi);   cudaGetSymbolAddress((void**)&wlo, g_wlo);
    cudaGetSymbolAddress((void**)&wThi, g_wThi); cudaGetSymbolAddress((void**)&wTlo, g_wTlo);
    cudaGetSymbolAddress((void**)&wchi, g_wchi); cudaGetSymbolAddress((void**)&wclo, g_wclo);
    cudaGetSymbolAddress((void**)&bc, g_bc);     cudaGetSymbolAddress((void**)&zb, g_zb);
    cudaGetSymbolAddress((void**)&q2hi, g_q2hi); cudaGetSymbolAddress((void**)&q2lo, g_q2lo);
    cudaGetSymbolAddress((void**)&k2hi, g_k2hi); cudaGetSymbolAddress((void**)&k2lo, g_k2lo);
    cudaGetSymbolAddress((void**)&v2h, g_v2h);   cudaGetSymbolAddress((void**)&v2l, g_v2l);
    cudaGetSymbolAddress((void**)&ophi, g_ophi); cudaGetSymbolAddress((void**)&oplo, g_oplo);

    // 1) splits: x, vq, vk, vv, wo
    SplitArgs sa;
    const float* srcs[5] = {x, vq_w, vk_w, vv_w, (const float*)d_in[13]};
    for (int i = 0; i < 5; ++i) {
        sa.src[i] = srcs[i];
        if (i == 0) { sa.hi[i] = xhi; sa.lo[i] = xlo; sa.n[i] = 2097152; }
        else { sa.hi[i] = whi + (size_t)(i - 1) * 1048576; sa.lo[i] = wlo + (size_t)(i - 1) * 1048576; sa.n[i] = 1048576; }
    }
    split5<<<dim3(2048, 1, 5), 256>>>(sa);

    // 2) transpose-splits: wq, wk, wv
    wsplitT<<<dim3(32, 32, 3), 256>>>(wq_w, wk_w, wv_w, wThi, wTlo);

    // 3) combined biases
    bias_combine<<<dim3(128, 1, 3), 256>>>(vq_w, wq_b, vq_b, vk_w, wk_b, vk_b, vv_w, wv_b, vv_b, bc);

    const int gemm_smem = 3 * 32768 + 1024;
    cudaFuncSetAttribute(gemm_mma, cudaFuncAttributeMaxDynamicSharedMemorySize, gemm_smem);

    // 4) weight combine: Wc = Vq @ Wq (M=1024), split bf16 out
    GemmArgs a0{}, a1{}, a2{};
    a0 = {whi + 0, wlo + 0, wThi + 0, wTlo + 0, zb, wchi + 0, wclo + 0, 0};
    a1 = {whi + 1048576, wlo + 1048576, wThi + 1048576, wTlo + 1048576, zb, wchi + 1048576, wclo + 1048576, 0};
    a2 = {whi + 2097152, wlo + 2097152, wThi + 2097152, wTlo + 2097152, zb, wchi + 2097152, wclo + 2097152, 0};
    gemm_mma<<<dim3(8, 8, 3), 256, gemm_smem>>>(a0, a1, a2);

    // 5) data GEMMs: q2/k2 split bf16, v2 split fp16
    a0 = {xhi, xlo, wchi + 0, wclo + 0, bc + 0, q2hi, q2lo, 0};
    a1 = {xhi, xlo, wchi + 1048576, wclo + 1048576, bc + 1024, k2hi, k2lo, 0};
    a2 = {xhi, xlo, wchi + 2097152, wclo + 2097152, bc + 2048, v2h, v2l, 2};
    gemm_mma<<<dim3(8, 16, 3), 256, gemm_smem>>>(a0, a1, a2);

    // 6) attention (persistent per (c,b))
    const int attn_smem = 147456;
    cudaFuncSetAttribute(attention_mma, cudaFuncAttributeMaxDynamicSharedMemorySize, attn_smem);
    attention_mma<<<dim3(64, 2), 256, attn_smem>>>(q2hi, q2lo, k2hi, k2lo, v2h, v2l, ophi, oplo);

    // 7) final projection
    a0 = {ophi, oplo, whi + 3145728, wlo + 3145728, wo_b, out, nullptr, 1};
    gemm_mma<<<dim3(8, 16, 1), 256, gemm_smem>>>(a0, a0, a0);
}

// round 7
// speedup vs baseline: 3.5010x; 1.1039x over previous
#include <cuda_runtime.h>
#include <cuda_bf16.h>
#include <cuda_fp16.h>
#include <cstdint>
#include <math.h>

// ===========================================================================
// Round 7: term-major MMA ordering in GEMMs (break same-accumulator HMMA
// dependency chains); attention on single-fp16 Q/K/V (1-term QK & PV, occ 2).
// ===========================================================================

__device__ __forceinline__ uint32_t smem_u32(const void* p) {
    uint32_t a;
    asm("{ .reg .u64 t; cvta.to.shared.u64 t, %1; cvt.u32.u64 %0, t; }" : "=r"(a) : "l"(p));
    return a;
}
__device__ __forceinline__ void lm4(uint32_t* r, uint32_t a) {
    asm volatile("ldmatrix.sync.aligned.m8n8.x4.shared.b16 {%0,%1,%2,%3}, [%4];"
        : "=r"(r[0]), "=r"(r[1]), "=r"(r[2]), "=r"(r[3]) : "r"(a));
}
__device__ __forceinline__ void lm4t(uint32_t* r, uint32_t a) {
    asm volatile("ldmatrix.sync.aligned.m8n8.x4.trans.shared.b16 {%0,%1,%2,%3}, [%4];"
        : "=r"(r[0]), "=r"(r[1]), "=r"(r[2]), "=r"(r[3]) : "r"(a));
}
__device__ __forceinline__ void mma_bf16(float* d, const uint32_t* a, uint32_t b0, uint32_t b1) {
    asm volatile("mma.sync.aligned.m16n8k16.row.col.f32.bf16.bf16.f32 "
        "{%0,%1,%2,%3}, {%4,%5,%6,%7}, {%8,%9}, {%0,%1,%2,%3};"
        : "+f"(d[0]), "+f"(d[1]), "+f"(d[2]), "+f"(d[3])
        : "r"(a[0]), "r"(a[1]), "r"(a[2]), "r"(a[3]), "r"(b0), "r"(b1));
}
__device__ __forceinline__ void mma_f16(float* d, const uint32_t* a, uint32_t b0, uint32_t b1) {
    asm volatile("mma.sync.aligned.m16n8k16.row.col.f32.f16.f16.f32 "
        "{%0,%1,%2,%3}, {%4,%5,%6,%7}, {%8,%9}, {%0,%1,%2,%3};"
        : "+f"(d[0]), "+f"(d[1]), "+f"(d[2]), "+f"(d[3])
        : "r"(a[0]), "r"(a[1]), "r"(a[2]), "r"(a[3]), "r"(b0), "r"(b1));
}
__device__ __forceinline__ void cpasync16(uint32_t dst, const void* src) {
    asm volatile("cp.async.cg.shared.global [%0], [%1], 16;" :: "r"(dst), "l"(src));
}
__device__ __forceinline__ uint32_t packh(float lo, float hi) {
    uint32_t d;
    asm("cvt.rn.f16x2.f32 %0, %1, %2;" : "=r"(d) : "f"(hi), "f"(lo));
    return d;
}
__device__ __forceinline__ uint32_t hmul2(uint32_t a, uint32_t b) {
    uint32_t d; asm("mul.rn.f16x2 %0, %1, %2;" : "=r"(d) : "r"(a), "r"(b)); return d;
}
__device__ __forceinline__ uint32_t hex2(uint32_t a) {
    uint32_t d; asm("ex2.approx.f16x2 %0, %1;" : "=r"(d) : "r"(a)); return d;
}

// ---------------- scratch (device globals) ---------------------------------
__device__ __nv_bfloat16 g_xhi[2097152], g_xlo[2097152];
__device__ __nv_bfloat16 g_whi[4194304], g_wlo[4194304];   // vq,vk,vv,wo splits
__device__ __nv_bfloat16 g_wThi[3145728], g_wTlo[3145728]; // wq,wk,wv transposed splits
__device__ __nv_bfloat16 g_wchi[3145728], g_wclo[3145728]; // combined weights
__device__ float g_bc[3072];                               // combined biases
__device__ float g_zb[1024];                               // zero bias (.bss)
__device__ __half g_q2f[2097152], g_k2f[2097152], g_v2f[2097152];
__device__ __nv_bfloat16 g_ophi[2097152], g_oplo[2097152];

// ---------------- split fp32 -> bf16 hi/lo (x, vq, vk, vv, wo) -------------
struct SplitArgs {
    const float* src[5];
    __nv_bfloat16* hi[5];
    __nv_bfloat16* lo[5];
    int n[5];
};

__global__ void __launch_bounds__(256) split5(SplitArgs a) {
    const int z = blockIdx.z;
    const int i = (blockIdx.x * 256 + threadIdx.x) * 4;
    if (i >= a.n[z]) return;
    const float4 v = *(const float4*)(a.src[z] + i);
    __nv_bfloat16 h0 = __float2bfloat16(v.x), h1 = __float2bfloat16(v.y);
    __nv_bfloat16 h2 = __float2bfloat16(v.z), h3 = __float2bfloat16(v.w);
    __nv_bfloat162 H0; H0.x = h0; H0.y = h1;
    __nv_bfloat162 H1; H1.x = h2; H1.y = h3;
    __nv_bfloat162 L0; L0.x = __float2bfloat16(v.x - __bfloat162float(h0));
    L0.y = __float2bfloat16(v.y - __bfloat162float(h1));
    __nv_bfloat162 L1; L1.x = __float2bfloat16(v.z - __bfloat162float(h2));
    L1.y = __float2bfloat16(v.w - __bfloat162float(h3));
    *(__nv_bfloat162*)(a.hi[z] + i) = H0;
    *(__nv_bfloat162*)(a.hi[z] + i + 2) = H1;
    *(__nv_bfloat162*)(a.lo[z] + i) = L0;
    *(__nv_bfloat162*)(a.lo[z] + i + 2) = L1;
}

// ---------------- transpose + split (wq, wk, wv) ----------------------------
__global__ void __launch_bounds__(256)
wsplitT(const float* W0, const float* W1, const float* W2,
        __nv_bfloat16* hiT, __nv_bfloat16* loT)
{
    const int z = blockIdx.z;
    const float* W = (z == 0) ? W0 : (z == 1) ? W1 : W2;
    __nv_bfloat16* ho = hiT + (size_t)z * 1048576;
    __nv_bfloat16* lo = loT + (size_t)z * 1048576;

    __shared__ float s[32][33];
    const int tx = threadIdx.x & 31;
    const int ty = threadIdx.x >> 5;
    const int k0 = blockIdx.x * 32;
    const int m0 = blockIdx.y * 32;
#pragma unroll
    for (int j = 0; j < 4; ++j)
        s[ty + j * 8][tx] = W[(size_t)(m0 + ty + j * 8) * 1024 + k0 + tx];
    __syncthreads();
#pragma unroll
    for (int j = 0; j < 4; ++j) {
        const float v = s[tx][ty + j * 8];
        const __nv_bfloat16 h = __float2bfloat16(v);
        const size_t off = (size_t)(k0 + ty + j * 8) * 1024 + m0 + tx;
        ho[off] = h;
        lo[off] = __float2bfloat16(v - __bfloat162float(h));
    }
}

// ---------------- combined bias: bc[n] = V[n,:].b + vb[n] -------------------
__global__ void __launch_bounds__(256)
bias_combine(const float* V0, const float* b0, const float* c0,
             const float* V1, const float* b1, const float* c1,
             const float* V2, const float* b2, const float* c2,
             float* bc)
{
    const int z = blockIdx.z;
    const float* V = (z == 0) ? V0 : (z == 1) ? V1 : V2;
    const float* b = (z == 0) ? b0 : (z == 1) ? b1 : b2;
    const float* c = (z == 0) ? c0 : (z == 1) ? c1 : c2;
    const int lane = threadIdx.x & 31;
    const int w = threadIdx.x >> 5;
    const int n = blockIdx.x * 8 + w;
    float s = 0.f;
#pragma unroll
    for (int it = 0; it < 8; ++it) {
        const int k = (it * 32 + lane) * 4;
        const float4 vv = *(const float4*)(V + (size_t)n * 1024 + k);
        const float4 bb = *(const float4*)(b + k);
        s += vv.x * bb.x + vv.y * bb.y + vv.z * bb.z + vv.w * bb.w;
    }
#pragma unroll
    for (int o = 16; o > 0; o >>= 1) s += __shfl_xor_sync(0xffffffffu, s, o);
    if (lane == 0) bc[z * 1024 + n] = s + c[n];
}

// ---------------- mma.sync GEMM (3-stage, occ 2, term-major) ----------------
// mode 0: bf16 hi/lo out; mode 1: fp32 out; mode 2: fp16 single out.
struct GemmArgs {
    const __nv_bfloat16 *Ahi, *Alo, *Bhi, *Blo;
    const float* bias;
    void *C0, *C1;
    int mode;
};

__device__ __forceinline__ uint32_t swz(int r, int s) {
    return (uint32_t)(r * 64 + ((s ^ ((r >> 1) & 3)) << 4));
}

__global__ void __launch_bounds__(256, 2)
gemm_mma(GemmArgs g0, GemmArgs g1, GemmArgs g2)
{
    const GemmArgs ga = (blockIdx.z == 0) ? g0 : (blockIdx.z == 1) ? g1 : g2;
    extern __shared__ char smem_raw[];
    const uint32_t sb = (smem_u32(smem_raw) + 1023u) & ~1023u;

    const int tid = threadIdx.x;
    const int lane = tid & 31;
    const int wid = tid >> 5;
    const int wm = wid & 3;
    const int wn = wid >> 2;
    const int bm = blockIdx.y * 128;
    const int bn = blockIdx.x * 128;

    const __nv_bfloat16* gp[8];
    uint32_t dst[8];
#pragma unroll
    for (int i = 0; i < 8; ++i) {
        const int u = tid + i * 256;
        const int t = u >> 9;
        const int r = (u >> 2) & 127;
        const int s = u & 3;
        const __nv_bfloat16* base = (t == 0) ? ga.Ahi : (t == 1) ? ga.Alo : (t == 2) ? ga.Bhi : ga.Blo;
        const int grow = ((t < 2) ? bm : bn) + r;
        gp[i] = base + (size_t)grow * 1024 + s * 8;
        dst[i] = sb + t * 8192 + swz(r, s);
    }

    uint32_t lmA[2], lmB[4];
    {
        const int rA = wm * 32 + ((lane >> 3) & 1) * 8 + (lane & 7);
        const int sA = lane >> 4;
#pragma unroll
        for (int mt = 0; mt < 2; ++mt) lmA[mt] = sb + swz(rA + mt * 16, sA);
        const int rB = wn * 64 + (lane >> 4) * 8 + (lane & 7);
        const int sB = (lane >> 3) & 1;
#pragma unroll
        for (int ng = 0; ng < 4; ++ng) lmB[ng] = sb + 16384 + swz(rB + ng * 16, sB);
    }

    float acc[2][4][2][4];
#pragma unroll
    for (int mt = 0; mt < 2; ++mt)
#pragma unroll
        for (int ng = 0; ng < 4; ++ng)
#pragma unroll
            for (int h = 0; h < 2; ++h)
#pragma unroll
                for (int j = 0; j < 4; ++j) acc[mt][ng][h][j] = 0.f;

#pragma unroll
    for (int i = 0; i < 8; ++i) cpasync16(dst[i], gp[i]);
    asm volatile("cp.async.commit_group;" ::: "memory");
#pragma unroll
    for (int i = 0; i < 8; ++i) cpasync16(dst[i] + 32768, gp[i] + 32);
    asm volatile("cp.async.commit_group;" ::: "memory");

#pragma unroll 1
    for (int ch = 0; ch < 32; ++ch) {
        if (ch < 31) { asm volatile("cp.async.wait_group 1;" ::: "memory"); }
        else         { asm volatile("cp.async.wait_group 0;" ::: "memory"); }
        __syncthreads();

        if (ch + 2 < 32) {
            const uint32_t sn = (uint32_t)(((ch + 2) % 3) * 32768);
#pragma unroll
            for (int i = 0; i < 8; ++i) cpasync16(dst[i] + sn, gp[i] + (ch + 2) * 32);
            asm volatile("cp.async.commit_group;" ::: "memory");
        }

        const uint32_t so = (uint32_t)((ch % 3) * 32768);
#pragma unroll
        for (int ks = 0; ks < 2; ++ks) {
            const uint32_t kx = (uint32_t)(ks << 5);
            uint32_t ah[2][4], al[2][4];
#pragma unroll
            for (int mt = 0; mt < 2; ++mt) {
                lm4(ah[mt], (lmA[mt] + so) ^ kx);
                lm4(al[mt], (lmA[mt] + 8192 + so) ^ kx);
            }
#pragma unroll
            for (int ngp = 0; ngp < 2; ++ngp) {
                uint32_t bh[2][4], bl[2][4];
#pragma unroll
                for (int g = 0; g < 2; ++g) {
                    const int ng = ngp * 2 + g;
                    lm4(bh[g], (lmB[ng] + so) ^ kx);
                    lm4(bl[g], (lmB[ng] + 8192 + so) ^ kx);
                }
                // term-major passes: same-accumulator MMAs are 8 issues apart
#pragma unroll
                for (int g = 0; g < 2; ++g)
#pragma unroll
                    for (int mt = 0; mt < 2; ++mt)
#pragma unroll
                        for (int h = 0; h < 2; ++h)
                            mma_bf16(acc[mt][ngp * 2 + g][h], ah[mt], bh[g][2 * h], bh[g][2 * h + 1]);
#pragma unroll
                for (int g = 0; g < 2; ++g)
#pragma unroll
                    for (int mt = 0; mt < 2; ++mt)
#pragma unroll
                        for (int h = 0; h < 2; ++h)
                            mma_bf16(acc[mt][ngp * 2 + g][h], al[mt], bh[g][2 * h], bh[g][2 * h + 1]);
#pragma unroll
                for (int g = 0; g < 2; ++g)
#pragma unroll
                    for (int mt = 0; mt < 2; ++mt)
#pragma unroll
                        for (int h = 0; h < 2; ++h)
                            mma_bf16(acc[mt][ngp * 2 + g][h], ah[mt], bl[g][2 * h], bl[g][2 * h + 1]);
            }
        }
    }

#pragma unroll
    for (int mt = 0; mt < 2; ++mt) {
        const int r0 = bm + wm * 32 + mt * 16 + (lane >> 2);
#pragma unroll
        for (int ng = 0; ng < 4; ++ng)
#pragma unroll
            for (int h = 0; h < 2; ++h) {
                const int col = bn + wn * 64 + ng * 16 + h * 8 + 2 * (lane & 3);
                const float2 b2 = *(const float2*)(ga.bias + col);
                const float* a4 = acc[mt][ng][h];
                const float v00 = a4[0] + b2.x, v01 = a4[1] + b2.y;
                const float v10 = a4[2] + b2.x, v11 = a4[3] + b2.y;
                if (ga.mode == 1) {
                    float2 p0; p0.x = v00; p0.y = v01;
                    float2 p1; p1.x = v10; p1.y = v11;
                    *(float2*)((float*)ga.C0 + (size_t)r0 * 1024 + col) = p0;
                    *(float2*)((float*)ga.C0 + (size_t)(r0 + 8) * 1024 + col) = p1;
                } else if (ga.mode == 0) {
                    __nv_bfloat16* hp = (__nv_bfloat16*)ga.C0;
                    __nv_bfloat16* lp = (__nv_bfloat16*)ga.C1;
                    __nv_bfloat162 H0, L0, H1, L1;
                    H0.x = __float2bfloat16(v00); H0.y = __float2bfloat16(v01);
                    L0.x = __float2bfloat16(v00 - __bfloat162float(H0.x));
                    L0.y = __float2bfloat16(v01 - __bfloat162float(H0.y));
                    H1.x = __float2bfloat16(v10); H1.y = __float2bfloat16(v11);
                    L1.x = __float2bfloat16(v10 - __bfloat162float(H1.x));
                    L1.y = __float2bfloat16(v11 - __bfloat162float(H1.y));
                    *(__nv_bfloat162*)(hp + (size_t)r0 * 1024 + col) = H0;
                    *(__nv_bfloat162*)(lp + (size_t)r0 * 1024 + col) = L0;
                    *(__nv_bfloat162*)(hp + (size_t)(r0 + 8) * 1024 + col) = H1;
                    *(__nv_bfloat162*)(lp + (size_t)(r0 + 8) * 1024 + col) = L1;
                } else {
                    __half* hp = (__half*)ga.C0;
                    __half2 H0, H1;
                    H0.x = __float2half_rn(v00); H0.y = __float2half_rn(v01);
                    H1.x = __float2half_rn(v10); H1.y = __float2half_rn(v11);
                    *(__half2*)(hp + (size_t)r0 * 1024 + col) = H0;
                    *(__half2*)(hp + (size_t)(r0 + 8) * 1024 + col) = H1;
                }
            }
    }
}

// ---------------- MMA flash attention (single fp16 Q/K/V) -------------------
// Grid (2, 64, 2): CTA handles (c, b) for 2 q-tiles. K/V staged once (fp16,
// 32KB each), Q per tile (8KB). 1-term QK, 1-term PV, ones-MMA row sums.
#define AK 0u
#define AV 32768u
#define AQ 65536u

__global__ void __launch_bounds__(256, 2)
attention_mma(const __half* __restrict__ q2, const __half* __restrict__ k2,
              const __half* __restrict__ v2,
              __nv_bfloat16* __restrict__ Ohi, __nv_bfloat16* __restrict__ Olo)
{
    extern __shared__ char smraw[];
    const uint32_t sb = smem_u32(smraw);

    const int qp = blockIdx.x;   // q-tile pair
    const int c  = blockIdx.y;
    const int b  = blockIdx.z;
    const int tid = threadIdx.x;
    const int lane = tid & 31;
    const int w = tid >> 5;

    // ---- stage K + V (fp16, 1024x16 each) ----
#pragma unroll
    for (int i = 0; i < 16; ++i) {
        const int u = tid + i * 256;
        const int arr = u >> 11;
        const int rem = u & 2047;
        const int r = rem >> 1;
        const int half = rem & 1;
        const __half* base = arr ? v2 : k2;
        const __half* src = base + ((size_t)((b << 10) + r) << 10) + (c << 4) + (half << 3);
        const uint32_t dstp = sb + (uint32_t)(arr << 15) + (uint32_t)(r * 32 + ((half ^ ((r >> 2) & 1)) << 4));
        cpasync16(dstp, src);
    }
    asm volatile("cp.async.commit_group;" ::: "memory");

    const uint32_t qoff = (uint32_t)((lane & 15) * 32 + ((((lane >> 4) & 1) ^ ((lane >> 2) & 1)) << 4));
    const uint32_t kloff = (uint32_t)(((lane & 7) + ((lane >> 4) << 3)) * 32 +
                                      ((((lane >> 3) & 1) ^ ((lane >> 2) & 1)) << 4));
    const uint32_t vloff = (uint32_t)(((lane & 7) + (((lane >> 3) & 1) << 3)) * 32 +
                                      ((((lane >> 4) & 1) ^ ((lane >> 2) & 1)) << 4));
    const float SCL = 0.25f * 1.4426950408889634f;
    const uint32_t scl2 = packh(SCL, SCL);
    const uint32_t ONES = 0x3C003C00u;

    const int ca = c >> 2, e = c & 3;
    const int tt = 2 * e + b;
    const int b2 = tt >> 2, r2 = tt & 3;

#pragma unroll 1
    for (int it = 0; it < 2; ++it) {
        const int qt = qp * 2 + it;
        // stage Q tile (256x16 fp16)
#pragma unroll
        for (int i = 0; i < 2; ++i) {
            const int u = tid + i * 256;
            const int r = u >> 1;
            const int half = u & 1;
            const __half* src = q2 + ((size_t)((b << 10) + (qt << 8) + r) << 10) + (c << 4) + (half << 3);
            const uint32_t dstp = sb + AQ + (uint32_t)(r * 32 + ((half ^ ((r >> 2) & 1)) << 4));
            cpasync16(dstp, src);
        }
        asm volatile("cp.async.commit_group;" ::: "memory");
        asm volatile("cp.async.wait_group 0;" ::: "memory");
        __syncthreads();

        uint32_t qf[2][4];
#pragma unroll
        for (int mt = 0; mt < 2; ++mt)
            lm4(qf[mt], sb + AQ + (uint32_t)((w * 32 + mt * 16) * 32) + qoff);

        float oac[2][2][4];
        float ls[2][4];
#pragma unroll
        for (int mt = 0; mt < 2; ++mt) {
#pragma unroll
            for (int j = 0; j < 4; ++j) ls[mt][j] = 0.f;
#pragma unroll
            for (int ht = 0; ht < 2; ++ht)
#pragma unroll
                for (int j = 0; j < 4; ++j) oac[mt][ht][j] = 0.f;
        }

#pragma unroll 1
        for (int kb = 0; kb < 16; ++kb) {
            float sc[2][8][4];
#pragma unroll
            for (int mt = 0; mt < 2; ++mt)
#pragma unroll
                for (int j = 0; j < 8; ++j)
#pragma unroll
                    for (int i = 0; i < 4; ++i) sc[mt][j][i] = 0.f;

            // QK^T: single fp16 term; K frags shared across m-tiles
#pragma unroll
            for (int nt = 0; nt < 4; ++nt) {
                const uint32_t s0 = (uint32_t)((kb * 64 + nt * 16) * 32);
                uint32_t kh4[4];
                lm4(kh4, sb + AK + s0 + kloff);
#pragma unroll
                for (int mt = 0; mt < 2; ++mt) {
                    mma_f16(sc[mt][2 * nt], qf[mt], kh4[0], kh4[1]);
                    mma_f16(sc[mt][2 * nt + 1], qf[mt], kh4[2], kh4[3]);
                }
            }

            // P = exp2(sc*SCL) in f16x2; single-V PV; ones-MMA row sums
#pragma unroll
            for (int ks = 0; ks < 4; ++ks) {
                const uint32_t s0 = (uint32_t)((kb * 64 + ks * 16) * 32);
                uint32_t vh4[4];
                lm4t(vh4, sb + AV + s0 + vloff);
#pragma unroll
                for (int mt = 0; mt < 2; ++mt) {
                    uint32_t pa[4];
                    pa[0] = hex2(hmul2(packh(sc[mt][2 * ks][0], sc[mt][2 * ks][1]), scl2));
                    pa[1] = hex2(hmul2(packh(sc[mt][2 * ks][2], sc[mt][2 * ks][3]), scl2));
                    pa[2] = hex2(hmul2(packh(sc[mt][2 * ks + 1][0], sc[mt][2 * ks + 1][1]), scl2));
                    pa[3] = hex2(hmul2(packh(sc[mt][2 * ks + 1][2], sc[mt][2 * ks + 1][3]), scl2));
                    mma_f16(oac[mt][0], pa, vh4[0], vh4[1]);
                    mma_f16(oac[mt][1], pa, vh4[2], vh4[3]);
                    mma_f16(ls[mt], pa, ONES, ONES);
                }
            }
        }

        // epilogue: normalize + permuted split-bf16 store
#pragma unroll
        for (int mt = 0; mt < 2; ++mt) {
            const int s_lo = qt * 256 + w * 32 + mt * 16 + (lane >> 2);
            const float inv_lo = 1.0f / ls[mt][0];
            const float inv_hi = 1.0f / ls[mt][2];
#pragma unroll
            for (int ht = 0; ht < 2; ++ht) {
                const int h0 = ht * 8 + 2 * (lane & 3);
#pragma unroll
                for (int rr = 0; rr < 2; ++rr) {
                    const int s = s_lo + rr * 8;
                    const float inv = rr ? inv_hi : inv_lo;
                    const float v0 = oac[mt][ht][rr * 2 + 0] * inv;
                    const float v1 = oac[mt][ht][rr * 2 + 1] * inv;
                    const int s2 = (r2 << 8) | (s >> 2);
                    const int f = (ca << 6) | ((s & 3) << 4) | h0;
                    const size_t off = (((size_t)b2 << 10) + s2) * 1024 + f;
                    __nv_bfloat162 H, L;
                    H.x = __float2bfloat16(v0); H.y = __float2bfloat16(v1);
                    L.x = __float2bfloat16(v0 - __bfloat162float(H.x));
                    L.y = __float2bfloat16(v1 - __bfloat162float(H.y));
                    *(__nv_bfloat162*)(Ohi + off) = H;
                    *(__nv_bfloat162*)(Olo + off) = L;
                }
            }
        }
        __syncthreads();
    }
}

// ---------------------------------------------------------------------------
extern "C" void kernel_launch(void* const* d_in, const int* in_sizes, int n_in,
                              void* d_out, int out_size)
{
    const float* x    = (const float*)d_in[0];
    const float* wq_w = (const float*)d_in[1];
    const float* wq_b = (const float*)d_in[2];
    const float* wk_w = (const float*)d_in[3];
    const float* wk_b = (const float*)d_in[4];
    const float* wv_w = (const float*)d_in[5];
    const float* wv_b = (const float*)d_in[6];
    const float* vq_w = (const float*)d_in[7];
    const float* vq_b = (const float*)d_in[8];
    const float* vk_w = (const float*)d_in[9];
    const float* vk_b = (const float*)d_in[10];
    const float* vv_w = (const float*)d_in[11];
    const float* vv_b = (const float*)d_in[12];
    const float* wo_b = (const float*)d_in[14];
    float* out = (float*)d_out;

    __nv_bfloat16 *xhi, *xlo, *whi, *wlo, *wThi, *wTlo, *wchi, *wclo;
    __nv_bfloat16 *ophi, *oplo;
    __half *q2f, *k2f, *v2f;
    float *bc, *zb;
    cudaGetSymbolAddress((void**)&xhi, g_xhi);   cudaGetSymbolAddress((void**)&xlo, g_xlo);
    cudaGetSymbolAddress((void**)&whi, g_whi);   cudaGetSymbolAddress((void**)&wlo, g_wlo);
    cudaGetSymbolAddress((void**)&wThi, g_wThi); cudaGetSymbolAddress((void**)&wTlo, g_wTlo);
    cudaGetSymbolAddress((void**)&wchi, g_wchi); cudaGetSymbolAddress((void**)&wclo, g_wclo);
    cudaGetSymbolAddress((void**)&bc, g_bc);     cudaGetSymbolAddress((void**)&zb, g_zb);
    cudaGetSymbolAddress((void**)&q2f, g_q2f);   cudaGetSymbolAddress((void**)&k2f, g_k2f);
    cudaGetSymbolAddress((void**)&v2f, g_v2f);
    cudaGetSymbolAddress((void**)&ophi, g_ophi); cudaGetSymbolAddress((void**)&oplo, g_oplo);

    // 1) splits: x, vq, vk, vv, wo
    SplitArgs sa;
    const float* srcs[5] = {x, vq_w, vk_w, vv_w, (const float*)d_in[13]};
    for (int i = 0; i < 5; ++i) {
        sa.src[i] = srcs[i];
        if (i == 0) { sa.hi[i] = xhi; sa.lo[i] = xlo; sa.n[i] = 2097152; }
        else { sa.hi[i] = whi + (size_t)(i - 1) * 1048576; sa.lo[i] = wlo + (size_t)(i - 1) * 1048576; sa.n[i] = 1048576; }
    }
    split5<<<dim3(2048, 1, 5), 256>>>(sa);

    // 2) transpose-splits: wq, wk, wv
    wsplitT<<<dim3(32, 32, 3), 256>>>(wq_w, wk_w, wv_w, wThi, wTlo);

    // 3) combined biases
    bias_combine<<<dim3(128, 1, 3), 256>>>(vq_w, wq_b, vq_b, vk_w, wk_b, vk_b, vv_w, wv_b, vv_b, bc);

    const int gemm_smem = 3 * 32768 + 1024;
    cudaFuncSetAttribute(gemm_mma, cudaFuncAttributeMaxDynamicSharedMemorySize, gemm_smem);

    // 4) weight combine: Wc = Vq @ Wq (M=1024), split bf16 out
    GemmArgs a0{}, a1{}, a2{};
    a0 = {whi + 0, wlo + 0, wThi + 0, wTlo + 0, zb, wchi + 0, wclo + 0, 0};
    a1 = {whi + 1048576, wlo + 1048576, wThi + 1048576, wTlo + 1048576, zb, wchi + 1048576, wclo + 1048576, 0};
    a2 = {whi + 2097152, wlo + 2097152, wThi + 2097152, wTlo + 2097152, zb, wchi + 2097152, wclo + 2097152, 0};
    gemm_mma<<<dim3(8, 8, 3), 256, gemm_smem>>>(a0, a1, a2);

    // 5) data GEMMs: q2/k2/v2 as single fp16
    a0 = {xhi, xlo, wchi + 0, wclo + 0, bc + 0, q2f, nullptr, 2};
    a1 = {xhi, xlo, wchi + 1048576, wclo + 1048576, bc + 1024, k2f, nullptr, 2};
    a2 = {xhi, xlo, wchi + 2097152, wclo + 2097152, bc + 2048, v2f, nullptr, 2};
    gemm_mma<<<dim3(8, 16, 3), 256, gemm_smem>>>(a0, a1, a2);

    // 6) attention
    const int attn_smem = 73728;
    cudaFuncSetAttribute(attention_mma, cudaFuncAttributeMaxDynamicSharedMemorySize, attn_smem);
    attention_mma<<<dim3(2, 64, 2), 256, attn_smem>>>(q2f, k2f, v2f, ophi, oplo);

    // 7) final projection
    a0 = {ophi, oplo, whi + 3145728, wlo + 3145728, wo_b, out, nullptr, 1};
    gemm_mma<<<dim3(8, 16, 1), 256, gemm_smem>>>(a0, a0, a0);
}

// round 8
// speedup vs baseline: 4.5178x; 1.2904x over previous
#include <cuda_runtime.h>
#include <cuda_bf16.h>
#include <cuda_fp16.h>
#include <cstdint>
#include <math.h>

// ===========================================================================
// Round 8: HMMA work reduction. All-fp16 split precision:
//  - wcomb & data GEMMs: 2-term (A hi/lo fp16 x B single fp16)  [-33% MMAs]
//  - final GEMM: 3-term fp16 hi/lo (same cost as before, more accurate)
//  - attention unchanged (single-fp16 MMA flash, occ 2)
// ===========================================================================

__device__ __forceinline__ uint32_t smem_u32(const void* p) {
    uint32_t a;
    asm("{ .reg .u64 t; cvta.to.shared.u64 t, %1; cvt.u32.u64 %0, t; }" : "=r"(a) : "l"(p));
    return a;
}
__device__ __forceinline__ void lm4(uint32_t* r, uint32_t a) {
    asm volatile("ldmatrix.sync.aligned.m8n8.x4.shared.b16 {%0,%1,%2,%3}, [%4];"
        : "=r"(r[0]), "=r"(r[1]), "=r"(r[2]), "=r"(r[3]) : "r"(a));
}
__device__ __forceinline__ void lm4t(uint32_t* r, uint32_t a) {
    asm volatile("ldmatrix.sync.aligned.m8n8.x4.trans.shared.b16 {%0,%1,%2,%3}, [%4];"
        : "=r"(r[0]), "=r"(r[1]), "=r"(r[2]), "=r"(r[3]) : "r"(a));
}
__device__ __forceinline__ void mma_f16(float* d, const uint32_t* a, uint32_t b0, uint32_t b1) {
    asm volatile("mma.sync.aligned.m16n8k16.row.col.f32.f16.f16.f32 "
        "{%0,%1,%2,%3}, {%4,%5,%6,%7}, {%8,%9}, {%0,%1,%2,%3};"
        : "+f"(d[0]), "+f"(d[1]), "+f"(d[2]), "+f"(d[3])
        : "r"(a[0]), "r"(a[1]), "r"(a[2]), "r"(a[3]), "r"(b0), "r"(b1));
}
__device__ __forceinline__ void cpasync16(uint32_t dst, const void* src) {
    asm volatile("cp.async.cg.shared.global [%0], [%1], 16;" :: "r"(dst), "l"(src));
}
__device__ __forceinline__ uint32_t packh(float lo, float hi) {
    uint32_t d;
    asm("cvt.rn.f16x2.f32 %0, %1, %2;" : "=r"(d) : "f"(hi), "f"(lo));
    return d;
}
__device__ __forceinline__ uint32_t hmul2(uint32_t a, uint32_t b) {
    uint32_t d; asm("mul.rn.f16x2 %0, %1, %2;" : "=r"(d) : "r"(a), "r"(b)); return d;
}
__device__ __forceinline__ uint32_t hex2(uint32_t a) {
    uint32_t d; asm("ex2.approx.f16x2 %0, %1;" : "=r"(d) : "r"(a)); return d;
}

// ---------------- scratch (device globals) ---------------------------------
__device__ __half g_xh[2097152], g_xl[2097152];
__device__ __half g_wh[4194304], g_wl[4194304];   // vq,vk,vv,wo hi/lo
__device__ __half g_wT[3145728];                  // wq,wk,wv transposed, single
__device__ __half g_wc[3145728];                  // combined weights, single
__device__ float g_bc[3072];                      // combined biases
__device__ float g_zb[1024];                      // zero bias (.bss)
__device__ __half g_q2f[2097152], g_k2f[2097152], g_v2f[2097152];
__device__ __half g_oh[2097152], g_ol[2097152];

// ---------------- split fp32 -> fp16 hi/lo (x, vq, vk, vv, wo) --------------
struct SplitArgs {
    const float* src[5];
    __half* hi[5];
    __half* lo[5];
    int n[5];
};

__global__ void __launch_bounds__(256) split5(SplitArgs a) {
    const int z = blockIdx.z;
    const int i = (blockIdx.x * 256 + threadIdx.x) * 4;
    if (i >= a.n[z]) return;
    const float4 v = *(const float4*)(a.src[z] + i);
    __half h0 = __float2half_rn(v.x), h1 = __float2half_rn(v.y);
    __half h2 = __float2half_rn(v.z), h3 = __float2half_rn(v.w);
    __half2 H0; H0.x = h0; H0.y = h1;
    __half2 H1; H1.x = h2; H1.y = h3;
    __half2 L0; L0.x = __float2half_rn(v.x - __half2float(h0));
    L0.y = __float2half_rn(v.y - __half2float(h1));
    __half2 L1; L1.x = __float2half_rn(v.z - __half2float(h2));
    L1.y = __float2half_rn(v.w - __half2float(h3));
    *(__half2*)(a.hi[z] + i) = H0;
    *(__half2*)(a.hi[z] + i + 2) = H1;
    *(__half2*)(a.lo[z] + i) = L0;
    *(__half2*)(a.lo[z] + i + 2) = L1;
}

// ---------------- transpose to single fp16 (wq, wk, wv) ---------------------
__global__ void __launch_bounds__(256)
wsplitT(const float* W0, const float* W1, const float* W2, __half* hiT)
{
    const int z = blockIdx.z;
    const float* W = (z == 0) ? W0 : (z == 1) ? W1 : W2;
    __half* ho = hiT + (size_t)z * 1048576;

    __shared__ float s[32][33];
    const int tx = threadIdx.x & 31;
    const int ty = threadIdx.x >> 5;
    const int k0 = blockIdx.x * 32;
    const int m0 = blockIdx.y * 32;
#pragma unroll
    for (int j = 0; j < 4; ++j)
        s[ty + j * 8][tx] = W[(size_t)(m0 + ty + j * 8) * 1024 + k0 + tx];
    __syncthreads();
#pragma unroll
    for (int j = 0; j < 4; ++j)
        ho[(size_t)(k0 + ty + j * 8) * 1024 + m0 + tx] = __float2half_rn(s[tx][ty + j * 8]);
}

// ---------------- combined bias: bc[n] = V[n,:].b + vb[n] -------------------
__global__ void __launch_bounds__(256)
bias_combine(const float* V0, const float* b0, const float* c0,
             const float* V1, const float* b1, const float* c1,
             const float* V2, const float* b2, const float* c2,
             float* bc)
{
    const int z = blockIdx.z;
    const float* V = (z == 0) ? V0 : (z == 1) ? V1 : V2;
    const float* b = (z == 0) ? b0 : (z == 1) ? b1 : b2;
    const float* c = (z == 0) ? c0 : (z == 1) ? c1 : c2;
    const int lane = threadIdx.x & 31;
    const int w = threadIdx.x >> 5;
    const int n = blockIdx.x * 8 + w;
    float s = 0.f;
#pragma unroll
    for (int it = 0; it < 8; ++it) {
        const int k = (it * 32 + lane) * 4;
        const float4 vv = *(const float4*)(V + (size_t)n * 1024 + k);
        const float4 bb = *(const float4*)(b + k);
        s += vv.x * bb.x + vv.y * bb.y + vv.z * bb.z + vv.w * bb.w;
    }
#pragma unroll
    for (int o = 16; o > 0; o >>= 1) s += __shfl_xor_sync(0xffffffffu, s, o);
    if (lane == 0) bc[z * 1024 + n] = s + c[n];
}

// ---------------- mma.sync GEMM, templated term count -----------------------
// NT=2: C = (Ah+Al)*B (3 smem tiles). NT=3: C = Ah*Bh + Al*Bh + Ah*Bl (4 tiles)
// mode 1: fp32 out; mode 2: fp16 single out. Both add fp32 bias.
struct GemmArgs {
    const __half *Ahi, *Alo, *Bhi, *Blo;
    const float* bias;
    void* C0;
    int mode;
};

__device__ __forceinline__ uint32_t swz(int r, int s) {
    return (uint32_t)(r * 64 + ((s ^ ((r >> 1) & 3)) << 4));
}

template<int NT>
__global__ void __launch_bounds__(256, 2)
gemm_mma(GemmArgs g0, GemmArgs g1, GemmArgs g2)
{
    constexpr int T = NT + 1;                 // smem tiles per stage
    constexpr uint32_t SS = (uint32_t)T * 8192u;  // stage stride

    const GemmArgs ga = (blockIdx.z == 0) ? g0 : (blockIdx.z == 1) ? g1 : g2;
    extern __shared__ char smem_raw[];
    const uint32_t sb = (smem_u32(smem_raw) + 1023u) & ~1023u;

    const int tid = threadIdx.x;
    const int lane = tid & 31;
    const int wid = tid >> 5;
    const int wm = wid & 3;
    const int wn = wid >> 2;
    const int bm = blockIdx.y * 128;
    const int bn = blockIdx.x * 128;

    const __half* bases[4] = {ga.Ahi, ga.Alo, ga.Bhi, ga.Blo};
    const __half* gp[2 * T];
    uint32_t dst[2 * T];
#pragma unroll
    for (int i = 0; i < 2 * T; ++i) {
        const int u = tid + i * 256;
        const int t = u >> 9;
        const int r = (u >> 2) & 127;
        const int s = u & 3;
        const int grow = ((t < 2) ? bm : bn) + r;
        gp[i] = bases[t] + (size_t)grow * 1024 + s * 8;
        dst[i] = sb + t * 8192 + swz(r, s);
    }

    uint32_t lmA[2], lmB[4];
    {
        const int rA = wm * 32 + ((lane >> 3) & 1) * 8 + (lane & 7);
        const int sA = lane >> 4;
#pragma unroll
        for (int mt = 0; mt < 2; ++mt) lmA[mt] = sb + swz(rA + mt * 16, sA);
        const int rB = wn * 64 + (lane >> 4) * 8 + (lane & 7);
        const int sB = (lane >> 3) & 1;
#pragma unroll
        for (int ng = 0; ng < 4; ++ng) lmB[ng] = sb + 16384 + swz(rB + ng * 16, sB);
    }

    float acc[2][4][2][4];
#pragma unroll
    for (int mt = 0; mt < 2; ++mt)
#pragma unroll
        for (int ng = 0; ng < 4; ++ng)
#pragma unroll
            for (int h = 0; h < 2; ++h)
#pragma unroll
                for (int j = 0; j < 4; ++j) acc[mt][ng][h][j] = 0.f;

#pragma unroll
    for (int i = 0; i < 2 * T; ++i) cpasync16(dst[i], gp[i]);
    asm volatile("cp.async.commit_group;" ::: "memory");
#pragma unroll
    for (int i = 0; i < 2 * T; ++i) cpasync16(dst[i] + SS, gp[i] + 32);
    asm volatile("cp.async.commit_group;" ::: "memory");

#pragma unroll 1
    for (int ch = 0; ch < 32; ++ch) {
        if (ch < 31) { asm volatile("cp.async.wait_group 1;" ::: "memory"); }
        else         { asm volatile("cp.async.wait_group 0;" ::: "memory"); }
        __syncthreads();

        if (ch + 2 < 32) {
            const uint32_t sn = (uint32_t)(((ch + 2) % 3)) * SS;
#pragma unroll
            for (int i = 0; i < 2 * T; ++i) cpasync16(dst[i] + sn, gp[i] + (ch + 2) * 32);
            asm volatile("cp.async.commit_group;" ::: "memory");
        }

        const uint32_t so = (uint32_t)(ch % 3) * SS;
#pragma unroll
        for (int ks = 0; ks < 2; ++ks) {
            const uint32_t kx = (uint32_t)(ks << 5);
            uint32_t ah[2][4], al[2][4];
#pragma unroll
            for (int mt = 0; mt < 2; ++mt) {
                lm4(ah[mt], (lmA[mt] + so) ^ kx);
                lm4(al[mt], (lmA[mt] + 8192 + so) ^ kx);
            }
#pragma unroll
            for (int ngp = 0; ngp < 2; ++ngp) {
                uint32_t bh[2][4];
#pragma unroll
                for (int g = 0; g < 2; ++g)
                    lm4(bh[g], (lmB[ngp * 2 + g] + so) ^ kx);

#pragma unroll
                for (int g = 0; g < 2; ++g)
#pragma unroll
                    for (int mt = 0; mt < 2; ++mt)
#pragma unroll
                        for (int h = 0; h < 2; ++h)
                            mma_f16(acc[mt][ngp * 2 + g][h], ah[mt], bh[g][2 * h], bh[g][2 * h + 1]);
#pragma unroll
                for (int g = 0; g < 2; ++g)
#pragma unroll
                    for (int mt = 0; mt < 2; ++mt)
#pragma unroll
                        for (int h = 0; h < 2; ++h)
                            mma_f16(acc[mt][ngp * 2 + g][h], al[mt], bh[g][2 * h], bh[g][2 * h + 1]);

                if (NT == 3) {
                    uint32_t bl[2][4];
#pragma unroll
                    for (int g = 0; g < 2; ++g)
                        lm4(bl[g], (lmB[ngp * 2 + g] + 8192 + so) ^ kx);
#pragma unroll
                    for (int g = 0; g < 2; ++g)
#pragma unroll
                        for (int mt = 0; mt < 2; ++mt)
#pragma unroll
                            for (int h = 0; h < 2; ++h)
                                mma_f16(acc[mt][ngp * 2 + g][h], ah[mt], bl[g][2 * h], bl[g][2 * h + 1]);
                }
            }
        }
    }

#pragma unroll
    for (int mt = 0; mt < 2; ++mt) {
        const int r0 = bm + wm * 32 + mt * 16 + (lane >> 2);
#pragma unroll
        for (int ng = 0; ng < 4; ++ng)
#pragma unroll
            for (int h = 0; h < 2; ++h) {
                const int col = bn + wn * 64 + ng * 16 + h * 8 + 2 * (lane & 3);
                const float2 b2 = *(const float2*)(ga.bias + col);
                const float* a4 = acc[mt][ng][h];
                const float v00 = a4[0] + b2.x, v01 = a4[1] + b2.y;
                const float v10 = a4[2] + b2.x, v11 = a4[3] + b2.y;
                if (ga.mode == 1) {
                    float2 p0; p0.x = v00; p0.y = v01;
                    float2 p1; p1.x = v10; p1.y = v11;
                    *(float2*)((float*)ga.C0 + (size_t)r0 * 1024 + col) = p0;
                    *(float2*)((float*)ga.C0 + (size_t)(r0 + 8) * 1024 + col) = p1;
                } else {
                    __half* hp = (__half*)ga.C0;
                    __half2 H0, H1;
                    H0.x = __float2half_rn(v00); H0.y = __float2half_rn(v01);
                    H1.x = __float2half_rn(v10); H1.y = __float2half_rn(v11);
                    *(__half2*)(hp + (size_t)r0 * 1024 + col) = H0;
                    *(__half2*)(hp + (size_t)(r0 + 8) * 1024 + col) = H1;
                }
            }
    }
}

// ---------------- MMA flash attention (single fp16 Q/K/V) -------------------
#define AK 0u
#define AV 32768u
#define AQ 65536u

__global__ void __launch_bounds__(256, 2)
attention_mma(const __half* __restrict__ q2, const __half* __restrict__ k2,
              const __half* __restrict__ v2,
              __half* __restrict__ Oh, __half* __restrict__ Ol)
{
    extern __shared__ char smraw[];
    const uint32_t sb = smem_u32(smraw);

    const int qp = blockIdx.x;
    const int c  = blockIdx.y;
    const int b  = blockIdx.z;
    const int tid = threadIdx.x;
    const int lane = tid & 31;
    const int w = tid >> 5;

#pragma unroll
    for (int i = 0; i < 16; ++i) {
        const int u = tid + i * 256;
        const int arr = u >> 11;
        const int rem = u & 2047;
        const int r = rem >> 1;
        const int half = rem & 1;
        const __half* base = arr ? v2 : k2;
        const __half* src = base + ((size_t)((b << 10) + r) << 10) + (c << 4) + (half << 3);
        const uint32_t dstp = sb + (uint32_t)(arr << 15) + (uint32_t)(r * 32 + ((half ^ ((r >> 2) & 1)) << 4));
        cpasync16(dstp, src);
    }
    asm volatile("cp.async.commit_group;" ::: "memory");

    const uint32_t qoff = (uint32_t)((lane & 15) * 32 + ((((lane >> 4) & 1) ^ ((lane >> 2) & 1)) << 4));
    const uint32_t kloff = (uint32_t)(((lane & 7) + ((lane >> 4) << 3)) * 32 +
                                      ((((lane >> 3) & 1) ^ ((lane >> 2) & 1)) << 4));
    const uint32_t vloff = (uint32_t)(((lane & 7) + (((lane >> 3) & 1) << 3)) * 32 +
                                      ((((lane >> 4) & 1) ^ ((lane >> 2) & 1)) << 4));
    const float SCL = 0.25f * 1.4426950408889634f;
    const uint32_t scl2 = packh(SCL, SCL);
    const uint32_t ONES = 0x3C003C00u;

    const int ca = c >> 2, e = c & 3;
    const int tt = 2 * e + b;
    const int b2 = tt >> 2, r2 = tt & 3;

#pragma unroll 1
    for (int it = 0; it < 2; ++it) {
        const int qt = qp * 2 + it;
#pragma unroll
        for (int i = 0; i < 2; ++i) {
            const int u = tid + i * 256;
            const int r = u >> 1;
            const int half = u & 1;
            const __half* src = q2 + ((size_t)((b << 10) + (qt << 8) + r) << 10) + (c << 4) + (half << 3);
            const uint32_t dstp = sb + AQ + (uint32_t)(r * 32 + ((half ^ ((r >> 2) & 1)) << 4));
            cpasync16(dstp, src);
        }
        asm volatile("cp.async.commit_group;" ::: "memory");
        asm volatile("cp.async.wait_group 0;" ::: "memory");
        __syncthreads();

        uint32_t qf[2][4];
#pragma unroll
        for (int mt = 0; mt < 2; ++mt)
            lm4(qf[mt], sb + AQ + (uint32_t)((w * 32 + mt * 16) * 32) + qoff);

        float oac[2][2][4];
        float ls[2][4];
#pragma unroll
        for (int mt = 0; mt < 2; ++mt) {
#pragma unroll
            for (int j = 0; j < 4; ++j) ls[mt][j] = 0.f;
#pragma unroll
            for (int ht = 0; ht < 2; ++ht)
#pragma unroll
                for (int j = 0; j < 4; ++j) oac[mt][ht][j] = 0.f;
        }

#pragma unroll 1
        for (int kb = 0; kb < 16; ++kb) {
            float sc[2][8][4];
#pragma unroll
            for (int mt = 0; mt < 2; ++mt)
#pragma unroll
                for (int j = 0; j < 8; ++j)
#pragma unroll
                    for (int i = 0; i < 4; ++i) sc[mt][j][i] = 0.f;

#pragma unroll
            for (int nt = 0; nt < 4; ++nt) {
                const uint32_t s0 = (uint32_t)((kb * 64 + nt * 16) * 32);
                uint32_t kh4[4];
                lm4(kh4, sb + AK + s0 + kloff);
#pragma unroll
                for (int mt = 0; mt < 2; ++mt) {
                    mma_f16(sc[mt][2 * nt], qf[mt], kh4[0], kh4[1]);
                    mma_f16(sc[mt][2 * nt + 1], qf[mt], kh4[2], kh4[3]);
                }
            }

#pragma unroll
            for (int ks = 0; ks < 4; ++ks) {
                const uint32_t s0 = (uint32_t)((kb * 64 + ks * 16) * 32);
                uint32_t vh4[4];
                lm4t(vh4, sb + AV + s0 + vloff);
#pragma unroll
                for (int mt = 0; mt < 2; ++mt) {
                    uint32_t pa[4];
                    pa[0] = hex2(hmul2(packh(sc[mt][2 * ks][0], sc[mt][2 * ks][1]), scl2));
                    pa[1] = hex2(hmul2(packh(sc[mt][2 * ks][2], sc[mt][2 * ks][3]), scl2));
                    pa[2] = hex2(hmul2(packh(sc[mt][2 * ks + 1][0], sc[mt][2 * ks + 1][1]), scl2));
                    pa[3] = hex2(hmul2(packh(sc[mt][2 * ks + 1][2], sc[mt][2 * ks + 1][3]), scl2));
                    mma_f16(oac[mt][0], pa, vh4[0], vh4[1]);
                    mma_f16(oac[mt][1], pa, vh4[2], vh4[3]);
                    mma_f16(ls[mt], pa, ONES, ONES);
                }
            }
        }

        // epilogue: normalize + permuted split-fp16 store
#pragma unroll
        for (int mt = 0; mt < 2; ++mt) {
            const int s_lo = qt * 256 + w * 32 + mt * 16 + (lane >> 2);
            const float inv_lo = 1.0f / ls[mt][0];
            const float inv_hi = 1.0f / ls[mt][2];
#pragma unroll
            for (int ht = 0; ht < 2; ++ht) {
                const int h0 = ht * 8 + 2 * (lane & 3);
#pragma unroll
                for (int rr = 0; rr < 2; ++rr) {
                    const int s = s_lo + rr * 8;
                    const float inv = rr ? inv_hi : inv_lo;
                    const float v0 = oac[mt][ht][rr * 2 + 0] * inv;
                    const float v1 = oac[mt][ht][rr * 2 + 1] * inv;
                    const int s2 = (r2 << 8) | (s >> 2);
                    const int f = (ca << 6) | ((s & 3) << 4) | h0;
                    const size_t off = (((size_t)b2 << 10) + s2) * 1024 + f;
                    __half2 H, L;
                    H.x = __float2half_rn(v0); H.y = __float2half_rn(v1);
                    L.x = __float2half_rn(v0 - __half2float(H.x));
                    L.y = __float2half_rn(v1 - __half2float(H.y));
                    *(__half2*)(Oh + off) = H;
                    *(__half2*)(Ol + off) = L;
                }
            }
        }
        __syncthreads();
    }
}

// ---------------------------------------------------------------------------
extern "C" void kernel_launch(void* const* d_in, const int* in_sizes, int n_in,
                              void* d_out, int out_size)
{
    const float* x    = (const float*)d_in[0];
    const float* wq_w = (const float*)d_in[1];
    const float* wq_b = (const float*)d_in[2];
    const float* wk_w = (const float*)d_in[3];
    const float* wk_b = (const float*)d_in[4];
    const float* wv_w = (const float*)d_in[5];
    const float* wv_b = (const float*)d_in[6];
    const float* vq_w = (const float*)d_in[7];
    const float* vq_b = (const float*)d_in[8];
    const float* vk_w = (const float*)d_in[9];
    const float* vk_b = (const float*)d_in[10];
    const float* vv_w = (const float*)d_in[11];
    const float* vv_b = (const float*)d_in[12];
    const float* wo_b = (const float*)d_in[14];
    float* out = (float*)d_out;

    __half *xh, *xl, *wh, *wl, *wT, *wc, *q2f, *k2f, *v2f, *oh, *ol;
    float *bc, *zb;
    cudaGetSymbolAddress((void**)&xh, g_xh);   cudaGetSymbolAddress((void**)&xl, g_xl);
    cudaGetSymbolAddress((void**)&wh, g_wh);   cudaGetSymbolAddress((void**)&wl, g_wl);
    cudaGetSymbolAddress((void**)&wT, g_wT);   cudaGetSymbolAddress((void**)&wc, g_wc);
    cudaGetSymbolAddress((void**)&bc, g_bc);   cudaGetSymbolAddress((void**)&zb, g_zb);
    cudaGetSymbolAddress((void**)&q2f, g_q2f); cudaGetSymbolAddress((void**)&k2f, g_k2f);
    cudaGetSymbolAddress((void**)&v2f, g_v2f);
    cudaGetSymbolAddress((void**)&oh, g_oh);   cudaGetSymbolAddress((void**)&ol, g_ol);

    // 1) splits: x, vq, vk, vv, wo  -> fp16 hi/lo
    SplitArgs sa;
    const float* srcs[5] = {x, vq_w, vk_w, vv_w, (const float*)d_in[13]};
    for (int i = 0; i < 5; ++i) {
        sa.src[i] = srcs[i];
        if (i == 0) { sa.hi[i] = xh; sa.lo[i] = xl; sa.n[i] = 2097152; }
        else { sa.hi[i] = wh + (size_t)(i - 1) * 1048576; sa.lo[i] = wl + (size_t)(i - 1) * 1048576; sa.n[i] = 1048576; }
    }
    split5<<<dim3(2048, 1, 5), 256>>>(sa);

    // 2) transpose wq, wk, wv -> single fp16
    wsplitT<<<dim3(32, 32, 3), 256>>>(wq_w, wk_w, wv_w, wT);

    // 3) combined biases
    bias_combine<<<dim3(128, 1, 3), 256>>>(vq_w, wq_b, vq_b, vk_w, wk_b, vk_b, vv_w, wv_b, vv_b, bc);

    const int smem2 = 3 * 24576 + 1024;
    const int smem3 = 3 * 32768 + 1024;
    cudaFuncSetAttribute(gemm_mma<2>, cudaFuncAttributeMaxDynamicSharedMemorySize, smem2);
    cudaFuncSetAttribute(gemm_mma<3>, cudaFuncAttributeMaxDynamicSharedMemorySize, smem3);

    // 4) weight combine: Wc = Vq @ Wq (2-term fp16), single fp16 out
    GemmArgs a0{}, a1{}, a2{};
    a0 = {wh + 0, wl + 0, wT + 0, nullptr, zb, wc + 0, 2};
    a1 = {wh + 1048576, wl + 1048576, wT + 1048576, nullptr, zb, wc + 1048576, 2};
    a2 = {wh + 2097152, wl + 2097152, wT + 2097152, nullptr, zb, wc + 2097152, 2};
    gemm_mma<2><<<dim3(8, 8, 3), 256, smem2>>>(a0, a1, a2);

    // 5) data GEMMs: q2/k2/v2 single fp16 (2-term)
    a0 = {xh, xl, wc + 0, nullptr, bc + 0, q2f, 2};
    a1 = {xh, xl, wc + 1048576, nullptr, bc + 1024, k2f, 2};
    a2 = {xh, xl, wc + 2097152, nullptr, bc + 2048, v2f, 2};
    gemm_mma<2><<<dim3(8, 16, 3), 256, smem2>>>(a0, a1, a2);

    // 6) attention -> o fp16 hi/lo, permuted
    const int attn_smem = 73728;
    cudaFuncSetAttribute(attention_mma, cudaFuncAttributeMaxDynamicSharedMemorySize, attn_smem);
    attention_mma<<<dim3(2, 64, 2), 256, attn_smem>>>(q2f, k2f, v2f, oh, ol);

    // 7) final projection (3-term fp16), fp32 out
    a0 = {oh, ol, wh + 3145728, wl + 3145728, wo_b, out, 1};
    gemm_mma<3><<<dim3(8, 16, 1), 256, smem3>>>(a0, a0, a0);
}

// round 9
// speedup vs baseline: 5.2770x; 1.1680x over previous
#include <cuda_runtime.h>
#include <cuda_fp16.h>
#include <cstdint>
#include <math.h>

// ===========================================================================
// Round 9: drop GEMM terms that are below output quantization.
//  - wcomb & data GEMMs: 1-term fp16 (outputs are fp16 -> lo-terms were noise)
//  - final GEMM: 3-term fp16 hi/lo (output is the measured fp32 result)
//  - attention unchanged (single-fp16 MMA flash, occ 2)
// ===========================================================================

__device__ __forceinline__ uint32_t smem_u32(const void* p) {
    uint32_t a;
    asm("{ .reg .u64 t; cvta.to.shared.u64 t, %1; cvt.u32.u64 %0, t; }" : "=r"(a) : "l"(p));
    return a;
}
__device__ __forceinline__ void lm4(uint32_t* r, uint32_t a) {
    asm volatile("ldmatrix.sync.aligned.m8n8.x4.shared.b16 {%0,%1,%2,%3}, [%4];"
        : "=r"(r[0]), "=r"(r[1]), "=r"(r[2]), "=r"(r[3]) : "r"(a));
}
__device__ __forceinline__ void lm4t(uint32_t* r, uint32_t a) {
    asm volatile("ldmatrix.sync.aligned.m8n8.x4.trans.shared.b16 {%0,%1,%2,%3}, [%4];"
        : "=r"(r[0]), "=r"(r[1]), "=r"(r[2]), "=r"(r[3]) : "r"(a));
}
__device__ __forceinline__ void mma_f16(float* d, const uint32_t* a, uint32_t b0, uint32_t b1) {
    asm volatile("mma.sync.aligned.m16n8k16.row.col.f32.f16.f16.f32 "
        "{%0,%1,%2,%3}, {%4,%5,%6,%7}, {%8,%9}, {%0,%1,%2,%3};"
        : "+f"(d[0]), "+f"(d[1]), "+f"(d[2]), "+f"(d[3])
        : "r"(a[0]), "r"(a[1]), "r"(a[2]), "r"(a[3]), "r"(b0), "r"(b1));
}
__device__ __forceinline__ void cpasync16(uint32_t dst, const void* src) {
    asm volatile("cp.async.cg.shared.global [%0], [%1], 16;" :: "r"(dst), "l"(src));
}
__device__ __forceinline__ uint32_t packh(float lo, float hi) {
    uint32_t d;
    asm("cvt.rn.f16x2.f32 %0, %1, %2;" : "=r"(d) : "f"(hi), "f"(lo));
    return d;
}
__device__ __forceinline__ uint32_t hmul2(uint32_t a, uint32_t b) {
    uint32_t d; asm("mul.rn.f16x2 %0, %1, %2;" : "=r"(d) : "r"(a), "r"(b)); return d;
}
__device__ __forceinline__ uint32_t hex2(uint32_t a) {
    uint32_t d; asm("ex2.approx.f16x2 %0, %1;" : "=r"(d) : "r"(a)); return d;
}

// ---------------- scratch (device globals) ---------------------------------
__device__ __half g_xh[2097152];                  // x single fp16
__device__ __half g_ws[3145728];                  // vq,vk,vv single fp16
__device__ __half g_woh[1048576], g_wol[1048576]; // wo hi/lo
__device__ __half g_wT[3145728];                  // wq,wk,wv transposed, single
__device__ __half g_wc[3145728];                  // combined weights, single
__device__ float g_bc[3072];                      // combined biases
__device__ float g_zb[1024];                      // zero bias (.bss)
__device__ __half g_q2f[2097152], g_k2f[2097152], g_v2f[2097152];
__device__ __half g_oh[2097152], g_ol[2097152];

// ---------------- fp32 -> fp16 single convert (x, vq, vk, vv) ---------------
struct CvtArgs {
    const float* src[4];
    __half* dst[4];
    int n[4];
};

__global__ void __launch_bounds__(256) cvt4(CvtArgs a) {
    const int z = blockIdx.z;
    const int i = (blockIdx.x * 256 + threadIdx.x) * 4;
    if (i >= a.n[z]) return;
    const float4 v = *(const float4*)(a.src[z] + i);
    __half2 H0; H0.x = __float2half_rn(v.x); H0.y = __float2half_rn(v.y);
    __half2 H1; H1.x = __float2half_rn(v.z); H1.y = __float2half_rn(v.w);
    *(__half2*)(a.dst[z] + i) = H0;
    *(__half2*)(a.dst[z] + i + 2) = H1;
}

// ---------------- fp32 -> fp16 hi/lo split (wo) ------------------------------
__global__ void __launch_bounds__(256)
split1(const float* __restrict__ src, __half* __restrict__ hi, __half* __restrict__ lo) {
    const int i = (blockIdx.x * 256 + threadIdx.x) * 4;
    const float4 v = *(const float4*)(src + i);
    __half h0 = __float2half_rn(v.x), h1 = __float2half_rn(v.y);
    __half h2 = __float2half_rn(v.z), h3 = __float2half_rn(v.w);
    __half2 H0; H0.x = h0; H0.y = h1;
    __half2 H1; H1.x = h2; H1.y = h3;
    __half2 L0; L0.x = __float2half_rn(v.x - __half2float(h0));
    L0.y = __float2half_rn(v.y - __half2float(h1));
    __half2 L1; L1.x = __float2half_rn(v.z - __half2float(h2));
    L1.y = __float2half_rn(v.w - __half2float(h3));
    *(__half2*)(hi + i) = H0;
    *(__half2*)(hi + i + 2) = H1;
    *(__half2*)(lo + i) = L0;
    *(__half2*)(lo + i + 2) = L1;
}

// ---------------- transpose to single fp16 (wq, wk, wv) ---------------------
__global__ void __launch_bounds__(256)
wsplitT(const float* W0, const float* W1, const float* W2, __half* hiT)
{
    const int z = blockIdx.z;
    const float* W = (z == 0) ? W0 : (z == 1) ? W1 : W2;
    __half* ho = hiT + (size_t)z * 1048576;

    __shared__ float s[32][33];
    const int tx = threadIdx.x & 31;
    const int ty = threadIdx.x >> 5;
    const int k0 = blockIdx.x * 32;
    const int m0 = blockIdx.y * 32;
#pragma unroll
    for (int j = 0; j < 4; ++j)
        s[ty + j * 8][tx] = W[(size_t)(m0 + ty + j * 8) * 1024 + k0 + tx];
    __syncthreads();
#pragma unroll
    for (int j = 0; j < 4; ++j)
        ho[(size_t)(k0 + ty + j * 8) * 1024 + m0 + tx] = __float2half_rn(s[tx][ty + j * 8]);
}

// ---------------- combined bias: bc[n] = V[n,:].b + vb[n] -------------------
__global__ void __launch_bounds__(256)
bias_combine(const float* V0, const float* b0, const float* c0,
             const float* V1, const float* b1, const float* c1,
             const float* V2, const float* b2, const float* c2,
             float* bc)
{
    const int z = blockIdx.z;
    const float* V = (z == 0) ? V0 : (z == 1) ? V1 : V2;
    const float* b = (z == 0) ? b0 : (z == 1) ? b1 : b2;
    const float* c = (z == 0) ? c0 : (z == 1) ? c1 : c2;
    const int lane = threadIdx.x & 31;
    const int w = threadIdx.x >> 5;
    const int n = blockIdx.x * 8 + w;
    float s = 0.f;
#pragma unroll
    for (int it = 0; it < 8; ++it) {
        const int k = (it * 32 + lane) * 4;
        const float4 vv = *(const float4*)(V + (size_t)n * 1024 + k);
        const float4 bb = *(const float4*)(b + k);
        s += vv.x * bb.x + vv.y * bb.y + vv.z * bb.z + vv.w * bb.w;
    }
#pragma unroll
    for (int o = 16; o > 0; o >>= 1) s += __shfl_xor_sync(0xffffffffu, s, o);
    if (lane == 0) bc[z * 1024 + n] = s + c[n];
}

// ---------------- mma.sync GEMM, templated term count -----------------------
// NT=1: C = A*B (2 smem tiles). NT=3: C = Ah*Bh + Al*Bh + Ah*Bl (4 tiles).
// mode 1: fp32 out; mode 2: fp16 single out. Both add fp32 bias.
struct GemmArgs {
    const __half *Ahi, *Alo, *Bhi, *Blo;
    const float* bias;
    void* C0;
    int mode;
};

__device__ __forceinline__ uint32_t swz(int r, int s) {
    return (uint32_t)(r * 64 + ((s ^ ((r >> 1) & 3)) << 4));
}

template<int NT>
__global__ void __launch_bounds__(256, 2)
gemm_mma(GemmArgs g0, GemmArgs g1, GemmArgs g2)
{
    constexpr int T = (NT == 1) ? 2 : 4;           // smem tiles per stage
    constexpr uint32_t SS = (uint32_t)T * 8192u;   // stage stride
    constexpr uint32_t BOFF = (NT == 1) ? 8192u : 16384u;

    const GemmArgs ga = (blockIdx.z == 0) ? g0 : (blockIdx.z == 1) ? g1 : g2;
    extern __shared__ char smem_raw[];
    const uint32_t sb = (smem_u32(smem_raw) + 1023u) & ~1023u;

    const int tid = threadIdx.x;
    const int lane = tid & 31;
    const int wid = tid >> 5;
    const int wm = wid & 3;
    const int wn = wid >> 2;
    const int bm = blockIdx.y * 128;
    const int bn = blockIdx.x * 128;

    const __half* bases2[2] = {ga.Ahi, ga.Bhi};
    const __half* bases4[4] = {ga.Ahi, ga.Alo, ga.Bhi, ga.Blo};
    const __half* gp[2 * T];
    uint32_t dst[2 * T];
#pragma unroll
    for (int i = 0; i < 2 * T; ++i) {
        const int u = tid + i * 256;
        const int t = u >> 9;
        const int r = (u >> 2) & 127;
        const int s = u & 3;
        const __half* base = (NT == 1) ? bases2[t] : bases4[t];
        const bool isA = (t < T / 2);
        const int grow = (isA ? bm : bn) + r;
        gp[i] = base + (size_t)grow * 1024 + s * 8;
        dst[i] = sb + t * 8192 + swz(r, s);
    }

    uint32_t lmA[2], lmB[4];
    {
        const int rA = wm * 32 + ((lane >> 3) & 1) * 8 + (lane & 7);
        const int sA = lane >> 4;
#pragma unroll
        for (int mt = 0; mt < 2; ++mt) lmA[mt] = sb + swz(rA + mt * 16, sA);
        const int rB = wn * 64 + (lane >> 4) * 8 + (lane & 7);
        const int sB = (lane >> 3) & 1;
#pragma unroll
        for (int ng = 0; ng < 4; ++ng) lmB[ng] = sb + BOFF + swz(rB + ng * 16, sB);
    }

    float acc[2][4][2][4];
#pragma unroll
    for (int mt = 0; mt < 2; ++mt)
#pragma unroll
        for (int ng = 0; ng < 4; ++ng)
#pragma unroll
            for (int h = 0; h < 2; ++h)
#pragma unroll
                for (int j = 0; j < 4; ++j) acc[mt][ng][h][j] = 0.f;

#pragma unroll
    for (int i = 0; i < 2 * T; ++i) cpasync16(dst[i], gp[i]);
    asm volatile("cp.async.commit_group;" ::: "memory");
#pragma unroll
    for (int i = 0; i < 2 * T; ++i) cpasync16(dst[i] + SS, gp[i] + 32);
    asm volatile("cp.async.commit_group;" ::: "memory");

#pragma unroll 1
    for (int ch = 0; ch < 32; ++ch) {
        if (ch < 31) { asm volatile("cp.async.wait_group 1;" ::: "memory"); }
        else         { asm volatile("cp.async.wait_group 0;" ::: "memory"); }
        __syncthreads();

        if (ch + 2 < 32) {
            const uint32_t sn = (uint32_t)((ch + 2) % 3) * SS;
#pragma unroll
            for (int i = 0; i < 2 * T; ++i) cpasync16(dst[i] + sn, gp[i] + (ch + 2) * 32);
            asm volatile("cp.async.commit_group;" ::: "memory");
        }

        const uint32_t so = (uint32_t)(ch % 3) * SS;
#pragma unroll
        for (int ks = 0; ks < 2; ++ks) {
            const uint32_t kx = (uint32_t)(ks << 5);
            uint32_t ah[2][4];
#pragma unroll
            for (int mt = 0; mt < 2; ++mt) lm4(ah[mt], (lmA[mt] + so) ^ kx);
            uint32_t al[2][4];
            if (NT == 3) {
#pragma unroll
                for (int mt = 0; mt < 2; ++mt) lm4(al[mt], (lmA[mt] + 8192 + so) ^ kx);
            }
#pragma unroll
            for (int ngp = 0; ngp < 2; ++ngp) {
                uint32_t bh[2][4];
#pragma unroll
                for (int g = 0; g < 2; ++g)
                    lm4(bh[g], (lmB[ngp * 2 + g] + so) ^ kx);

#pragma unroll
                for (int g = 0; g < 2; ++g)
#pragma unroll
                    for (int mt = 0; mt < 2; ++mt)
#pragma unroll
                        for (int h = 0; h < 2; ++h)
                            mma_f16(acc[mt][ngp * 2 + g][h], ah[mt], bh[g][2 * h], bh[g][2 * h + 1]);

                if (NT == 3) {
#pragma unroll
                    for (int g = 0; g < 2; ++g)
#pragma unroll
                        for (int mt = 0; mt < 2; ++mt)
#pragma unroll
                            for (int h = 0; h < 2; ++h)
                                mma_f16(acc[mt][ngp * 2 + g][h], al[mt], bh[g][2 * h], bh[g][2 * h + 1]);
                    uint32_t bl[2][4];
#pragma unroll
                    for (int g = 0; g < 2; ++g)
                        lm4(bl[g], (lmB[ngp * 2 + g] + 8192 + so) ^ kx);
#pragma unroll
                    for (int g = 0; g < 2; ++g)
#pragma unroll
                        for (int mt = 0; mt < 2; ++mt)
#pragma unroll
                            for (int h = 0; h < 2; ++h)
                                mma_f16(acc[mt][ngp * 2 + g][h], ah[mt], bl[g][2 * h], bl[g][2 * h + 1]);
                }
            }
        }
    }

#pragma unroll
    for (int mt = 0; mt < 2; ++mt) {
        const int r0 = bm + wm * 32 + mt * 16 + (lane >> 2);
#pragma unroll
        for (int ng = 0; ng < 4; ++ng)
#pragma unroll
            for (int h = 0; h < 2; ++h) {
                const int col = bn + wn * 64 + ng * 16 + h * 8 + 2 * (lane & 3);
                const float2 b2 = *(const float2*)(ga.bias + col);
                const float* a4 = acc[mt][ng][h];
                const float v00 = a4[0] + b2.x, v01 = a4[1] + b2.y;
                const float v10 = a4[2] + b2.x, v11 = a4[3] + b2.y;
                if (ga.mode == 1) {
                    float2 p0; p0.x = v00; p0.y = v01;
                    float2 p1; p1.x = v10; p1.y = v11;
                    *(float2*)((float*)ga.C0 + (size_t)r0 * 1024 + col) = p0;
                    *(float2*)((float*)ga.C0 + (size_t)(r0 + 8) * 1024 + col) = p1;
                } else {
                    __half* hp = (__half*)ga.C0;
                    __half2 H0, H1;
                    H0.x = __float2half_rn(v00); H0.y = __float2half_rn(v01);
                    H1.x = __float2half_rn(v10); H1.y = __float2half_rn(v11);
                    *(__half2*)(hp + (size_t)r0 * 1024 + col) = H0;
                    *(__half2*)(hp + (size_t)(r0 + 8) * 1024 + col) = H1;
                }
            }
    }
}

// ---------------- MMA flash attention (single fp16 Q/K/V) -------------------
#define AK 0u
#define AV 32768u
#define AQ 65536u

__global__ void __launch_bounds__(256, 2)
attention_mma(const __half* __restrict__ q2, const __half* __restrict__ k2,
              const __half* __restrict__ v2,
              __half* __restrict__ Oh, __half* __restrict__ Ol)
{
    extern __shared__ char smraw[];
    const uint32_t sb = smem_u32(smraw);

    const int qp = blockIdx.x;
    const int c  = blockIdx.y;
    const int b  = blockIdx.z;
    const int tid = threadIdx.x;
    const int lane = tid & 31;
    const int w = tid >> 5;

#pragma unroll
    for (int i = 0; i < 16; ++i) {
        const int u = tid + i * 256;
        const int arr = u >> 11;
        const int rem = u & 2047;
        const int r = rem >> 1;
        const int half = rem & 1;
        const __half* base = arr ? v2 : k2;
        const __half* src = base + ((size_t)((b << 10) + r) << 10) + (c << 4) + (half << 3);
        const uint32_t dstp = sb + (uint32_t)(arr << 15) + (uint32_t)(r * 32 + ((half ^ ((r >> 2) & 1)) << 4));
        cpasync16(dstp, src);
    }
    asm volatile("cp.async.commit_group;" ::: "memory");

    const uint32_t qoff = (uint32_t)((lane & 15) * 32 + ((((lane >> 4) & 1) ^ ((lane >> 2) & 1)) << 4));
    const uint32_t kloff = (uint32_t)(((lane & 7) + ((lane >> 4) << 3)) * 32 +
                                      ((((lane >> 3) & 1) ^ ((lane >> 2) & 1)) << 4));
    const uint32_t vloff = (uint32_t)(((lane & 7) + (((lane >> 3) & 1) << 3)) * 32 +
                                      ((((lane >> 4) & 1) ^ ((lane >> 2) & 1)) << 4));
    const float SCL = 0.25f * 1.4426950408889634f;
    const uint32_t scl2 = packh(SCL, SCL);
    const uint32_t ONES = 0x3C003C00u;

    const int ca = c >> 2, e = c & 3;
    const int tt = 2 * e + b;
    const int b2 = tt >> 2, r2 = tt & 3;

#pragma unroll 1
    for (int it = 0; it < 2; ++it) {
        const int qt = qp * 2 + it;
#pragma unroll
        for (int i = 0; i < 2; ++i) {
            const int u = tid + i * 256;
            const int r = u >> 1;
            const int half = u & 1;
            const __half* src = q2 + ((size_t)((b << 10) + (qt << 8) + r) << 10) + (c << 4) + (half << 3);
            const uint32_t dstp = sb + AQ + (uint32_t)(r * 32 + ((half ^ ((r >> 2) & 1)) << 4));
            cpasync16(dstp, src);
        }
        asm volatile("cp.async.commit_group;" ::: "memory");
        asm volatile("cp.async.wait_group 0;" ::: "memory");
        __syncthreads();

        uint32_t qf[2][4];
#pragma unroll
        for (int mt = 0; mt < 2; ++mt)
            lm4(qf[mt], sb + AQ + (uint32_t)((w * 32 + mt * 16) * 32) + qoff);

        float oac[2][2][4];
        float ls[2][4];
#pragma unroll
        for (int mt = 0; mt < 2; ++mt) {
#pragma unroll
            for (int j = 0; j < 4; ++j) ls[mt][j] = 0.f;
#pragma unroll
            for (int ht = 0; ht < 2; ++ht)
#pragma unroll
                for (int j = 0; j < 4; ++j) oac[mt][ht][j] = 0.f;
        }

#pragma unroll 1
        for (int kb = 0; kb < 16; ++kb) {
            float sc[2][8][4];
#pragma unroll
            for (int mt = 0; mt < 2; ++mt)
#pragma unroll
                for (int j = 0; j < 8; ++j)
#pragma unroll
                    for (int i = 0; i < 4; ++i) sc[mt][j][i] = 0.f;

#pragma unroll
            for (int nt = 0; nt < 4; ++nt) {
                const uint32_t s0 = (uint32_t)((kb * 64 + nt * 16) * 32);
                uint32_t kh4[4];
                lm4(kh4, sb + AK + s0 + kloff);
#pragma unroll
                for (int mt = 0; mt < 2; ++mt) {
                    mma_f16(sc[mt][2 * nt], qf[mt], kh4[0], kh4[1]);
                    mma_f16(sc[mt][2 * nt + 1], qf[mt], kh4[2], kh4[3]);
                }
            }

#pragma unroll
            for (int ks = 0; ks < 4; ++ks) {
                const uint32_t s0 = (uint32_t)((kb * 64 + ks * 16) * 32);
                uint32_t vh4[4];
                lm4t(vh4, sb + AV + s0 + vloff);
#pragma unroll
                for (int mt = 0; mt < 2; ++mt) {
                    uint32_t pa[4];
                    pa[0] = hex2(hmul2(packh(sc[mt][2 * ks][0], sc[mt][2 * ks][1]), scl2));
                    pa[1] = hex2(hmul2(packh(sc[mt][2 * ks][2], sc[mt][2 * ks][3]), scl2));
                    pa[2] = hex2(hmul2(packh(sc[mt][2 * ks + 1][0], sc[mt][2 * ks + 1][1]), scl2));
                    pa[3] = hex2(hmul2(packh(sc[mt][2 * ks + 1][2], sc[mt][2 * ks + 1][3]), scl2));
                    mma_f16(oac[mt][0], pa, vh4[0], vh4[1]);
                    mma_f16(oac[mt][1], pa, vh4[2], vh4[3]);
                    mma_f16(ls[mt], pa, ONES, ONES);
                }
            }
        }

        // epilogue: normalize + permuted split-fp16 store
#pragma unroll
        for (int mt = 0; mt < 2; ++mt) {
            const int s_lo = qt * 256 + w * 32 + mt * 16 + (lane >> 2);
            const float inv_lo = 1.0f / ls[mt][0];
            const float inv_hi = 1.0f / ls[mt][2];
#pragma unroll
            for (int ht = 0; ht < 2; ++ht) {
                const int h0 = ht * 8 + 2 * (lane & 3);
#pragma unroll
                for (int rr = 0; rr < 2; ++rr) {
                    const int s = s_lo + rr * 8;
                    const float inv = rr ? inv_hi : inv_lo;
                    const float v0 = oac[mt][ht][rr * 2 + 0] * inv;
                    const float v1 = oac[mt][ht][rr * 2 + 1] * inv;
                    const int s2 = (r2 << 8) | (s >> 2);
                    const int f = (ca << 6) | ((s & 3) << 4) | h0;
                    const size_t off = (((size_t)b2 << 10) + s2) * 1024 + f;
                    __half2 H, L;
                    H.x = __float2half_rn(v0); H.y = __float2half_rn(v1);
                    L.x = __float2half_rn(v0 - __half2float(H.x));
                    L.y = __float2half_rn(v1 - __half2float(H.y));
                    *(__half2*)(Oh + off) = H;
                    *(__half2*)(Ol + off) = L;
                }
            }
        }
        __syncthreads();
    }
}

// ---------------------------------------------------------------------------
extern "C" void kernel_launch(void* const* d_in, const int* in_sizes, int n_in,
                              void* d_out, int out_size)
{
    const float* x    = (const float*)d_in[0];
    const float* wq_w = (const float*)d_in[1];
    const float* wq_b = (const float*)d_in[2];
    const float* wk_w = (const float*)d_in[3];
    const float* wk_b = (const float*)d_in[4];
    const float* wv_w = (const float*)d_in[5];
    const float* wv_b = (const float*)d_in[6];
    const float* vq_w = (const float*)d_in[7];
    const float* vq_b = (const float*)d_in[8];
    const float* vk_w = (const float*)d_in[9];
    const float* vk_b = (const float*)d_in[10];
    const float* vv_w = (const float*)d_in[11];
    const float* vv_b = (const float*)d_in[12];
    const float* wo_w = (const float*)d_in[13];
    const float* wo_b = (const float*)d_in[14];
    float* out = (float*)d_out;

    __half *xh, *ws, *woh, *wol, *wT, *wc, *q2f, *k2f, *v2f, *oh, *ol;
    float *bc, *zb;
    cudaGetSymbolAddress((void**)&xh, g_xh);
    cudaGetSymbolAddress((void**)&ws, g_ws);
    cudaGetSymbolAddress((void**)&woh, g_woh); cudaGetSymbolAddress((void**)&wol, g_wol);
    cudaGetSymbolAddress((void**)&wT, g_wT);   cudaGetSymbolAddress((void**)&wc, g_wc);
    cudaGetSymbolAddress((void**)&bc, g_bc);   cudaGetSymbolAddress((void**)&zb, g_zb);
    cudaGetSymbolAddress((void**)&q2f, g_q2f); cudaGetSymbolAddress((void**)&k2f, g_k2f);
    cudaGetSymbolAddress((void**)&v2f, g_v2f);
    cudaGetSymbolAddress((void**)&oh, g_oh);   cudaGetSymbolAddress((void**)&ol, g_ol);

    // 1) converts: x, vq, vk, vv -> single fp16
    CvtArgs ca;
    ca.src[0] = x;    ca.dst[0] = xh;           ca.n[0] = 2097152;
    ca.src[1] = vq_w; ca.dst[1] = ws + 0;       ca.n[1] = 1048576;
    ca.src[2] = vk_w; ca.dst[2] = ws + 1048576; ca.n[2] = 1048576;
    ca.src[3] = vv_w; ca.dst[3] = ws + 2097152; ca.n[3] = 1048576;
    cvt4<<<dim3(2048, 1, 4), 256>>>(ca);

    // 2) wo -> hi/lo split; wq,wk,wv -> transposed single
    split1<<<1024, 256>>>(wo_w, woh, wol);
    wsplitT<<<dim3(32, 32, 3), 256>>>(wq_w, wk_w, wv_w, wT);

    // 3) combined biases
    bias_combine<<<dim3(128, 1, 3), 256>>>(vq_w, wq_b, vq_b, vk_w, wk_b, vk_b, vv_w, wv_b, vv_b, bc);

    const int smem1 = 3 * 16384 + 1024;
    const int smem3 = 3 * 32768 + 1024;
    cudaFuncSetAttribute(gemm_mma<1>, cudaFuncAttributeMaxDynamicSharedMemorySize, smem1);
    cudaFuncSetAttribute(gemm_mma<3>, cudaFuncAttributeMaxDynamicSharedMemorySize, smem3);

    // 4) weight combine: Wc = Vq @ Wq (1-term fp16), single fp16 out
    GemmArgs a0{}, a1{}, a2{};
    a0 = {ws + 0, nullptr, wT + 0, nullptr, zb, wc + 0, 2};
    a1 = {ws + 1048576, nullptr, wT + 1048576, nullptr, zb, wc + 1048576, 2};
    a2 = {ws + 2097152, nullptr, wT + 2097152, nullptr, zb, wc + 2097152, 2};
    gemm_mma<1><<<dim3(8, 8, 3), 256, smem1>>>(a0, a1, a2);

    // 5) data GEMMs: q2/k2/v2 single fp16 (1-term)
    a0 = {xh, nullptr, wc + 0, nullptr, bc + 0, q2f, 2};
    a1 = {xh, nullptr, wc + 1048576, nullptr, bc + 1024, k2f, 2};
    a2 = {xh, nullptr, wc + 2097152, nullptr, bc + 2048, v2f, 2};
    gemm_mma<1><<<dim3(8, 16, 3), 256, smem1>>>(a0, a1, a2);

    // 6) attention -> o fp16 hi/lo, permuted
    const int attn_smem = 73728;
    cudaFuncSetAttribute(attention_mma, cudaFuncAttributeMaxDynamicSharedMemorySize, attn_smem);
    attention_mma<<<dim3(2, 64, 2), 256, attn_smem>>>(q2f, k2f, v2f, oh, ol);

    // 7) final projection (3-term fp16), fp32 out
    a0 = {oh, ol, woh, wol, wo_b, out, 1};
    gemm_mma<3><<<dim3(8, 16, 1), 256, smem3>>>(a0, a0, a0);
}

// round 10
// speedup vs baseline: 5.8569x; 1.1099x over previous
#include <cuda_runtime.h>
#include <cuda_fp16.h>
#include <cstdint>
#include <math.h>

// ===========================================================================
// Round 10: 1-term fp16 everywhere on the GEMM path (wcomb, data, final);
// attention with fp16-accum QK^T (Q pre-scaled by SCL via GEMM epilogue) and
// direct f16x2 exp2; o stored single fp16. Error budget per calibrated model.
// ===========================================================================

__device__ __forceinline__ uint32_t smem_u32(const void* p) {
    uint32_t a;
    asm("{ .reg .u64 t; cvta.to.shared.u64 t, %1; cvt.u32.u64 %0, t; }" : "=r"(a) : "l"(p));
    return a;
}
__device__ __forceinline__ void lm4(uint32_t* r, uint32_t a) {
    asm volatile("ldmatrix.sync.aligned.m8n8.x4.shared.b16 {%0,%1,%2,%3}, [%4];"
        : "=r"(r[0]), "=r"(r[1]), "=r"(r[2]), "=r"(r[3]) : "r"(a));
}
__device__ __forceinline__ void lm4t(uint32_t* r, uint32_t a) {
    asm volatile("ldmatrix.sync.aligned.m8n8.x4.trans.shared.b16 {%0,%1,%2,%3}, [%4];"
        : "=r"(r[0]), "=r"(r[1]), "=r"(r[2]), "=r"(r[3]) : "r"(a));
}
// f32-accum fp16 MMA
__device__ __forceinline__ void mma_f16(float* d, const uint32_t* a, uint32_t b0, uint32_t b1) {
    asm volatile("mma.sync.aligned.m16n8k16.row.col.f32.f16.f16.f32 "
        "{%0,%1,%2,%3}, {%4,%5,%6,%7}, {%8,%9}, {%0,%1,%2,%3};"
        : "+f"(d[0]), "+f"(d[1]), "+f"(d[2]), "+f"(d[3])
        : "r"(a[0]), "r"(a[1]), "r"(a[2]), "r"(a[3]), "r"(b0), "r"(b1));
}
// f16-accum fp16 MMA (d = 2 f16x2 regs: {c0,c1} row-lo, {c2,c3} row-hi)
__device__ __forceinline__ void mma_f16h(uint32_t* d, const uint32_t* a, uint32_t b0, uint32_t b1) {
    asm volatile("mma.sync.aligned.m16n8k16.row.col.f16.f16.f16.f16 "
        "{%0,%1}, {%2,%3,%4,%5}, {%6,%7}, {%0,%1};"
        : "+r"(d[0]), "+r"(d[1])
        : "r"(a[0]), "r"(a[1]), "r"(a[2]), "r"(a[3]), "r"(b0), "r"(b1));
}
__device__ __forceinline__ void cpasync16(uint32_t dst, const void* src) {
    asm volatile("cp.async.cg.shared.global [%0], [%1], 16;" :: "r"(dst), "l"(src));
}
__device__ __forceinline__ uint32_t hex2(uint32_t a) {
    uint32_t d; asm("ex2.approx.f16x2 %0, %1;" : "=r"(d) : "r"(a)); return d;
}

// ---------------- scratch (device globals) ---------------------------------
__device__ __half g_xh[2097152];                  // x single fp16
__device__ __half g_ws[3145728];                  // vq,vk,vv single fp16
__device__ __half g_wos[1048576];                 // wo single fp16
__device__ __half g_wT[3145728];                  // wq,wk,wv transposed, single
__device__ __half g_wc[3145728];                  // combined weights, single
__device__ float g_bc[3072];                      // combined biases
__device__ float g_zb[1024];                      // zero bias (.bss)
__device__ __half g_q2f[2097152], g_k2f[2097152], g_v2f[2097152];
__device__ __half g_of[2097152];                  // attention output, permuted

// ---------------- fp32 -> fp16 single convert (x, vq, vk, vv, wo) -----------
struct CvtArgs {
    const float* src[5];
    __half* dst[5];
    int n[5];
};

__global__ void __launch_bounds__(256) cvt5(CvtArgs a) {
    const int z = blockIdx.z;
    const int i = (blockIdx.x * 256 + threadIdx.x) * 4;
    if (i >= a.n[z]) return;
    const float4 v = *(const float4*)(a.src[z] + i);
    __half2 H0; H0.x = __float2half_rn(v.x); H0.y = __float2half_rn(v.y);
    __half2 H1; H1.x = __float2half_rn(v.z); H1.y = __float2half_rn(v.w);
    *(__half2*)(a.dst[z] + i) = H0;
    *(__half2*)(a.dst[z] + i + 2) = H1;
}

// ---------------- transpose to single fp16 (wq, wk, wv) ---------------------
__global__ void __launch_bounds__(256)
wsplitT(const float* W0, const float* W1, const float* W2, __half* hiT)
{
    const int z = blockIdx.z;
    const float* W = (z == 0) ? W0 : (z == 1) ? W1 : W2;
    __half* ho = hiT + (size_t)z * 1048576;

    __shared__ float s[32][33];
    const int tx = threadIdx.x & 31;
    const int ty = threadIdx.x >> 5;
    const int k0 = blockIdx.x * 32;
    const int m0 = blockIdx.y * 32;
#pragma unroll
    for (int j = 0; j < 4; ++j)
        s[ty + j * 8][tx] = W[(size_t)(m0 + ty + j * 8) * 1024 + k0 + tx];
    __syncthreads();
#pragma unroll
    for (int j = 0; j < 4; ++j)
        ho[(size_t)(k0 + ty + j * 8) * 1024 + m0 + tx] = __float2half_rn(s[tx][ty + j * 8]);
}

// ---------------- combined bias: bc[n] = V[n,:].b + vb[n] -------------------
__global__ void __launch_bounds__(256)
bias_combine(const float* V0, const float* b0, const float* c0,
             const float* V1, const float* b1, const float* c1,
             const float* V2, const float* b2, const float* c2,
             float* bc)
{
    const int z = blockIdx.z;
    const float* V = (z == 0) ? V0 : (z == 1) ? V1 : V2;
    const float* b = (z == 0) ? b0 : (z == 1) ? b1 : b2;
    const float* c = (z == 0) ? c0 : (z == 1) ? c1 : c2;
    const int lane = threadIdx.x & 31;
    const int w = threadIdx.x >> 5;
    const int n = blockIdx.x * 8 + w;
    float s = 0.f;
#pragma unroll
    for (int it = 0; it < 8; ++it) {
        const int k = (it * 32 + lane) * 4;
        const float4 vv = *(const float4*)(V + (size_t)n * 1024 + k);
        const float4 bb = *(const float4*)(b + k);
        s += vv.x * bb.x + vv.y * bb.y + vv.z * bb.z + vv.w * bb.w;
    }
#pragma unroll
    for (int o = 16; o > 0; o >>= 1) s += __shfl_xor_sync(0xffffffffu, s, o);
    if (lane == 0) bc[z * 1024 + n] = s + c[n];
}

// ---------------- mma.sync GEMM, 1-term fp16 ---------------------------------
// C = A*B (+bias) * oscale. mode 1: fp32 out; mode 2: fp16 single out.
struct GemmArgs {
    const __half *A, *B;
    const float* bias;
    void* C0;
    int mode;
    float oscale;
};

__device__ __forceinline__ uint32_t swz(int r, int s) {
    return (uint32_t)(r * 64 + ((s ^ ((r >> 1) & 3)) << 4));
}

__global__ void __launch_bounds__(256, 2)
gemm_mma(GemmArgs g0, GemmArgs g1, GemmArgs g2)
{
    constexpr uint32_t SS = 16384u;   // stage stride (2 tiles x 8KB)

    const GemmArgs ga = (blockIdx.z == 0) ? g0 : (blockIdx.z == 1) ? g1 : g2;
    extern __shared__ char smem_raw[];
    const uint32_t sb = (smem_u32(smem_raw) + 1023u) & ~1023u;

    const int tid = threadIdx.x;
    const int lane = tid & 31;
    const int wid = tid >> 5;
    const int wm = wid & 3;
    const int wn = wid >> 2;
    const int bm = blockIdx.y * 128;
    const int bn = blockIdx.x * 128;

    const __half* gp[4];
    uint32_t dst[4];
#pragma unroll
    for (int i = 0; i < 4; ++i) {
        const int u = tid + i * 256;
        const int t = u >> 9;            // 0=A 1=B
        const int r = (u >> 2) & 127;
        const int s = u & 3;
        const __half* base = t ? ga.B : ga.A;
        const int grow = (t ? bn : bm) + r;
        gp[i] = base + (size_t)grow * 1024 + s * 8;
        dst[i] = sb + t * 8192 + swz(r, s);
    }

    uint32_t lmA[2], lmB[4];
    {
        const int rA = wm * 32 + ((lane >> 3) & 1) * 8 + (lane & 7);
        const int sA = lane >> 4;
#pragma unroll
        for (int mt = 0; mt < 2; ++mt) lmA[mt] = sb + swz(rA + mt * 16, sA);
        const int rB = wn * 64 + (lane >> 4) * 8 + (lane & 7);
        const int sB = (lane >> 3) & 1;
#pragma unroll
        for (int ng = 0; ng < 4; ++ng) lmB[ng] = sb + 8192 + swz(rB + ng * 16, sB);
    }

    float acc[2][4][2][4];
#pragma unroll
    for (int mt = 0; mt < 2; ++mt)
#pragma unroll
        for (int ng = 0; ng < 4; ++ng)
#pragma unroll
            for (int h = 0; h < 2; ++h)
#pragma unroll
                for (int j = 0; j < 4; ++j) acc[mt][ng][h][j] = 0.f;

#pragma unroll
    for (int i = 0; i < 4; ++i) cpasync16(dst[i], gp[i]);
    asm volatile("cp.async.commit_group;" ::: "memory");
#pragma unroll
    for (int i = 0; i < 4; ++i) cpasync16(dst[i] + SS, gp[i] + 32);
    asm volatile("cp.async.commit_group;" ::: "memory");

#pragma unroll 1
    for (int ch = 0; ch < 32; ++ch) {
        if (ch < 31) { asm volatile("cp.async.wait_group 1;" ::: "memory"); }
        else         { asm volatile("cp.async.wait_group 0;" ::: "memory"); }
        __syncthreads();

        if (ch + 2 < 32) {
            const uint32_t sn = (uint32_t)((ch + 2) % 3) * SS;
#pragma unroll
            for (int i = 0; i < 4; ++i) cpasync16(dst[i] + sn, gp[i] + (ch + 2) * 32);
            asm volatile("cp.async.commit_group;" ::: "memory");
        }

        const uint32_t so = (uint32_t)(ch % 3) * SS;
#pragma unroll
        for (int ks = 0; ks < 2; ++ks) {
            const uint32_t kx = (uint32_t)(ks << 5);
            uint32_t ah[2][4];
#pragma unroll
            for (int mt = 0; mt < 2; ++mt) lm4(ah[mt], (lmA[mt] + so) ^ kx);
#pragma unroll
            for (int ngp = 0; ngp < 2; ++ngp) {
                uint32_t bh[2][4];
#pragma unroll
                for (int g = 0; g < 2; ++g)
                    lm4(bh[g], (lmB[ngp * 2 + g] + so) ^ kx);
#pragma unroll
                for (int g = 0; g < 2; ++g)
#pragma unroll
                    for (int mt = 0; mt < 2; ++mt)
#pragma unroll
                        for (int h = 0; h < 2; ++h)
                            mma_f16(acc[mt][ngp * 2 + g][h], ah[mt], bh[g][2 * h], bh[g][2 * h + 1]);
            }
        }
    }

    const float osc = ga.oscale;
#pragma unroll
    for (int mt = 0; mt < 2; ++mt) {
        const int r0 = bm + wm * 32 + mt * 16 + (lane >> 2);
#pragma unroll
        for (int ng = 0; ng < 4; ++ng)
#pragma unroll
            for (int h = 0; h < 2; ++h) {
                const int col = bn + wn * 64 + ng * 16 + h * 8 + 2 * (lane & 3);
                const float2 b2 = *(const float2*)(ga.bias + col);
                const float* a4 = acc[mt][ng][h];
                const float v00 = (a4[0] + b2.x) * osc, v01 = (a4[1] + b2.y) * osc;
                const float v10 = (a4[2] + b2.x) * osc, v11 = (a4[3] + b2.y) * osc;
                if (ga.mode == 1) {
                    float2 p0; p0.x = v00; p0.y = v01;
                    float2 p1; p1.x = v10; p1.y = v11;
                    *(float2*)((float*)ga.C0 + (size_t)r0 * 1024 + col) = p0;
                    *(float2*)((float*)ga.C0 + (size_t)(r0 + 8) * 1024 + col) = p1;
                } else {
                    __half* hp = (__half*)ga.C0;
                    __half2 H0, H1;
                    H0.x = __float2half_rn(v00); H0.y = __float2half_rn(v01);
                    H1.x = __float2half_rn(v10); H1.y = __float2half_rn(v11);
                    *(__half2*)(hp + (size_t)r0 * 1024 + col) = H0;
                    *(__half2*)(hp + (size_t)(r0 + 8) * 1024 + col) = H1;
                }
            }
    }
}

// ---------------- MMA flash attention ---------------------------------------
// Q pre-scaled by SCL (log2-domain scores). QK^T in fp16 accum -> hex2 direct.
// PV + ones-row-sum MMAs in fp32 accum. Output single fp16, permuted.
#define AK 0u
#define AV 32768u
#define AQ 65536u

__global__ void __launch_bounds__(256, 2)
attention_mma(const __half* __restrict__ q2, const __half* __restrict__ k2,
              const __half* __restrict__ v2, __half* __restrict__ Of)
{
    extern __shared__ char smraw[];
    const uint32_t sb = smem_u32(smraw);

    const int qp = blockIdx.x;
    const int c  = blockIdx.y;
    const int b  = blockIdx.z;
    const int tid = threadIdx.x;
    const int lane = tid & 31;
    const int w = tid >> 5;

#pragma unroll
    for (int i = 0; i < 16; ++i) {
        const int u = tid + i * 256;
        const int arr = u >> 11;
        const int rem = u & 2047;
        const int r = rem >> 1;
        const int half = rem & 1;
        const __half* base = arr ? v2 : k2;
        const __half* src = base + ((size_t)((b << 10) + r) << 10) + (c << 4) + (half << 3);
        const uint32_t dstp = sb + (uint32_t)(arr << 15) + (uint32_t)(r * 32 + ((half ^ ((r >> 2) & 1)) << 4));
        cpasync16(dstp, src);
    }
    asm volatile("cp.async.commit_group;" ::: "memory");

    const uint32_t qoff = (uint32_t)((lane & 15) * 32 + ((((lane >> 4) & 1) ^ ((lane >> 2) & 1)) << 4));
    const uint32_t kloff = (uint32_t)(((lane & 7) + ((lane >> 4) << 3)) * 32 +
                                      ((((lane >> 3) & 1) ^ ((lane >> 2) & 1)) << 4));
    const uint32_t vloff = (uint32_t)(((lane & 7) + (((lane >> 3) & 1) << 3)) * 32 +
                                      ((((lane >> 4) & 1) ^ ((lane >> 2) & 1)) << 4));
    const uint32_t ONES = 0x3C003C00u;

    const int ca = c >> 2, e = c & 3;
    const int tt = 2 * e + b;
    const int b2 = tt >> 2, r2 = tt & 3;

#pragma unroll 1
    for (int it = 0; it < 2; ++it) {
        const int qt = qp * 2 + it;
#pragma unroll
        for (int i = 0; i < 2; ++i) {
            const int u = tid + i * 256;
            const int r = u >> 1;
            const int half = u & 1;
            const __half* src = q2 + ((size_t)((b << 10) + (qt << 8) + r) << 10) + (c << 4) + (half << 3);
            const uint32_t dstp = sb + AQ + (uint32_t)(r * 32 + ((half ^ ((r >> 2) & 1)) << 4));
            cpasync16(dstp, src);
        }
        asm volatile("cp.async.commit_group;" ::: "memory");
        asm volatile("cp.async.wait_group 0;" ::: "memory");
        __syncthreads();

        uint32_t qf[2][4];
#pragma unroll
        for (int mt = 0; mt < 2; ++mt)
            lm4(qf[mt], sb + AQ + (uint32_t)((w * 32 + mt * 16) * 32) + qoff);

        float oac[2][2][4];
        float ls[2][4];
#pragma unroll
        for (int mt = 0; mt < 2; ++mt) {
#pragma unroll
            for (int j = 0; j < 4; ++j) ls[mt][j] = 0.f;
#pragma unroll
            for (int ht = 0; ht < 2; ++ht)
#pragma unroll
                for (int j = 0; j < 4; ++j) oac[mt][ht][j] = 0.f;
        }

#pragma unroll 1
        for (int kb = 0; kb < 16; ++kb) {
            // scores in fp16 accum: sc16[mt][j] = {lo-row pair, hi-row pair}
            uint32_t sc16[2][8][2];
#pragma unroll
            for (int mt = 0; mt < 2; ++mt)
#pragma unroll
                for (int j = 0; j < 8; ++j) { sc16[mt][j][0] = 0u; sc16[mt][j][1] = 0u; }

#pragma unroll
            for (int nt = 0; nt < 4; ++nt) {
                const uint32_t s0 = (uint32_t)((kb * 64 + nt * 16) * 32);
                uint32_t kh4[4];
                lm4(kh4, sb + AK + s0 + kloff);
#pragma unroll
                for (int mt = 0; mt < 2; ++mt) {
                    mma_f16h(sc16[mt][2 * nt], qf[mt], kh4[0], kh4[1]);
                    mma_f16h(sc16[mt][2 * nt + 1], qf[mt], kh4[2], kh4[3]);
                }
            }

#pragma unroll
            for (int ks = 0; ks < 4; ++ks) {
                const uint32_t s0 = (uint32_t)((kb * 64 + ks * 16) * 32);
                uint32_t vh4[4];
                lm4t(vh4, sb + AV + s0 + vloff);
#pragma unroll
                for (int mt = 0; mt < 2; ++mt) {
                    uint32_t pa[4];
                    pa[0] = hex2(sc16[mt][2 * ks][0]);
                    pa[1] = hex2(sc16[mt][2 * ks][1]);
                    pa[2] = hex2(sc16[mt][2 * ks + 1][0]);
                    pa[3] = hex2(sc16[mt][2 * ks + 1][1]);
                    mma_f16(oac[mt][0], pa, vh4[0], vh4[1]);
                    mma_f16(oac[mt][1], pa, vh4[2], vh4[3]);
                    mma_f16(ls[mt], pa, ONES, ONES);
                }
            }
        }

        // epilogue: normalize + permuted single-fp16 store
#pragma unroll
        for (int mt = 0; mt < 2; ++mt) {
            const int s_lo = qt * 256 + w * 32 + mt * 16 + (lane >> 2);
            const float inv_lo = 1.0f / ls[mt][0];
            const float inv_hi = 1.0f / ls[mt][2];
#pragma unroll
            for (int ht = 0; ht < 2; ++ht) {
                const int h0 = ht * 8 + 2 * (lane & 3);
#pragma unroll
                for (int rr = 0; rr < 2; ++rr) {
                    const int s = s_lo + rr * 8;
                    const float inv = rr ? inv_hi : inv_lo;
                    const float v0 = oac[mt][ht][rr * 2 + 0] * inv;
                    const float v1 = oac[mt][ht][rr * 2 + 1] * inv;
                    const int s2 = (r2 << 8) | (s >> 2);
                    const int f = (ca << 6) | ((s & 3) << 4) | h0;
                    const size_t off = (((size_t)b2 << 10) + s2) * 1024 + f;
                    __half2 H;
                    H.x = __float2half_rn(v0); H.y = __float2half_rn(v1);
                    *(__half2*)(Of + off) = H;
                }
            }
        }
        __syncthreads();
    }
}

// ---------------------------------------------------------------------------
extern "C" void kernel_launch(void* const* d_in, const int* in_sizes, int n_in,
                              void* d_out, int out_size)
{
    const float* x    = (const float*)d_in[0];
    const float* wq_w = (const float*)d_in[1];
    const float* wq_b = (const float*)d_in[2];
    const float* wk_w = (const float*)d_in[3];
    const float* wk_b = (const float*)d_in[4];
    const float* wv_w = (const float*)d_in[5];
    const float* wv_b = (const float*)d_in[6];
    const float* vq_w = (const float*)d_in[7];
    const float* vq_b = (const float*)d_in[8];
    const float* vk_w = (const float*)d_in[9];
    const float* vk_b = (const float*)d_in[10];
    const float* vv_w = (const float*)d_in[11];
    const float* vv_b = (const float*)d_in[12];
    const float* wo_w = (const float*)d_in[13];
    const float* wo_b = (const float*)d_in[14];
    float* out = (float*)d_out;

    __half *xh, *ws, *wos, *wT, *wc, *q2f, *k2f, *v2f, *of;
    float *bc, *zb;
    cudaGetSymbolAddress((void**)&xh, g_xh);
    cudaGetSymbolAddress((void**)&ws, g_ws);
    cudaGetSymbolAddress((void**)&wos, g_wos);
    cudaGetSymbolAddress((void**)&wT, g_wT);   cudaGetSymbolAddress((void**)&wc, g_wc);
    cudaGetSymbolAddress((void**)&bc, g_bc);   cudaGetSymbolAddress((void**)&zb, g_zb);
    cudaGetSymbolAddress((void**)&q2f, g_q2f); cudaGetSymbolAddress((void**)&k2f, g_k2f);
    cudaGetSymbolAddress((void**)&v2f, g_v2f);
    cudaGetSymbolAddress((void**)&of, g_of);

    // 1) converts: x, vq, vk, vv, wo -> single fp16
    CvtArgs ca;
    ca.src[0] = x;    ca.dst[0] = xh;           ca.n[0] = 2097152;
    ca.src[1] = vq_w; ca.dst[1] = ws + 0;       ca.n[1] = 1048576;
    ca.src[2] = vk_w; ca.dst[2] = ws + 1048576; ca.n[2] = 1048576;
    ca.src[3] = vv_w; ca.dst[3] = ws + 2097152; ca.n[3] = 1048576;
    ca.src[4] = wo_w; ca.dst[4] = wos;          ca.n[4] = 1048576;
    cvt5<<<dim3(2048, 1, 5), 256>>>(ca);

    // 2) wq,wk,wv -> transposed single fp16
    wsplitT<<<dim3(32, 32, 3), 256>>>(wq_w, wk_w, wv_w, wT);

    // 3) combined biases
    bias_combine<<<dim3(128, 1, 3), 256>>>(vq_w, wq_b, vq_b, vk_w, wk_b, vk_b, vv_w, wv_b, vv_b, bc);

    const int gemm_smem = 3 * 16384 + 1024;
    cudaFuncSetAttribute(gemm_mma, cudaFuncAttributeMaxDynamicSharedMemorySize, gemm_smem);

    const float SCL = 0.25f * 1.4426950408889634f;  // (1/sqrt(16)) * log2(e)

    // 4) weight combine: Wc = Vq @ Wq (1-term fp16)
    GemmArgs a0{}, a1{}, a2{};
    a0 = {ws + 0, wT + 0, zb, wc + 0, 2, 1.0f};
    a1 = {ws + 1048576, wT + 1048576, zb, wc + 1048576, 2, 1.0f};
    a2 = {ws + 2097152, wT + 2097152, zb, wc + 2097152, 2, 1.0f};
    gemm_mma<<<dim3(8, 8, 3), 256, gemm_smem>>>(a0, a1, a2);

    // 5) data GEMMs: q2 (pre-scaled by SCL), k2, v2 single fp16
    a0 = {xh, wc + 0, bc + 0, q2f, 2, SCL};
    a1 = {xh, wc + 1048576, bc + 1024, k2f, 2, 1.0f};
    a2 = {xh, wc + 2097152, bc + 2048, v2f, 2, 1.0f};
    gemm_mma<<<dim3(8, 16, 3), 256, gemm_smem>>>(a0, a1, a2);

    // 6) attention -> o single fp16, permuted
    const int attn_smem = 73728;
    cudaFuncSetAttribute(attention_mma, cudaFuncAttributeMaxDynamicSharedMemorySize, attn_smem);
    attention_mma<<<dim3(2, 64, 2), 256, attn_smem>>>(q2f, k2f, v2f, of);

    // 7) final projection (1-term fp16), fp32 out
    a0 = {of, wos, wo_b, out, 1, 1.0f};
    gemm_mma<<<dim3(8, 16, 1), 256, gemm_smem>>>(a0, a0, a0);
}

// round 11
// speedup vs baseline: 6.9897x; 1.1934x over previous
#include <cuda_runtime.h>
#include <cuda_fp16.h>
#include <cstdint>
#include <math.h>

// ===========================================================================
// Round 11: wave-quantization fix. All GEMMs on 128x64 tiles (grid sizes near
// multiples of the 296 occ-2 slots); single fused prep kernel. Math path is
// identical to R10 (1-term fp16 GEMMs, fp16-accum QK, calibrated 2.6e-4).
// ===========================================================================

__device__ __forceinline__ uint32_t smem_u32(const void* p) {
    uint32_t a;
    asm("{ .reg .u64 t; cvta.to.shared.u64 t, %1; cvt.u32.u64 %0, t; }" : "=r"(a) : "l"(p));
    return a;
}
__device__ __forceinline__ void lm4(uint32_t* r, uint32_t a) {
    asm volatile("ldmatrix.sync.aligned.m8n8.x4.shared.b16 {%0,%1,%2,%3}, [%4];"
        : "=r"(r[0]), "=r"(r[1]), "=r"(r[2]), "=r"(r[3]) : "r"(a));
}
__device__ __forceinline__ void lm4t(uint32_t* r, uint32_t a) {
    asm volatile("ldmatrix.sync.aligned.m8n8.x4.trans.shared.b16 {%0,%1,%2,%3}, [%4];"
        : "=r"(r[0]), "=r"(r[1]), "=r"(r[2]), "=r"(r[3]) : "r"(a));
}
__device__ __forceinline__ void mma_f16(float* d, const uint32_t* a, uint32_t b0, uint32_t b1) {
    asm volatile("mma.sync.aligned.m16n8k16.row.col.f32.f16.f16.f32 "
        "{%0,%1,%2,%3}, {%4,%5,%6,%7}, {%8,%9}, {%0,%1,%2,%3};"
        : "+f"(d[0]), "+f"(d[1]), "+f"(d[2]), "+f"(d[3])
        : "r"(a[0]), "r"(a[1]), "r"(a[2]), "r"(a[3]), "r"(b0), "r"(b1));
}
__device__ __forceinline__ void mma_f16h(uint32_t* d, const uint32_t* a, uint32_t b0, uint32_t b1) {
    asm volatile("mma.sync.aligned.m16n8k16.row.col.f16.f16.f16.f16 "
        "{%0,%1}, {%2,%3,%4,%5}, {%6,%7}, {%0,%1};"
        : "+r"(d[0]), "+r"(d[1])
        : "r"(a[0]), "r"(a[1]), "r"(a[2]), "r"(a[3]), "r"(b0), "r"(b1));
}
__device__ __forceinline__ void cpasync16(uint32_t dst, const void* src) {
    asm volatile("cp.async.cg.shared.global [%0], [%1], 16;" :: "r"(dst), "l"(src));
}
__device__ __forceinline__ uint32_t hex2(uint32_t a) {
    uint32_t d; asm("ex2.approx.f16x2 %0, %1;" : "=r"(d) : "r"(a)); return d;
}

// ---------------- scratch (device globals) ---------------------------------
__device__ __half g_xh[2097152];
__device__ __half g_ws[3145728];                  // vq,vk,vv single fp16
__device__ __half g_wos[1048576];                 // wo single fp16
__device__ __half g_wT[3145728];                  // wq,wk,wv transposed
__device__ __half g_wc[3145728];                  // combined weights
__device__ float g_bc[3072];
__device__ float g_zb[1024];
__device__ __half g_q2f[2097152], g_k2f[2097152], g_v2f[2097152];
__device__ __half g_of[2097152];

// ---------------- fused prep: cvt x5, transpose x3, bias_combine ------------
struct PrepArgs {
    const float* csrc[5];
    __half* cdst[5];
    int cn[5];
    const float* wsrc[3];   // wq, wk, wv
    __half* wT;
    const float* V[3];      // vq, vk, vv
    const float* bI[3];     // wq_b, wk_b, wv_b
    const float* bO[3];     // vq_b, vk_b, vv_b
    float* bc;
};

__global__ void __launch_bounds__(256) prep_all(PrepArgs a) {
    const int z = blockIdx.z;
    const int bx = blockIdx.x;
    const int tid = threadIdx.x;
    __shared__ float s[32][33];

    if (z < 5) {
        // fp32 -> fp16 convert
        const int i = (bx * 256 + tid) * 4;
        if (i >= a.cn[z]) return;
        const float4 v = *(const float4*)(a.csrc[z] + i);
        __half2 H0; H0.x = __float2half_rn(v.x); H0.y = __float2half_rn(v.y);
        __half2 H1; H1.x = __float2half_rn(v.z); H1.y = __float2half_rn(v.w);
        *(__half2*)(a.cdst[z] + i) = H0;
        *(__half2*)(a.cdst[z] + i + 2) = H1;
    } else if (z < 8) {
        // transpose W[z-5] -> wT (32x32 tiles, 1024 blocks)
        if (bx >= 1024) return;
        const int zz = z - 5;
        const float* W = a.wsrc[zz];
        __half* ho = a.wT + (size_t)zz * 1048576;
        const int tx = tid & 31;
        const int ty = tid >> 5;
        const int k0 = (bx & 31) * 32;
        const int m0 = (bx >> 5) * 32;
#pragma unroll
        for (int j = 0; j < 4; ++j)
            s[ty + j * 8][tx] = W[(size_t)(m0 + ty + j * 8) * 1024 + k0 + tx];
        __syncthreads();
#pragma unroll
        for (int j = 0; j < 4; ++j)
            ho[(size_t)(k0 + ty + j * 8) * 1024 + m0 + tx] = __float2half_rn(s[tx][ty + j * 8]);
    } else {
        // bias_combine: bc[zz*1024+n] = V[zz][n,:] . bI[zz] + bO[zz][n]
        if (bx >= 384) return;
        const int zz = bx >> 7;
        const int lane = tid & 31;
        const int w = tid >> 5;
        const int n = (bx & 127) * 8 + w;
        const float* V = a.V[zz];
        const float* b = a.bI[zz];
        float sum = 0.f;
#pragma unroll
        for (int it = 0; it < 8; ++it) {
            const int k = (it * 32 + lane) * 4;
            const float4 vv = *(const float4*)(V + (size_t)n * 1024 + k);
            const float4 bb = *(const float4*)(b + k);
            sum += vv.x * bb.x + vv.y * bb.y + vv.z * bb.z + vv.w * bb.w;
        }
#pragma unroll
        for (int o = 16; o > 0; o >>= 1) sum += __shfl_xor_sync(0xffffffffu, sum, o);
        if (lane == 0) a.bc[zz * 1024 + n] = sum + a.bO[zz][n];
    }
}

// ---------------- mma.sync GEMM, 1-term fp16, 128x64 tiles ------------------
// C = (A*B + bias) * oscale. mode 1: fp32 out; mode 2: fp16 out.
struct GemmArgs {
    const __half *A, *B;
    const float* bias;
    void* C0;
    int mode;
    float oscale;
};

__device__ __forceinline__ uint32_t swz(int r, int s) {
    return (uint32_t)(r * 64 + ((s ^ ((r >> 1) & 3)) << 4));
}

__global__ void __launch_bounds__(256, 2)
gemm_mma(GemmArgs g0, GemmArgs g1, GemmArgs g2)
{
    constexpr uint32_t SS = 12288u;   // stage: A 8KB + B 4KB

    const GemmArgs ga = (blockIdx.z == 0) ? g0 : (blockIdx.z == 1) ? g1 : g2;
    extern __shared__ char smem_raw[];
    const uint32_t sb = (smem_u32(smem_raw) + 1023u) & ~1023u;

    const int tid = threadIdx.x;
    const int lane = tid & 31;
    const int wid = tid >> 5;
    const int wm = wid & 3;          // 4 m-warps (32 rows each)
    const int wn = wid >> 2;         // 2 n-warps (32 cols each)
    const int bm = blockIdx.y * 128;
    const int bn = blockIdx.x * 64;

    // loads: A 512 atoms + B 256 atoms = 3 per thread
    const __half* gp[3];
    uint32_t dst[3];
#pragma unroll
    for (int i = 0; i < 3; ++i) {
        const int u = tid + i * 256;
        if (u < 512) {
            const int r = u >> 2, sc = u & 3;
            gp[i] = ga.A + (size_t)(bm + r) * 1024 + sc * 8;
            dst[i] = sb + swz(r, sc);
        } else {
            const int v = u - 512;
            const int r = v >> 2, sc = v & 3;
            gp[i] = ga.B + (size_t)(bn + r) * 1024 + sc * 8;
            dst[i] = sb + 8192 + swz(r, sc);
        }
    }

    uint32_t lmA[2], lmB[2];
    {
        const int rA = wm * 32 + ((lane >> 3) & 1) * 8 + (lane & 7);
        const int sA = lane >> 4;
#pragma unroll
        for (int mt = 0; mt < 2; ++mt) lmA[mt] = sb + swz(rA + mt * 16, sA);
        const int rB = wn * 32 + (lane >> 4) * 8 + (lane & 7);
        const int sB = (lane >> 3) & 1;
#pragma unroll
        for (int ng = 0; ng < 2; ++ng) lmB[ng] = sb + 8192 + swz(rB + ng * 16, sB);
    }

    float acc[2][2][2][4];
#pragma unroll
    for (int mt = 0; mt < 2; ++mt)
#pragma unroll
        for (int ng = 0; ng < 2; ++ng)
#pragma unroll
            for (int h = 0; h < 2; ++h)
#pragma unroll
                for (int j = 0; j < 4; ++j) acc[mt][ng][h][j] = 0.f;

#pragma unroll
    for (int i = 0; i < 3; ++i) cpasync16(dst[i], gp[i]);
    asm volatile("cp.async.commit_group;" ::: "memory");
#pragma unroll
    for (int i = 0; i < 3; ++i) cpasync16(dst[i] + SS, gp[i] + 32);
    asm volatile("cp.async.commit_group;" ::: "memory");

#pragma unroll 1
    for (int ch = 0; ch < 32; ++ch) {
        if (ch < 31) { asm volatile("cp.async.wait_group 1;" ::: "memory"); }
        else         { asm volatile("cp.async.wait_group 0;" ::: "memory"); }
        __syncthreads();

        if (ch + 2 < 32) {
            const uint32_t sn = (uint32_t)((ch + 2) % 3) * SS;
#pragma unroll
            for (int i = 0; i < 3; ++i) cpasync16(dst[i] + sn, gp[i] + (ch + 2) * 32);
            asm volatile("cp.async.commit_group;" ::: "memory");
        }

        const uint32_t so = (uint32_t)(ch % 3) * SS;
#pragma unroll
        for (int ks = 0; ks < 2; ++ks) {
            const uint32_t kx = (uint32_t)(ks << 5);
            uint32_t ah[2][4], bh[2][4];
#pragma unroll
            for (int mt = 0; mt < 2; ++mt) lm4(ah[mt], (lmA[mt] + so) ^ kx);
#pragma unroll
            for (int ng = 0; ng < 2; ++ng) lm4(bh[ng], (lmB[ng] + so) ^ kx);
#pragma unroll
            for (int ng = 0; ng < 2; ++ng)
#pragma unroll
                for (int mt = 0; mt < 2; ++mt)
#pragma unroll
                    for (int h = 0; h < 2; ++h)
                        mma_f16(acc[mt][ng][h], ah[mt], bh[ng][2 * h], bh[ng][2 * h + 1]);
        }
    }

    const float osc = ga.oscale;
#pragma unroll
    for (int mt = 0; mt < 2; ++mt) {
        const int r0 = bm + wm * 32 + mt * 16 + (lane >> 2);
#pragma unroll
        for (int ng = 0; ng < 2; ++ng)
#pragma unroll
            for (int h = 0; h < 2; ++h) {
                const int col = bn + wn * 32 + ng * 16 + h * 8 + 2 * (lane & 3);
                const float2 b2 = *(const float2*)(ga.bias + col);
                const float* a4 = acc[mt][ng][h];
                const float v00 = (a4[0] + b2.x) * osc, v01 = (a4[1] + b2.y) * osc;
                const float v10 = (a4[2] + b2.x) * osc, v11 = (a4[3] + b2.y) * osc;
                if (ga.mode == 1) {
                    float2 p0; p0.x = v00; p0.y = v01;
                    float2 p1; p1.x = v10; p1.y = v11;
                    *(float2*)((float*)ga.C0 + (size_t)r0 * 1024 + col) = p0;
                    *(float2*)((float*)ga.C0 + (size_t)(r0 + 8) * 1024 + col) = p1;
                } else {
                    __half* hp = (__half*)ga.C0;
                    __half2 H0, H1;
                    H0.x = __float2half_rn(v00); H0.y = __float2half_rn(v01);
                    H1.x = __float2half_rn(v10); H1.y = __float2half_rn(v11);
                    *(__half2*)(hp + (size_t)r0 * 1024 + col) = H0;
                    *(__half2*)(hp + (size_t)(r0 + 8) * 1024 + col) = H1;
                }
            }
    }
}

// ---------------- MMA flash attention (unchanged from R10) ------------------
#define AK 0u
#define AV 32768u
#define AQ 65536u

__global__ void __launch_bounds__(256, 2)
attention_mma(const __half* __restrict__ q2, const __half* __restrict__ k2,
              const __half* __restrict__ v2, __half* __restrict__ Of)
{
    extern __shared__ char smraw[];
    const uint32_t sb = smem_u32(smraw);

    const int qp = blockIdx.x;
    const int c  = blockIdx.y;
    const int b  = blockIdx.z;
    const int tid = threadIdx.x;
    const int lane = tid & 31;
    const int w = tid >> 5;

#pragma unroll
    for (int i = 0; i < 16; ++i) {
        const int u = tid + i * 256;
        const int arr = u >> 11;
        const int rem = u & 2047;
        const int r = rem >> 1;
        const int half = rem & 1;
        const __half* base = arr ? v2 : k2;
        const __half* src = base + ((size_t)((b << 10) + r) << 10) + (c << 4) + (half << 3);
        const uint32_t dstp = sb + (uint32_t)(arr << 15) + (uint32_t)(r * 32 + ((half ^ ((r >> 2) & 1)) << 4));
        cpasync16(dstp, src);
    }
    asm volatile("cp.async.commit_group;" ::: "memory");

    const uint32_t qoff = (uint32_t)((lane & 15) * 32 + ((((lane >> 4) & 1) ^ ((lane >> 2) & 1)) << 4));
    const uint32_t kloff = (uint32_t)(((lane & 7) + ((lane >> 4) << 3)) * 32 +
                                      ((((lane >> 3) & 1) ^ ((lane >> 2) & 1)) << 4));
    const uint32_t vloff = (uint32_t)(((lane & 7) + (((lane >> 3) & 1) << 3)) * 32 +
                                      ((((lane >> 4) & 1) ^ ((lane >> 2) & 1)) << 4));
    const uint32_t ONES = 0x3C003C00u;

    const int ca = c >> 2, e = c & 3;
    const int tt = 2 * e + b;
    const int b2 = tt >> 2, r2 = tt & 3;

#pragma unroll 1
    for (int it = 0; it < 2; ++it) {
        const int qt = qp * 2 + it;
#pragma unroll
        for (int i = 0; i < 2; ++i) {
            const int u = tid + i * 256;
            const int r = u >> 1;
            const int half = u & 1;
            const __half* src = q2 + ((size_t)((b << 10) + (qt << 8) + r) << 10) + (c << 4) + (half << 3);
            const uint32_t dstp = sb + AQ + (uint32_t)(r * 32 + ((half ^ ((r >> 2) & 1)) << 4));
            cpasync16(dstp, src);
        }
        asm volatile("cp.async.commit_group;" ::: "memory");
        asm volatile("cp.async.wait_group 0;" ::: "memory");
        __syncthreads();

        uint32_t qf[2][4];
#pragma unroll
        for (int mt = 0; mt < 2; ++mt)
            lm4(qf[mt], sb + AQ + (uint32_t)((w * 32 + mt * 16) * 32) + qoff);

        float oac[2][2][4];
        float ls[2][4];
#pragma unroll
        for (int mt = 0; mt < 2; ++mt) {
#pragma unroll
            for (int j = 0; j < 4; ++j) ls[mt][j] = 0.f;
#pragma unroll
            for (int ht = 0; ht < 2; ++ht)
#pragma unroll
                for (int j = 0; j < 4; ++j) oac[mt][ht][j] = 0.f;
        }

#pragma unroll 1
        for (int kb = 0; kb < 16; ++kb) {
            uint32_t sc16[2][8][2];
#pragma unroll
            for (int mt = 0; mt < 2; ++mt)
#pragma unroll
                for (int j = 0; j < 8; ++j) { sc16[mt][j][0] = 0u; sc16[mt][j][1] = 0u; }

#pragma unroll
            for (int nt = 0; nt < 4; ++nt) {
                const uint32_t s0 = (uint32_t)((kb * 64 + nt * 16) * 32);
                uint32_t kh4[4];
                lm4(kh4, sb + AK + s0 + kloff);
#pragma unroll
                for (int mt = 0; mt < 2; ++mt) {
                    mma_f16h(sc16[mt][2 * nt], qf[mt], kh4[0], kh4[1]);
                    mma_f16h(sc16[mt][2 * nt + 1], qf[mt], kh4[2], kh4[3]);
                }
            }

#pragma unroll
            for (int ks = 0; ks < 4; ++ks) {
                const uint32_t s0 = (uint32_t)((kb * 64 + ks * 16) * 32);
                uint32_t vh4[4];
                lm4t(vh4, sb + AV + s0 + vloff);
#pragma unroll
                for (int mt = 0; mt < 2; ++mt) {
                    uint32_t pa[4];
                    pa[0] = hex2(sc16[mt][2 * ks][0]);
                    pa[1] = hex2(sc16[mt][2 * ks][1]);
                    pa[2] = hex2(sc16[mt][2 * ks + 1][0]);
                    pa[3] = hex2(sc16[mt][2 * ks + 1][1]);
                    mma_f16(oac[mt][0], pa, vh4[0], vh4[1]);
                    mma_f16(oac[mt][1], pa, vh4[2], vh4[3]);
                    mma_f16(ls[mt], pa, ONES, ONES);
                }
            }
        }

#pragma unroll
        for (int mt = 0; mt < 2; ++mt) {
            const int s_lo = qt * 256 + w * 32 + mt * 16 + (lane >> 2);
            const float inv_lo = 1.0f / ls[mt][0];
            const float inv_hi = 1.0f / ls[mt][2];
#pragma unroll
            for (int ht = 0; ht < 2; ++ht) {
                const int h0 = ht * 8 + 2 * (lane & 3);
#pragma unroll
                for (int rr = 0; rr < 2; ++rr) {
                    const int s = s_lo + rr * 8;
                    const float inv = rr ? inv_hi : inv_lo;
                    const float v0 = oac[mt][ht][rr * 2 + 0] * inv;
                    const float v1 = oac[mt][ht][rr * 2 + 1] * inv;
                    const int s2 = (r2 << 8) | (s >> 2);
                    const int f = (ca << 6) | ((s & 3) << 4) | h0;
                    const size_t off = (((size_t)b2 << 10) + s2) * 1024 + f;
                    __half2 H;
                    H.x = __float2half_rn(v0); H.y = __float2half_rn(v1);
                    *(__half2*)(Of + off) = H;
                }
            }
        }
        __syncthreads();
    }
}

// ---------------------------------------------------------------------------
extern "C" void kernel_launch(void* const* d_in, const int* in_sizes, int n_in,
                              void* d_out, int out_size)
{
    const float* x    = (const float*)d_in[0];
    const float* wq_w = (const float*)d_in[1];
    const float* wq_b = (const float*)d_in[2];
    const float* wk_w = (const float*)d_in[3];
    const float* wk_b = (const float*)d_in[4];
    const float* wv_w = (const float*)d_in[5];
    const float* wv_b = (const float*)d_in[6];
    const float* vq_w = (const float*)d_in[7];
    const float* vq_b = (const float*)d_in[8];
    const float* vk_w = (const float*)d_in[9];
    const float* vk_b = (const float*)d_in[10];
    const float* vv_w = (const float*)d_in[11];
    const float* vv_b = (const float*)d_in[12];
    const float* wo_w = (const float*)d_in[13];
    const float* wo_b = (const float*)d_in[14];
    float* out = (float*)d_out;

    __half *xh, *ws, *wos, *wT, *wc, *q2f, *k2f, *v2f, *of;
    float *bc, *zb;
    cudaGetSymbolAddress((void**)&xh, g_xh);
    cudaGetSymbolAddress((void**)&ws, g_ws);
    cudaGetSymbolAddress((void**)&wos, g_wos);
    cudaGetSymbolAddress((void**)&wT, g_wT);   cudaGetSymbolAddress((void**)&wc, g_wc);
    cudaGetSymbolAddress((void**)&bc, g_bc);   cudaGetSymbolAddress((void**)&zb, g_zb);
    cudaGetSymbolAddress((void**)&q2f, g_q2f); cudaGetSymbolAddress((void**)&k2f, g_k2f);
    cudaGetSymbolAddress((void**)&v2f, g_v2f);
    cudaGetSymbolAddress((void**)&of, g_of);

    // 1) fused prep
    PrepArgs pa;
    pa.csrc[0] = x;    pa.cdst[0] = xh;           pa.cn[0] = 2097152;
    pa.csrc[1] = vq_w; pa.cdst[1] = ws + 0;       pa.cn[1] = 1048576;
    pa.csrc[2] = vk_w; pa.cdst[2] = ws + 1048576; pa.cn[2] = 1048576;
    pa.csrc[3] = vv_w; pa.cdst[3] = ws + 2097152; pa.cn[3] = 1048576;
    pa.csrc[4] = wo_w; pa.cdst[4] = wos;          pa.cn[4] = 1048576;
    pa.wsrc[0] = wq_w; pa.wsrc[1] = wk_w; pa.wsrc[2] = wv_w;
    pa.wT = wT;
    pa.V[0] = vq_w; pa.V[1] = vk_w; pa.V[2] = vv_w;
    pa.bI[0] = wq_b; pa.bI[1] = wk_b; pa.bI[2] = wv_b;
    pa.bO[0] = vq_b; pa.bO[1] = vk_b; pa.bO[2] = vv_b;
    pa.bc = bc;
    prep_all<<<dim3(2048, 1, 9), 256>>>(pa);

    const int gemm_smem = 3 * 12288 + 1024;
    cudaFuncSetAttribute(gemm_mma, cudaFuncAttributeMaxDynamicSharedMemorySize, gemm_smem);

    const float SCL = 0.25f * 1.4426950408889634f;

    // 2) weight combine: Wc = Vq @ Wq (1-term fp16), 128x64 tiles
    GemmArgs a0{}, a1{}, a2{};
    a0 = {ws + 0, wT + 0, zb, wc + 0, 2, 1.0f};
    a1 = {ws + 1048576, wT + 1048576, zb, wc + 1048576, 2, 1.0f};
    a2 = {ws + 2097152, wT + 2097152, zb, wc + 2097152, 2, 1.0f};
    gemm_mma<<<dim3(16, 8, 3), 256, gemm_smem>>>(a0, a1, a2);

    // 3) data GEMMs: q2 (pre-scaled by SCL), k2, v2
    a0 = {xh, wc + 0, bc + 0, q2f, 2, SCL};
    a1 = {xh, wc + 1048576, bc + 1024, k2f, 2, 1.0f};
    a2 = {xh, wc + 2097152, bc + 2048, v2f, 2, 1.0f};
    gemm_mma<<<dim3(16, 16, 3), 256, gemm_smem>>>(a0, a1, a2);

    // 4) attention -> o single fp16, permuted
    const int attn_smem = 73728;
    cudaFuncSetAttribute(attention_mma, cudaFuncAttributeMaxDynamicSharedMemorySize, attn_smem);
    attention_mma<<<dim3(2, 64, 2), 256, attn_smem>>>(q2f, k2f, v2f, of);

    // 5) final projection (1-term fp16), fp32 out
    a0 = {of, wos, wo_b, out, 1, 1.0f};
    gemm_mma<<<dim3(16, 16, 1), 256, gemm_smem>>>(a0, a0, a0);
}